// round 4
// baseline (speedup 1.0000x reference)
#include <cuda_runtime.h>
#include <cuda_bf16.h>
#include <math.h>

// Problem constants
#define Bb   4
#define T    128
#define D    512
#define Hh   4
#define DK   128
#define NL   4
#define DFF  2048
#define NC   5

#define M2   1024            // merged towers rows
#define NDp  (M2*D)          // 524288

// ---------------- raw scratch (float) ----------------------------------------
#define OFF_X   0
#define OFF_QK  (OFF_X + NDp)
#define OFF_EQ  (OFF_QK + 65536)
#define OFF_EK  (OFF_EQ + 2560)
#define OFF_G   (OFF_EK + 2560)
#define OFF_W   (OFF_G + 32)
#define OFF_PK  (OFF_W + 2560)
#define RAW_TOTAL (OFF_PK + 262144)
__device__ float g_scratch[RAW_TOTAL];

// ---------------- split activation scratch (float2 = hi,lo) -------------------
#define AS_X   0
#define AS_H   (AS_X + NDp)
#define AS_Q   (AS_H + NDp)
#define AS_K   (AS_Q + NDp)
#define AS_V   (AS_K + NDp)
#define AS_T0  (AS_V + NDp)
#define AS_T1  (AS_T0 + NDp)
#define AS_FFN (AS_T1 + NDp)          // M2*DFF
#define AS_P   (AS_FFN + M2*DFF)      // 4*T*T
#define ASPLIT_TOTAL (AS_P + 65536)
__device__ float2 g_asplit[ASPLIT_TOTAL];

// ---------------- split weight scratch ---------------------------------------
#define SZ1  (NL*D*D)        // 1048576
#define SZF  (NL*D*DFF)      // 4194304
#define SZS  (D*D)           // 262144
#define WS_Q  0
#define WS_K  (WS_Q + SZ1)
#define WS_V  (WS_K + SZ1)
#define WS_O  (WS_V + SZ1)
#define WS_F1 (WS_O + SZ1)
#define WS_F2 (WS_F1 + SZF)
#define WS_SQ (WS_F2 + SZF)
#define WS_SK (WS_SQ + SZS)
#define WS_TOTAL (WS_SK + SZS)       // 13107200
__device__ float2 g_wsplit[WS_TOTAL];

__device__ __forceinline__ float gelu_f(float x) {
    return 0.5f * x * (1.0f + erff(x * 0.7071067811865475f));
}

// ---------------- tf32 / mma / cp.async helpers ------------------------------
__device__ __forceinline__ unsigned f2tf32(float x) {
    unsigned r;
    asm("cvt.rna.tf32.f32 %0, %1;" : "=r"(r) : "f"(x));
    return r;
}
__device__ __forceinline__ float2 split2f(float x) {
    float hi = __uint_as_float(f2tf32(x));
    float lo = __uint_as_float(f2tf32(x - hi));
    return make_float2(hi, lo);
}
__device__ __forceinline__ void mma_tf32(float* c, const unsigned* a, const unsigned* b) {
    asm volatile(
        "mma.sync.aligned.m16n8k8.row.col.f32.tf32.tf32.f32 "
        "{%0,%1,%2,%3},{%4,%5,%6,%7},{%8,%9},{%0,%1,%2,%3};"
        : "+f"(c[0]), "+f"(c[1]), "+f"(c[2]), "+f"(c[3])
        : "r"(a[0]), "r"(a[1]), "r"(a[2]), "r"(a[3]), "r"(b[0]), "r"(b[1]));
}
__device__ __forceinline__ void mma3(float* c, const unsigned* ah, const unsigned* al,
                                     const unsigned* bh, const unsigned* bl) {
    mma_tf32(c, ah, bh);
    mma_tf32(c, ah, bl);
    mma_tf32(c, al, bh);
}
__device__ __forceinline__ void fragA(const float2 v0, const float2 v1, const float2 v2, const float2 v3,
                                      unsigned* h, unsigned* l) {
    h[0] = __float_as_uint(v0.x); l[0] = __float_as_uint(v0.y);
    h[1] = __float_as_uint(v1.x); l[1] = __float_as_uint(v1.y);
    h[2] = __float_as_uint(v2.x); l[2] = __float_as_uint(v2.y);
    h[3] = __float_as_uint(v3.x); l[3] = __float_as_uint(v3.y);
}
__device__ __forceinline__ void cp16(void* s, const void* g) {
    unsigned sa = (unsigned)__cvta_generic_to_shared(s);
    asm volatile("cp.async.cg.shared.global [%0], [%1], 16;\n" :: "r"(sa), "l"(g) : "memory");
}
#define CP_COMMIT() asm volatile("cp.async.commit_group;\n" ::: "memory")
#define CP_WAIT(n)  asm volatile("cp.async.wait_group %0;\n" :: "n"(n) : "memory")

// ---------------- weight split prep ------------------------------------------
__global__ void split_weights(const float* __restrict__ Wq, const float* __restrict__ Wk,
                              const float* __restrict__ Wv, const float* __restrict__ Wo,
                              const float* __restrict__ f1, const float* __restrict__ f2,
                              const float* __restrict__ sq, const float* __restrict__ sk) {
    for (long long i = (long long)blockIdx.x * blockDim.x + threadIdx.x; i < WS_TOTAL;
         i += (long long)gridDim.x * blockDim.x) {
        const float* s; long long o;
        if (i < WS_K)        { s = Wq; o = i - WS_Q; }
        else if (i < WS_V)   { s = Wk; o = i - WS_K; }
        else if (i < WS_O)   { s = Wv; o = i - WS_V; }
        else if (i < WS_F1)  { s = Wo; o = i - WS_O; }
        else if (i < WS_F2)  { s = f1; o = i - WS_F1; }
        else if (i < WS_SQ)  { s = f2; o = i - WS_F2; }
        else if (i < WS_SK)  { s = sq; o = i - WS_SQ; }
        else                 { s = sk; o = i - WS_SK; }
        g_wsplit[i] = split2f(s[o]);
    }
}

// ---------------- pre-split 3xTF32 GEMM, 64x64 tile, 3-stage cp.async --------
// A,B: float2 (hi,lo) planes. C: OUTS=0 -> raw float, OUTS=1 -> split float2.
#define PADA 18
#define PADB 68

template<int TRANSB, int OUTS>
__global__ __launch_bounds__(256, 2)
void gemm_sp(const float2* __restrict__ A0, const float2* __restrict__ A1, const float2* __restrict__ A2,
             const float2* __restrict__ W0, const float2* __restrict__ W1, const float2* __restrict__ W2,
             const float* __restrict__ bias0, const float* __restrict__ bias1, const float* __restrict__ bias2,
             void* C0v, void* C1v, void* C2v,
             int M, int N, int K, int lda, int ldb, int ldc,
             int act,
             long long sA, long long sB, long long sC, int zPerSet) {
    int z = blockIdx.z;
    int set = z / zPerSet;
    int zz = z % zPerSet;

    const float2* A  = (set == 0) ? A0 : (set == 1 ? A1 : A2);
    const float2* Bm = (set == 0) ? W0 : (set == 1 ? W1 : W2);
    const float* bias = (set == 0) ? bias0 : (set == 1 ? bias1 : bias2);
    void* Cv = (set == 0) ? C0v : (set == 1 ? C1v : C2v);
    A  += zz * sA;
    Bm += zz * sB;

    extern __shared__ float2 smp[];
    float2* As = smp;                                 // [3][64][PADA]
    constexpr int BR = TRANSB ? 64 : 16;
    constexpr int BC = TRANSB ? PADA : PADB;
    float2* Bs = smp + 3 * 64 * PADA;                 // [3][BR][BC]
#define ASM(s,r,c) As[((s)*64+(r))*PADA+(c)]
#define BSM(s,r,c) Bs[((s)*BR+(r))*BC+(c)]

    int tid = threadIdx.x;
    int lane = tid & 31, wid = tid >> 5;
    int wm = wid & 1, wn = wid >> 1;
    int l3 = lane & 3, l2 = lane >> 2;

    int bm = blockIdx.y * 64;
    int bn = blockIdx.x * 64;

    // load indices (cp16 = 2 float2)
    int ar0 = tid >> 3, ac = (tid & 7) * 2;       // A: 64 rows x 8 units, 2 rounds
    int nbr = tid >> 5, nbc = (tid & 31) * 2;     // B nt: 16 rows x 32 units, 2 rounds? 512 units/256 = 2

    float acc[2][2][4] = {};
    int nk = K / 16;

    // prologue
    #pragma unroll
    for (int p = 0; p < 2; p++) {
        int k0 = p * 16;
        cp16(&ASM(p, ar0, ac),      A + (size_t)(bm + ar0) * lda + k0 + ac);
        cp16(&ASM(p, ar0 + 32, ac), A + (size_t)(bm + ar0 + 32) * lda + k0 + ac);
        if (TRANSB) {
            cp16(&BSM(p, ar0, ac),      Bm + (size_t)(bn + ar0) * ldb + k0 + ac);
            cp16(&BSM(p, ar0 + 32, ac), Bm + (size_t)(bn + ar0 + 32) * ldb + k0 + ac);
        } else {
            cp16(&BSM(p, nbr, nbc),     Bm + (size_t)(k0 + nbr) * ldb + bn + nbc);
            cp16(&BSM(p, nbr + 8, nbc), Bm + (size_t)(k0 + nbr + 8) * ldb + bn + nbc);
        }
        CP_COMMIT();
    }

    for (int kt = 0; kt < nk; kt++) {
        CP_WAIT(1);
        __syncthreads();
        int st = kt % 3;
        if (kt + 2 < nk) {
            int ns = (kt + 2) % 3;
            int k0 = (kt + 2) * 16;
            cp16(&ASM(ns, ar0, ac),      A + (size_t)(bm + ar0) * lda + k0 + ac);
            cp16(&ASM(ns, ar0 + 32, ac), A + (size_t)(bm + ar0 + 32) * lda + k0 + ac);
            if (TRANSB) {
                cp16(&BSM(ns, ar0, ac),      Bm + (size_t)(bn + ar0) * ldb + k0 + ac);
                cp16(&BSM(ns, ar0 + 32, ac), Bm + (size_t)(bn + ar0 + 32) * ldb + k0 + ac);
            } else {
                cp16(&BSM(ns, nbr, nbc),     Bm + (size_t)(k0 + nbr) * ldb + bn + nbc);
                cp16(&BSM(ns, nbr + 8, nbc), Bm + (size_t)(k0 + nbr + 8) * ldb + bn + nbc);
            }
        }
        CP_COMMIT();

        #pragma unroll
        for (int ks = 0; ks < 16; ks += 8) {
            unsigned ah[2][4], al[2][4], bh[2][2], bl[2][2];
            #pragma unroll
            for (int i = 0; i < 2; i++) {
                int m0 = wm * 32 + i * 16;
                fragA(ASM(st, m0 + l2, ks + l3),     ASM(st, m0 + l2 + 8, ks + l3),
                      ASM(st, m0 + l2, ks + l3 + 4), ASM(st, m0 + l2 + 8, ks + l3 + 4),
                      ah[i], al[i]);
            }
            #pragma unroll
            for (int j = 0; j < 2; j++) {
                int n0 = wn * 16 + j * 8;
                float2 b0, b1;
                if (TRANSB) { b0 = BSM(st, n0 + l2, ks + l3); b1 = BSM(st, n0 + l2, ks + l3 + 4); }
                else        { b0 = BSM(st, ks + l3, n0 + l2); b1 = BSM(st, ks + l3 + 4, n0 + l2); }
                bh[j][0] = __float_as_uint(b0.x); bl[j][0] = __float_as_uint(b0.y);
                bh[j][1] = __float_as_uint(b1.x); bl[j][1] = __float_as_uint(b1.y);
            }
            #pragma unroll
            for (int i = 0; i < 2; i++)
                #pragma unroll
                for (int j = 0; j < 2; j++)
                    mma3(acc[i][j], ah[i], al[i], bh[j], bl[j]);
        }
    }

    // epilogue
    #pragma unroll
    for (int i = 0; i < 2; i++) {
        #pragma unroll
        for (int j = 0; j < 2; j++) {
            int rg = bm + wm * 32 + i * 16 + l2;
            int cg = bn + wn * 16 + j * 8 + 2 * l3;
            float bv0 = bias ? bias[cg] : 0.0f;
            float bv1 = bias ? bias[cg + 1] : 0.0f;
            float v0 = acc[i][j][0] + bv0, v1 = acc[i][j][1] + bv1;
            float v2 = acc[i][j][2] + bv0, v3 = acc[i][j][3] + bv1;
            if (act) { v0 = gelu_f(v0); v1 = gelu_f(v1); v2 = gelu_f(v2); v3 = gelu_f(v3); }
            if (OUTS == 0) {
                float* C = (float*)Cv + zz * sC;
                *(float2*)(C + (size_t)rg * ldc + cg) = make_float2(v0, v1);
                *(float2*)(C + (size_t)(rg + 8) * ldc + cg) = make_float2(v2, v3);
            } else {
                float2* C = (float2*)Cv + zz * sC;
                float2 s0 = split2f(v0), s1 = split2f(v1), s2 = split2f(v2), s3 = split2f(v3);
                *(float4*)&C[(size_t)rg * ldc + cg] = make_float4(s0.x, s0.y, s1.x, s1.y);
                *(float4*)&C[(size_t)(rg + 8) * ldc + cg] = make_float4(s2.x, s2.y, s3.x, s3.y);
            }
        }
    }
#undef ASM
#undef BSM
}

// ---------------- fused attention (split I/O) --------------------------------
#define PADQ 130
__global__ __launch_bounds__(256)
void fused_attn(const float2* __restrict__ Q, const float2* __restrict__ K,
                const float2* __restrict__ V, float2* __restrict__ O) {
    extern __shared__ float2 dyn2[];
    float2* Pbuf = dyn2;                  // [64][PADQ]
    float2* Kbuf = dyn2 + 64 * PADQ;      // [128][PADQ]
    __shared__ float redM[64][4];
    __shared__ float redS[64][4];

    int bz = blockIdx.y;
    int bb = bz >> 2, h = bz & 3;
    int qbase = blockIdx.x * 64;

    int tid = threadIdx.x;
    int lane = tid & 31, wid = tid >> 5;
    int wm = wid & 1, wn = wid >> 1;
    int l3 = lane & 3, l2 = lane >> 2;

    const float2* Qg = Q + ((size_t)bb * T + qbase) * D + h * DK;
    const float2* Kg = K + ((size_t)bb * T) * D + h * DK;
    const float2* Vg = V + ((size_t)bb * T) * D + h * DK;

    #pragma unroll
    for (int t = 0; t < 16; t++) {
        int u = tid + t * 256;
        int r = u >> 6, c = (u & 63) * 2;
        cp16(&Pbuf[r * PADQ + c], Qg + (size_t)r * D + c);
    }
    CP_COMMIT();
    #pragma unroll
    for (int t = 0; t < 32; t++) {
        int u = tid + t * 256;
        int r = u >> 6, c = (u & 63) * 2;
        cp16(&Kbuf[r * PADQ + c], Kg + (size_t)r * D + c);
    }
    CP_COMMIT();
    CP_WAIT(0);
    __syncthreads();

    // phase 1: S = Q @ K^T
    float acc[2][4][4] = {};
    #pragma unroll 4
    for (int ks = 0; ks < DK; ks += 8) {
        unsigned ah[2][4], al[2][4], bh[4][2], bl[4][2];
        #pragma unroll
        for (int i = 0; i < 2; i++) {
            int m0 = wm * 32 + i * 16;
            fragA(Pbuf[(m0 + l2) * PADQ + ks + l3],     Pbuf[(m0 + l2 + 8) * PADQ + ks + l3],
                  Pbuf[(m0 + l2) * PADQ + ks + l3 + 4], Pbuf[(m0 + l2 + 8) * PADQ + ks + l3 + 4],
                  ah[i], al[i]);
        }
        #pragma unroll
        for (int j = 0; j < 4; j++) {
            int n0 = wn * 32 + j * 8;
            float2 b0 = Kbuf[(n0 + l2) * PADQ + ks + l3];
            float2 b1 = Kbuf[(n0 + l2) * PADQ + ks + l3 + 4];
            bh[j][0] = __float_as_uint(b0.x); bl[j][0] = __float_as_uint(b0.y);
            bh[j][1] = __float_as_uint(b1.x); bl[j][1] = __float_as_uint(b1.y);
        }
        #pragma unroll
        for (int i = 0; i < 2; i++)
            #pragma unroll
            for (int j = 0; j < 4; j++)
                mma3(acc[i][j], ah[i], al[i], bh[j], bl[j]);
    }
    __syncthreads();   // Q/K reads done

    // V load overlaps softmax
    #pragma unroll
    for (int t = 0; t < 32; t++) {
        int u = tid + t * 256;
        int r = u >> 6, c = (u & 63) * 2;
        cp16(&Kbuf[r * PADQ + c], Vg + (size_t)r * D + c);
    }
    CP_COMMIT();

    const float sc = 0.08838834764831845f;
    #pragma unroll
    for (int i = 0; i < 2; i++)
        #pragma unroll
        for (int j = 0; j < 4; j++)
            #pragma unroll
            for (int q = 0; q < 4; q++) acc[i][j][q] *= sc;

    #pragma unroll
    for (int i = 0; i < 2; i++)
        #pragma unroll
        for (int hf = 0; hf < 2; hf++) {
            int row = wm * 32 + i * 16 + l2 + hf * 8;
            float m = -1e30f;
            #pragma unroll
            for (int j = 0; j < 4; j++) m = fmaxf(m, fmaxf(acc[i][j][2 * hf], acc[i][j][2 * hf + 1]));
            m = fmaxf(m, __shfl_xor_sync(0xffffffff, m, 1));
            m = fmaxf(m, __shfl_xor_sync(0xffffffff, m, 2));
            if (l3 == 0) redM[row][wn] = m;
        }
    __syncthreads();
    #pragma unroll
    for (int i = 0; i < 2; i++)
        #pragma unroll
        for (int hf = 0; hf < 2; hf++) {
            int row = wm * 32 + i * 16 + l2 + hf * 8;
            float m = fmaxf(fmaxf(redM[row][0], redM[row][1]), fmaxf(redM[row][2], redM[row][3]));
            float s = 0.0f;
            #pragma unroll
            for (int j = 0; j < 4; j++) {
                acc[i][j][2 * hf]     = expf(acc[i][j][2 * hf] - m);
                acc[i][j][2 * hf + 1] = expf(acc[i][j][2 * hf + 1] - m);
                s += acc[i][j][2 * hf] + acc[i][j][2 * hf + 1];
            }
            s += __shfl_xor_sync(0xffffffff, s, 1);
            s += __shfl_xor_sync(0xffffffff, s, 2);
            if (l3 == 0) redS[row][wn] = s;
        }
    __syncthreads();
    // normalize + split + write P
    #pragma unroll
    for (int i = 0; i < 2; i++)
        #pragma unroll
        for (int hf = 0; hf < 2; hf++) {
            int row = wm * 32 + i * 16 + l2 + hf * 8;
            float inv = 1.0f / (redS[row][0] + redS[row][1] + redS[row][2] + redS[row][3]);
            #pragma unroll
            for (int j = 0; j < 4; j++) {
                int col = wn * 32 + j * 8 + 2 * l3;
                float2 s0 = split2f(acc[i][j][2 * hf] * inv);
                float2 s1 = split2f(acc[i][j][2 * hf + 1] * inv);
                *(float4*)&Pbuf[row * PADQ + col] = make_float4(s0.x, s0.y, s1.x, s1.y);
            }
        }
    CP_WAIT(0);
    __syncthreads();

    // phase 2: O = P @ V
    float out[2][4][4] = {};
    #pragma unroll 4
    for (int ks = 0; ks < T; ks += 8) {
        unsigned ah[2][4], al[2][4], bh[4][2], bl[4][2];
        #pragma unroll
        for (int i = 0; i < 2; i++) {
            int m0 = wm * 32 + i * 16;
            fragA(Pbuf[(m0 + l2) * PADQ + ks + l3],     Pbuf[(m0 + l2 + 8) * PADQ + ks + l3],
                  Pbuf[(m0 + l2) * PADQ + ks + l3 + 4], Pbuf[(m0 + l2 + 8) * PADQ + ks + l3 + 4],
                  ah[i], al[i]);
        }
        #pragma unroll
        for (int j = 0; j < 4; j++) {
            int n0 = wn * 32 + j * 8;
            float2 b0 = Kbuf[(ks + l3) * PADQ + n0 + l2];
            float2 b1 = Kbuf[(ks + l3 + 4) * PADQ + n0 + l2];
            bh[j][0] = __float_as_uint(b0.x); bl[j][0] = __float_as_uint(b0.y);
            bh[j][1] = __float_as_uint(b1.x); bl[j][1] = __float_as_uint(b1.y);
        }
        #pragma unroll
        for (int i = 0; i < 2; i++)
            #pragma unroll
            for (int j = 0; j < 4; j++)
                mma3(out[i][j], ah[i], al[i], bh[j], bl[j]);
    }

    float2* Og = O + ((size_t)bb * T + qbase) * D + h * DK;
    #pragma unroll
    for (int i = 0; i < 2; i++)
        #pragma unroll
        for (int j = 0; j < 4; j++) {
            int r = wm * 32 + i * 16 + l2;
            int c = wn * 32 + j * 8 + 2 * l3;
            float2 s0 = split2f(out[i][j][0]), s1 = split2f(out[i][j][1]);
            float2 s2 = split2f(out[i][j][2]), s3 = split2f(out[i][j][3]);
            *(float4*)&Og[(size_t)r * D + c] = make_float4(s0.x, s0.y, s1.x, s1.y);
            *(float4*)&Og[(size_t)(r + 8) * D + c] = make_float4(s2.x, s2.y, s3.x, s3.y);
        }
}

// ---------------- warp helpers ----------------------------------------------
__device__ __forceinline__ float warp_sum(float v) {
    #pragma unroll
    for (int o = 16; o > 0; o >>= 1) v += __shfl_xor_sync(0xffffffff, v, o);
    return v;
}
__device__ __forceinline__ float warp_max(float v) {
    #pragma unroll
    for (int o = 16; o > 0; o >>= 1) v = fmaxf(v, __shfl_xor_sync(0xffffffff, v, o));
    return v;
}

// ---------------- LayerNorm kernels (128 threads, 4 elems/thread) ------------
__global__ void add_pos_ln_kernel(const float* __restrict__ x, const float* __restrict__ pos,
                                  const float* __restrict__ w, const float* __restrict__ b,
                                  float* __restrict__ raw_out, float2* __restrict__ outs) {
    int row = blockIdx.x, tid = threadIdx.x;
    int lane = tid & 31, wd = tid >> 5;
    __shared__ float p1[4], p2[4];

    float4 xv = ((const float4*)(x + (size_t)row * D))[tid];
    float4 pv = ((const float4*)(pos + (size_t)(row % T) * D))[tid];
    float4 v = make_float4(xv.x + pv.x, xv.y + pv.y, xv.z + pv.z, xv.w + pv.w);

    float s = warp_sum(v.x + v.y + v.z + v.w);
    if (lane == 0) p1[wd] = s;
    __syncthreads();
    float mean = (p1[0] + p1[1] + p1[2] + p1[3]) * (1.0f / D);
    float4 d = make_float4(v.x - mean, v.y - mean, v.z - mean, v.w - mean);
    float q = warp_sum(d.x * d.x + d.y * d.y + d.z * d.z + d.w * d.w);
    if (lane == 0) p2[wd] = q;
    __syncthreads();
    float inv = rsqrtf((p2[0] + p2[1] + p2[2] + p2[3]) * (1.0f / D) + 1e-12f);

    float4 wv = ((const float4*)w)[tid];
    float4 bv = ((const float4*)b)[tid];
    float4 n = make_float4(wv.x * d.x * inv + bv.x, wv.y * d.y * inv + bv.y,
                           wv.z * d.z * inv + bv.z, wv.w * d.w * inv + bv.w);
    ((float4*)(raw_out + (size_t)row * D))[tid] = n;
    float2* orow = outs + (size_t)row * D + tid * 4;
    float2 s0 = split2f(n.x), s1 = split2f(n.y), s2 = split2f(n.z), s3 = split2f(n.w);
    *(float4*)orow       = make_float4(s0.x, s0.y, s1.x, s1.y);
    *(float4*)(orow + 2) = make_float4(s2.x, s2.y, s3.x, s3.y);
}

// x += (y.hi+y.lo) (persist); LN -> split outs, optionally raw_out
__global__ void residual_ln_kernel(float* __restrict__ x, const float2* __restrict__ ys,
                                   float* __restrict__ raw_out, float2* __restrict__ outs,
                                   const float* __restrict__ w, const float* __restrict__ b) {
    int row = blockIdx.x, tid = threadIdx.x;
    int lane = tid & 31, wd = tid >> 5;
    __shared__ float p1[4], p2[4];

    float4 xv = ((const float4*)(x + (size_t)row * D))[tid];
    const float2* yr = ys + (size_t)row * D + tid * 4;
    float2 y0 = yr[0], y1 = yr[1], y2 = yr[2], y3 = yr[3];
    float4 v = make_float4(xv.x + y0.x + y0.y, xv.y + y1.x + y1.y,
                           xv.z + y2.x + y2.y, xv.w + y3.x + y3.y);
    ((float4*)(x + (size_t)row * D))[tid] = v;

    float s = warp_sum(v.x + v.y + v.z + v.w);
    if (lane == 0) p1[wd] = s;
    __syncthreads();
    float mean = (p1[0] + p1[1] + p1[2] + p1[3]) * (1.0f / D);
    float4 d = make_float4(v.x - mean, v.y - mean, v.z - mean, v.w - mean);
    float q = warp_sum(d.x * d.x + d.y * d.y + d.z * d.z + d.w * d.w);
    if (lane == 0) p2[wd] = q;
    __syncthreads();
    float inv = rsqrtf((p2[0] + p2[1] + p2[2] + p2[3]) * (1.0f / D) + 1e-12f);

    float4 wv = ((const float4*)w)[tid];
    float4 bv = ((const float4*)b)[tid];
    float4 n = make_float4(wv.x * d.x * inv + bv.x, wv.y * d.y * inv + bv.y,
                           wv.z * d.z * inv + bv.z, wv.w * d.w * inv + bv.w);
    if (raw_out) ((float4*)(raw_out + (size_t)row * D))[tid] = n;
    float2* orow = outs + (size_t)row * D + tid * 4;
    float2 s0 = split2f(n.x), s1 = split2f(n.y), s2 = split2f(n.z), s3 = split2f(n.w);
    *(float4*)orow       = make_float4(s0.x, s0.y, s1.x, s1.y);
    *(float4*)(orow + 2) = make_float4(s2.x, s2.y, s3.x, s3.y);
}

// ---------------- sim head helpers ------------------------------------------
__global__ void edot_kernel(const float2* __restrict__ Xs, const float* __restrict__ E,
                            float* __restrict__ out) {
    int row = blockIdx.x;
    int tid = threadIdx.x;
    __shared__ float red[NC * 256];
    float acc[NC] = {};
    for (int d = tid; d < D; d += 256) {
        float2 xv = Xs[(size_t)row * D + d];
        float x = xv.x + xv.y;
        #pragma unroll
        for (int c = 0; c < NC; c++) acc[c] += x * E[(size_t)c * D + d];
    }
    #pragma unroll
    for (int c = 0; c < NC; c++) red[c * 256 + tid] = acc[c];
    __syncthreads();
    for (int off = 128; off > 0; off >>= 1) {
        if (tid < off) {
            #pragma unroll
            for (int c = 0; c < NC; c++) red[c * 256 + tid] += red[c * 256 + tid + off];
        }
        __syncthreads();
    }
    if (tid < NC) out[(size_t)row * NC + tid] = red[tid * 256];
}

__global__ void gram_kernel(const float* __restrict__ E, float* __restrict__ G) {
    int i = threadIdx.x;
    if (i < NC * NC) {
        int c = i / NC, c2 = i % NC;
        float s = 0.0f;
        for (int d = 0; d < D; d++) s += E[(size_t)c * D + d] * E[(size_t)c2 * D + d];
        G[i] = s;
    }
}

__global__ void sim_attn_kernel(const float* __restrict__ QK, const float* __restrict__ qa,
                                const float* __restrict__ aq, const float* __restrict__ Eq,
                                const float* __restrict__ Ek, const float* __restrict__ G,
                                float2* __restrict__ P, float* __restrict__ Wout) {
    int t = blockIdx.x, b = blockIdx.y;
    int s = threadIdx.x;
    int lane = s & 31, wd = s >> 5;
    __shared__ float g[NC * NC];
    __shared__ float part[4];
    __shared__ float pv[T];
    if (s < NC * NC) g[s] = G[s];
    __syncthreads();

    float f1[NC], f2[NC];
    const float* r1 = qa + (((size_t)b * T + t) * T + s) * NC;
    const float* r2 = aq + (((size_t)b * T + s) * T + t) * NC;
    #pragma unroll
    for (int c = 0; c < NC; c++) { f1[c] = r1[c]; f2[c] = r2[c]; }

    float sc = QK[((size_t)b * T + t) * T + s];
    const float* eq = Eq + ((size_t)b * T + t) * NC;
    const float* ek = Ek + ((size_t)b * T + s) * NC;
    #pragma unroll
    for (int c = 0; c < NC; c++) sc += f1[c] * ek[c] + f2[c] * eq[c];
    #pragma unroll
    for (int c = 0; c < NC; c++)
        #pragma unroll
        for (int c2 = 0; c2 < NC; c2++)
            sc += f1[c] * g[c * NC + c2] * f2[c2];

    float m = warp_max(sc);
    if (lane == 0) part[wd] = m;
    __syncthreads();
    float m1 = fmaxf(fmaxf(part[0], part[1]), fmaxf(part[2], part[3]));
    float e1 = expf(sc - m1);
    float ssum = warp_sum(e1);
    if (lane == 0) part[wd] = ssum;
    __syncthreads();
    float p = e1 / (part[0] + part[1] + part[2] + part[3]);

    float l = 1000.0f * p;
    m = warp_max(l);
    __syncthreads();
    if (lane == 0) part[wd] = m;
    __syncthreads();
    float m2 = fmaxf(fmaxf(part[0], part[1]), fmaxf(part[2], part[3]));
    float e2 = expf(l - m2);
    ssum = warp_sum(e2);
    __syncthreads();
    if (lane == 0) part[wd] = ssum;
    __syncthreads();
    float p2 = e2 / (part[0] + part[1] + part[2] + part[3]);
    p2 = fminf(fmaxf(p2, 0.0f), 1.0f);

    P[((size_t)b * T + t) * T + s] = split2f(p2);
    pv[s] = p2;
    __syncthreads();

    #pragma unroll
    for (int c = 0; c < NC; c++) {
        float v = warp_sum(pv[s] * f2[c]);
        __syncthreads();
        if (lane == 0) part[wd] = v;
        __syncthreads();
        if (s == 0) Wout[((size_t)b * T + t) * NC + c] = part[0] + part[1] + part[2] + part[3];
    }
}

__global__ void final_kernel(const float* __restrict__ pk, const float* __restrict__ Wm,
                             const float* __restrict__ E, const float* __restrict__ clsw,
                             const float* __restrict__ clsb, float* __restrict__ out) {
    int b = blockIdx.x;
    int d = threadIdx.x;
    __shared__ float wm[NC];
    __shared__ float red[512];

    if (d < NC) {
        float s = 0.0f;
        for (int t = 0; t < T; t++) s += Wm[((size_t)b * T + t) * NC + d];
        wm[d] = s * (1.0f / T);
    }
    __syncthreads();

    float s = 0.0f;
    for (int t = 0; t < T; t++) s += pk[((size_t)b * T + t) * D + d];
    s *= (1.0f / T);
    #pragma unroll
    for (int c = 0; c < NC; c++) s += wm[c] * E[(size_t)c * D + d];

    for (int j = 0; j < 3; j++) {
        red[d] = s * clsw[(size_t)d * 3 + j];
        __syncthreads();
        for (int off = 256; off > 0; off >>= 1) { if (d < off) red[d] += red[d + off]; __syncthreads(); }
        if (d == 0) out[b * 3 + j] = red[0] + clsb[j];
        __syncthreads();
    }
}

// ---------------- host ------------------------------------------------------
#define GEMM_SMEM_NT ((3*64*PADA + 3*16*PADB) * (int)sizeof(float2))
#define GEMM_SMEM_T  ((3*64*PADA + 3*64*PADA) * (int)sizeof(float2))
#define ATTN_SMEM    ((64 + 128) * PADQ * (int)sizeof(float2))

extern "C" void kernel_launch(void* const* d_in, const int* in_sizes, int n_in,
                              void* d_out, int out_size) {
    const float* q_emb   = (const float*)d_in[0];
    const float* a_emb   = (const float*)d_in[1];
    const float* qa_rel  = (const float*)d_in[2];
    const float* aq_rel  = (const float*)d_in[3];
    const float* conceptE= (const float*)d_in[4];
    const float* pos_emb = (const float*)d_in[5];
    const float* pe_w    = (const float*)d_in[6];
    const float* pe_b    = (const float*)d_in[7];
    const float* Wq      = (const float*)d_in[8];
    const float* bq      = (const float*)d_in[9];
    const float* Wk      = (const float*)d_in[10];
    const float* bk      = (const float*)d_in[11];
    const float* Wv      = (const float*)d_in[12];
    const float* bv      = (const float*)d_in[13];
    const float* Wo      = (const float*)d_in[14];
    const float* bo      = (const float*)d_in[15];
    const float* ff1w    = (const float*)d_in[16];
    const float* ff1b    = (const float*)d_in[17];
    const float* ff2w    = (const float*)d_in[18];
    const float* ff2b    = (const float*)d_in[19];
    const float* lninw   = (const float*)d_in[20];
    const float* lninb   = (const float*)d_in[21];
    const float* lnoutw  = (const float*)d_in[22];
    const float* lnoutb  = (const float*)d_in[23];
    const float* simWq   = (const float*)d_in[24];
    const float* simbq   = (const float*)d_in[25];
    const float* simWk   = (const float*)d_in[26];
    const float* simbk   = (const float*)d_in[27];
    const float* clsw    = (const float*)d_in[28];
    const float* clsb    = (const float*)d_in[29];
    float* out = (float*)d_out;

    float* raw = nullptr;
    float2* as = nullptr;
    float2* ws = nullptr;
    cudaGetSymbolAddress((void**)&raw, g_scratch);
    cudaGetSymbolAddress((void**)&as, g_asplit);
    cudaGetSymbolAddress((void**)&ws, g_wsplit);

    float*  X   = raw + OFF_X;
    float*  QKb = raw + OFF_QK;
    float*  EQb = raw + OFF_EQ;
    float*  EKb = raw + OFF_EK;
    float*  Gb  = raw + OFF_G;
    float*  Wb  = raw + OFF_W;
    float*  PKb = raw + OFF_PK;

    float2* XS  = as + AS_X;
    float2* HS  = as + AS_H;
    float2* QS  = as + AS_Q;
    float2* KS  = as + AS_K;
    float2* VS  = as + AS_V;
    float2* T0S = as + AS_T0;
    float2* T1S = as + AS_T1;
    float2* FFS = as + AS_FFN;
    float2* PS  = as + AS_P;

    static bool attr_done = false;
    if (!attr_done) {
        cudaFuncSetAttribute(gemm_sp<0,1>, cudaFuncAttributeMaxDynamicSharedMemorySize, GEMM_SMEM_NT);
        cudaFuncSetAttribute(gemm_sp<0,0>, cudaFuncAttributeMaxDynamicSharedMemorySize, GEMM_SMEM_NT);
        cudaFuncSetAttribute(gemm_sp<1,0>, cudaFuncAttributeMaxDynamicSharedMemorySize, GEMM_SMEM_T);
        cudaFuncSetAttribute(fused_attn, cudaFuncAttributeMaxDynamicSharedMemorySize, ATTN_SMEM);
        attr_done = true;
    }

    // weight splits
    split_weights<<<2048, 256>>>(Wq, Wk, Wv, Wo, ff1w, ff2w, simWq, simWk);

    // pos + LN both towers
    add_pos_ln_kernel<<<512, 128>>>(q_emb, pos_emb, pe_w, pe_b, X, XS);
    add_pos_ln_kernel<<<512, 128>>>(a_emb, pos_emb, pe_w, pe_b,
                                    X + (size_t)512 * D, XS + (size_t)512 * D);

    for (int i = 0; i < NL; i++) {
        const float2* wsq = ws + WS_Q + (size_t)i * D * D;
        const float2* wsk = ws + WS_K + (size_t)i * D * D;
        const float2* wsv = ws + WS_V + (size_t)i * D * D;
        const float2* wso = ws + WS_O + (size_t)i * D * D;
        const float2* wf1 = ws + WS_F1 + (size_t)i * D * DFF;
        const float2* wf2 = ws + WS_F2 + (size_t)i * DFF * D;

        // QKV fused (grid 8x16x3)
        gemm_sp<0,1><<<dim3(8, 16, 3), 256, GEMM_SMEM_NT>>>(
            XS, XS, XS, wsq, wsk, wsv,
            bq + (size_t)i * D, bk + (size_t)i * D, bv + (size_t)i * D,
            QS, KS, VS, M2, D, D, D, D, D, 0, 0, 0, 0, 1);

        fused_attn<<<dim3(2, 32), 256, ATTN_SMEM>>>(QS, KS, VS, T0S);

        // output projection (grid 8x16)
        gemm_sp<0,1><<<dim3(8, 16, 1), 256, GEMM_SMEM_NT>>>(
            T0S, 0, 0, wso, 0, 0, bo + (size_t)i * D, 0, 0,
            T1S, 0, 0, M2, D, D, D, D, D, 0, 0, 0, 0, 1);

        residual_ln_kernel<<<M2, 128>>>(X, T1S, nullptr, HS,
                                        lninw + (size_t)i * D, lninb + (size_t)i * D);

        // ff1 (grid 32x16, gelu)
        gemm_sp<0,1><<<dim3(32, 16, 1), 256, GEMM_SMEM_NT>>>(
            HS, 0, 0, wf1, 0, 0, ff1b + (size_t)i * DFF, 0, 0,
            FFS, 0, 0, M2, DFF, D, D, DFF, DFF, 1, 0, 0, 0, 1);
        // ff2 (grid 8x16)
        gemm_sp<0,1><<<dim3(8, 16, 1), 256, GEMM_SMEM_NT>>>(
            FFS, 0, 0, wf2, 0, 0, ff2b + (size_t)i * D, 0, 0,
            T1S, 0, 0, M2, D, DFF, DFF, D, D, 0, 0, 0, 0, 1);

        residual_ln_kernel<<<M2, 128>>>(X, T1S, X, XS,
                                        lnoutw + (size_t)i * D, lnoutb + (size_t)i * D);
    }

    // --- sim head ---
    gemm_sp<0,1><<<dim3(8, 8, 2), 256, GEMM_SMEM_NT>>>(
        XS, XS + (size_t)512 * D, 0, ws + WS_SQ, ws + WS_SK, 0,
        simbq, simbk, 0, QS, KS, 0,
        512, D, D, D, D, D, 0, 0, 0, 0, 1);

    edot_kernel<<<512, 256>>>(QS, conceptE, EQb);
    edot_kernel<<<512, 256>>>(KS, conceptE, EKb);
    gram_kernel<<<1, 32>>>(conceptE, Gb);

    // QK[b] = q_sim[b] @ k_sim[b]^T (grid 2x2x4)
    gemm_sp<1,0><<<dim3(2, 2, 4), 256, GEMM_SMEM_T>>>(
        QS, 0, 0, KS, 0, 0, 0, 0, 0, QKb, 0, 0,
        T, T, D, D, D, T, 0,
        (long long)T * D, (long long)T * D, (long long)T * T, 4);

    sim_attn_kernel<<<dim3(T, Bb), 128>>>(QKb, qa_rel, aq_rel, EQb, EKb, Gb, PS, Wb);

    // pk[b] = P[b] @ k_sim[b] (grid 8x2x4)
    gemm_sp<0,0><<<dim3(8, 2, 4), 256, GEMM_SMEM_NT>>>(
        PS, 0, 0, KS, 0, 0, 0, 0, 0, PKb, 0, 0,
        T, D, T, T, D, D, 0,
        (long long)T * T, (long long)T * D, (long long)T * D, 4);

    final_kernel<<<Bb, 512>>>(PKb, Wb, conceptE, clsw, clsb, out);
}

// round 5
// speedup vs baseline: 1.0001x; 1.0001x over previous
#include <cuda_runtime.h>
#include <cuda_bf16.h>
#include <math.h>

// Problem constants
#define Bb   4
#define T    128
#define D    512
#define Hh   4
#define DK   128
#define NL   4
#define DFF  2048
#define NC   5

#define M2   1024            // merged towers rows
#define NDp  (M2*D)          // 524288

// ---------------- raw scratch (float) ----------------------------------------
#define OFF_X   0
#define OFF_QK  (OFF_X + NDp)
#define OFF_EQ  (OFF_QK + 65536)
#define OFF_EK  (OFF_EQ + 2560)
#define OFF_G   (OFF_EK + 2560)
#define OFF_W   (OFF_G + 32)
#define OFF_PK  (OFF_W + 2560)
#define RAW_TOTAL (OFF_PK + 262144)
__device__ float g_scratch[RAW_TOTAL];

// ---------------- split activation scratch (float2 = hi,lo) -------------------
#define AS_X   0
#define AS_H   (AS_X + NDp)
#define AS_Q   (AS_H + NDp)
#define AS_K   (AS_Q + NDp)
#define AS_V   (AS_K + NDp)
#define AS_T0  (AS_V + NDp)
#define AS_T1  (AS_T0 + NDp)
#define AS_FFN (AS_T1 + NDp)          // M2*DFF
#define AS_P   (AS_FFN + M2*DFF)      // 4*T*T
#define ASPLIT_TOTAL (AS_P + 65536)
__device__ float2 g_asplit[ASPLIT_TOTAL];

// ---------------- split weight scratch ---------------------------------------
#define SZ1  (NL*D*D)        // 1048576
#define SZF  (NL*D*DFF)      // 4194304
#define SZS  (D*D)           // 262144
#define WS_Q  0
#define WS_K  (WS_Q + SZ1)
#define WS_V  (WS_K + SZ1)
#define WS_O  (WS_V + SZ1)
#define WS_F1 (WS_O + SZ1)
#define WS_F2 (WS_F1 + SZF)
#define WS_SQ (WS_F2 + SZF)
#define WS_SK (WS_SQ + SZS)
#define WS_TOTAL (WS_SK + SZS)       // 13107200
__device__ float2 g_wsplit[WS_TOTAL];

__device__ __forceinline__ float gelu_f(float x) {
    return 0.5f * x * (1.0f + erff(x * 0.7071067811865475f));
}

// ---------------- tf32 / mma / cp.async helpers ------------------------------
__device__ __forceinline__ unsigned f2tf32(float x) {
    unsigned r;
    asm("cvt.rna.tf32.f32 %0, %1;" : "=r"(r) : "f"(x));
    return r;
}
__device__ __forceinline__ float2 split2f(float x) {
    float hi = __uint_as_float(f2tf32(x));
    float lo = __uint_as_float(f2tf32(x - hi));
    return make_float2(hi, lo);
}
__device__ __forceinline__ void mma_tf32(float* c, const unsigned* a, const unsigned* b) {
    asm volatile(
        "mma.sync.aligned.m16n8k8.row.col.f32.tf32.tf32.f32 "
        "{%0,%1,%2,%3},{%4,%5,%6,%7},{%8,%9},{%0,%1,%2,%3};"
        : "+f"(c[0]), "+f"(c[1]), "+f"(c[2]), "+f"(c[3])
        : "r"(a[0]), "r"(a[1]), "r"(a[2]), "r"(a[3]), "r"(b[0]), "r"(b[1]));
}
__device__ __forceinline__ void mma3(float* c, const unsigned* ah, const unsigned* al,
                                     const unsigned* bh, const unsigned* bl) {
    mma_tf32(c, ah, bh);
    mma_tf32(c, ah, bl);
    mma_tf32(c, al, bh);
}
__device__ __forceinline__ void fragA(const float2 v0, const float2 v1, const float2 v2, const float2 v3,
                                      unsigned* h, unsigned* l) {
    h[0] = __float_as_uint(v0.x); l[0] = __float_as_uint(v0.y);
    h[1] = __float_as_uint(v1.x); l[1] = __float_as_uint(v1.y);
    h[2] = __float_as_uint(v2.x); l[2] = __float_as_uint(v2.y);
    h[3] = __float_as_uint(v3.x); l[3] = __float_as_uint(v3.y);
}
__device__ __forceinline__ void cp16(void* s, const void* g) {
    unsigned sa = (unsigned)__cvta_generic_to_shared(s);
    asm volatile("cp.async.cg.shared.global [%0], [%1], 16;\n" :: "r"(sa), "l"(g) : "memory");
}
#define CP_COMMIT() asm volatile("cp.async.commit_group;\n" ::: "memory")
#define CP_WAIT(n)  asm volatile("cp.async.wait_group %0;\n" :: "n"(n) : "memory")

// ---------------- weight split prep ------------------------------------------
__global__ void split_weights(const float* __restrict__ Wq, const float* __restrict__ Wk,
                              const float* __restrict__ Wv, const float* __restrict__ Wo,
                              const float* __restrict__ f1, const float* __restrict__ f2,
                              const float* __restrict__ sq, const float* __restrict__ sk) {
    for (long long i = (long long)blockIdx.x * blockDim.x + threadIdx.x; i < WS_TOTAL;
         i += (long long)gridDim.x * blockDim.x) {
        const float* s; long long o;
        if (i < WS_K)        { s = Wq; o = i - WS_Q; }
        else if (i < WS_V)   { s = Wk; o = i - WS_K; }
        else if (i < WS_O)   { s = Wv; o = i - WS_V; }
        else if (i < WS_F1)  { s = Wo; o = i - WS_O; }
        else if (i < WS_F2)  { s = f1; o = i - WS_F1; }
        else if (i < WS_SQ)  { s = f2; o = i - WS_F2; }
        else if (i < WS_SK)  { s = sq; o = i - WS_SQ; }
        else                 { s = sk; o = i - WS_SK; }
        g_wsplit[i] = split2f(s[o]);
    }
}

// ---------------- pre-split 3xTF32 GEMM, 64x64 tile, 3-stage cp.async --------
// A,B: float2 (hi,lo) planes. C: OUTS=0 -> raw float, OUTS=1 -> split float2.
#define PADA 18
#define PADB 68

template<int TRANSB, int OUTS>
__global__ __launch_bounds__(256, 2)
void gemm_sp(const float2* __restrict__ A0, const float2* __restrict__ A1, const float2* __restrict__ A2,
             const float2* __restrict__ W0, const float2* __restrict__ W1, const float2* __restrict__ W2,
             const float* __restrict__ bias0, const float* __restrict__ bias1, const float* __restrict__ bias2,
             void* C0v, void* C1v, void* C2v,
             int M, int N, int K, int lda, int ldb, int ldc,
             int act,
             long long sA, long long sB, long long sC, int zPerSet) {
    int z = blockIdx.z;
    int set = z / zPerSet;
    int zz = z % zPerSet;

    const float2* A  = (set == 0) ? A0 : (set == 1 ? A1 : A2);
    const float2* Bm = (set == 0) ? W0 : (set == 1 ? W1 : W2);
    const float* bias = (set == 0) ? bias0 : (set == 1 ? bias1 : bias2);
    void* Cv = (set == 0) ? C0v : (set == 1 ? C1v : C2v);
    A  += zz * sA;
    Bm += zz * sB;

    extern __shared__ float2 smp[];
    float2* As = smp;                                 // [3][64][PADA]
    constexpr int BR = TRANSB ? 64 : 16;
    constexpr int BC = TRANSB ? PADA : PADB;
    float2* Bs = smp + 3 * 64 * PADA;                 // [3][BR][BC]
#define ASM(s,r,c) As[((s)*64+(r))*PADA+(c)]
#define BSM(s,r,c) Bs[((s)*BR+(r))*BC+(c)]

    int tid = threadIdx.x;
    int lane = tid & 31, wid = tid >> 5;
    int wm = wid & 1, wn = wid >> 1;
    int l3 = lane & 3, l2 = lane >> 2;

    int bm = blockIdx.y * 64;
    int bn = blockIdx.x * 64;

    // load indices (cp16 = 2 float2)
    int ar0 = tid >> 3, ac = (tid & 7) * 2;       // A: 64 rows x 8 units, 2 rounds
    int nbr = tid >> 5, nbc = (tid & 31) * 2;     // B nt: 16 rows x 32 units, 2 rounds? 512 units/256 = 2

    float acc[2][2][4] = {};
    int nk = K / 16;

    // prologue
    #pragma unroll
    for (int p = 0; p < 2; p++) {
        int k0 = p * 16;
        cp16(&ASM(p, ar0, ac),      A + (size_t)(bm + ar0) * lda + k0 + ac);
        cp16(&ASM(p, ar0 + 32, ac), A + (size_t)(bm + ar0 + 32) * lda + k0 + ac);
        if (TRANSB) {
            cp16(&BSM(p, ar0, ac),      Bm + (size_t)(bn + ar0) * ldb + k0 + ac);
            cp16(&BSM(p, ar0 + 32, ac), Bm + (size_t)(bn + ar0 + 32) * ldb + k0 + ac);
        } else {
            cp16(&BSM(p, nbr, nbc),     Bm + (size_t)(k0 + nbr) * ldb + bn + nbc);
            cp16(&BSM(p, nbr + 8, nbc), Bm + (size_t)(k0 + nbr + 8) * ldb + bn + nbc);
        }
        CP_COMMIT();
    }

    for (int kt = 0; kt < nk; kt++) {
        CP_WAIT(1);
        __syncthreads();
        int st = kt % 3;
        if (kt + 2 < nk) {
            int ns = (kt + 2) % 3;
            int k0 = (kt + 2) * 16;
            cp16(&ASM(ns, ar0, ac),      A + (size_t)(bm + ar0) * lda + k0 + ac);
            cp16(&ASM(ns, ar0 + 32, ac), A + (size_t)(bm + ar0 + 32) * lda + k0 + ac);
            if (TRANSB) {
                cp16(&BSM(ns, ar0, ac),      Bm + (size_t)(bn + ar0) * ldb + k0 + ac);
                cp16(&BSM(ns, ar0 + 32, ac), Bm + (size_t)(bn + ar0 + 32) * ldb + k0 + ac);
            } else {
                cp16(&BSM(ns, nbr, nbc),     Bm + (size_t)(k0 + nbr) * ldb + bn + nbc);
                cp16(&BSM(ns, nbr + 8, nbc), Bm + (size_t)(k0 + nbr + 8) * ldb + bn + nbc);
            }
        }
        CP_COMMIT();

        #pragma unroll
        for (int ks = 0; ks < 16; ks += 8) {
            unsigned ah[2][4], al[2][4], bh[2][2], bl[2][2];
            #pragma unroll
            for (int i = 0; i < 2; i++) {
                int m0 = wm * 32 + i * 16;
                fragA(ASM(st, m0 + l2, ks + l3),     ASM(st, m0 + l2 + 8, ks + l3),
                      ASM(st, m0 + l2, ks + l3 + 4), ASM(st, m0 + l2 + 8, ks + l3 + 4),
                      ah[i], al[i]);
            }
            #pragma unroll
            for (int j = 0; j < 2; j++) {
                int n0 = wn * 16 + j * 8;
                float2 b0, b1;
                if (TRANSB) { b0 = BSM(st, n0 + l2, ks + l3); b1 = BSM(st, n0 + l2, ks + l3 + 4); }
                else        { b0 = BSM(st, ks + l3, n0 + l2); b1 = BSM(st, ks + l3 + 4, n0 + l2); }
                bh[j][0] = __float_as_uint(b0.x); bl[j][0] = __float_as_uint(b0.y);
                bh[j][1] = __float_as_uint(b1.x); bl[j][1] = __float_as_uint(b1.y);
            }
            #pragma unroll
            for (int i = 0; i < 2; i++)
                #pragma unroll
                for (int j = 0; j < 2; j++)
                    mma3(acc[i][j], ah[i], al[i], bh[j], bl[j]);
        }
    }

    // epilogue
    #pragma unroll
    for (int i = 0; i < 2; i++) {
        #pragma unroll
        for (int j = 0; j < 2; j++) {
            int rg = bm + wm * 32 + i * 16 + l2;
            int cg = bn + wn * 16 + j * 8 + 2 * l3;
            float bv0 = bias ? bias[cg] : 0.0f;
            float bv1 = bias ? bias[cg + 1] : 0.0f;
            float v0 = acc[i][j][0] + bv0, v1 = acc[i][j][1] + bv1;
            float v2 = acc[i][j][2] + bv0, v3 = acc[i][j][3] + bv1;
            if (act) { v0 = gelu_f(v0); v1 = gelu_f(v1); v2 = gelu_f(v2); v3 = gelu_f(v3); }
            if (OUTS == 0) {
                float* C = (float*)Cv + zz * sC;
                *(float2*)(C + (size_t)rg * ldc + cg) = make_float2(v0, v1);
                *(float2*)(C + (size_t)(rg + 8) * ldc + cg) = make_float2(v2, v3);
            } else {
                float2* C = (float2*)Cv + zz * sC;
                float2 s0 = split2f(v0), s1 = split2f(v1), s2 = split2f(v2), s3 = split2f(v3);
                *(float4*)&C[(size_t)rg * ldc + cg] = make_float4(s0.x, s0.y, s1.x, s1.y);
                *(float4*)&C[(size_t)(rg + 8) * ldc + cg] = make_float4(s2.x, s2.y, s3.x, s3.y);
            }
        }
    }
#undef ASM
#undef BSM
}

// ---------------- fused attention (split I/O) --------------------------------
#define PADQ 130
__global__ __launch_bounds__(256)
void fused_attn(const float2* __restrict__ Q, const float2* __restrict__ K,
                const float2* __restrict__ V, float2* __restrict__ O) {
    extern __shared__ float2 dyn2[];
    float2* Pbuf = dyn2;                  // [64][PADQ]
    float2* Kbuf = dyn2 + 64 * PADQ;      // [128][PADQ]
    __shared__ float redM[64][4];
    __shared__ float redS[64][4];

    int bz = blockIdx.y;
    int bb = bz >> 2, h = bz & 3;
    int qbase = blockIdx.x * 64;

    int tid = threadIdx.x;
    int lane = tid & 31, wid = tid >> 5;
    int wm = wid & 1, wn = wid >> 1;
    int l3 = lane & 3, l2 = lane >> 2;

    const float2* Qg = Q + ((size_t)bb * T + qbase) * D + h * DK;
    const float2* Kg = K + ((size_t)bb * T) * D + h * DK;
    const float2* Vg = V + ((size_t)bb * T) * D + h * DK;

    #pragma unroll
    for (int t = 0; t < 16; t++) {
        int u = tid + t * 256;
        int r = u >> 6, c = (u & 63) * 2;
        cp16(&Pbuf[r * PADQ + c], Qg + (size_t)r * D + c);
    }
    CP_COMMIT();
    #pragma unroll
    for (int t = 0; t < 32; t++) {
        int u = tid + t * 256;
        int r = u >> 6, c = (u & 63) * 2;
        cp16(&Kbuf[r * PADQ + c], Kg + (size_t)r * D + c);
    }
    CP_COMMIT();
    CP_WAIT(0);
    __syncthreads();

    // phase 1: S = Q @ K^T
    float acc[2][4][4] = {};
    #pragma unroll 4
    for (int ks = 0; ks < DK; ks += 8) {
        unsigned ah[2][4], al[2][4], bh[4][2], bl[4][2];
        #pragma unroll
        for (int i = 0; i < 2; i++) {
            int m0 = wm * 32 + i * 16;
            fragA(Pbuf[(m0 + l2) * PADQ + ks + l3],     Pbuf[(m0 + l2 + 8) * PADQ + ks + l3],
                  Pbuf[(m0 + l2) * PADQ + ks + l3 + 4], Pbuf[(m0 + l2 + 8) * PADQ + ks + l3 + 4],
                  ah[i], al[i]);
        }
        #pragma unroll
        for (int j = 0; j < 4; j++) {
            int n0 = wn * 32 + j * 8;
            float2 b0 = Kbuf[(n0 + l2) * PADQ + ks + l3];
            float2 b1 = Kbuf[(n0 + l2) * PADQ + ks + l3 + 4];
            bh[j][0] = __float_as_uint(b0.x); bl[j][0] = __float_as_uint(b0.y);
            bh[j][1] = __float_as_uint(b1.x); bl[j][1] = __float_as_uint(b1.y);
        }
        #pragma unroll
        for (int i = 0; i < 2; i++)
            #pragma unroll
            for (int j = 0; j < 4; j++)
                mma3(acc[i][j], ah[i], al[i], bh[j], bl[j]);
    }
    __syncthreads();   // Q/K reads done

    // V load overlaps softmax
    #pragma unroll
    for (int t = 0; t < 32; t++) {
        int u = tid + t * 256;
        int r = u >> 6, c = (u & 63) * 2;
        cp16(&Kbuf[r * PADQ + c], Vg + (size_t)r * D + c);
    }
    CP_COMMIT();

    const float sc = 0.08838834764831845f;
    #pragma unroll
    for (int i = 0; i < 2; i++)
        #pragma unroll
        for (int j = 0; j < 4; j++)
            #pragma unroll
            for (int q = 0; q < 4; q++) acc[i][j][q] *= sc;

    #pragma unroll
    for (int i = 0; i < 2; i++)
        #pragma unroll
        for (int hf = 0; hf < 2; hf++) {
            int row = wm * 32 + i * 16 + l2 + hf * 8;
            float m = -1e30f;
            #pragma unroll
            for (int j = 0; j < 4; j++) m = fmaxf(m, fmaxf(acc[i][j][2 * hf], acc[i][j][2 * hf + 1]));
            m = fmaxf(m, __shfl_xor_sync(0xffffffff, m, 1));
            m = fmaxf(m, __shfl_xor_sync(0xffffffff, m, 2));
            if (l3 == 0) redM[row][wn] = m;
        }
    __syncthreads();
    #pragma unroll
    for (int i = 0; i < 2; i++)
        #pragma unroll
        for (int hf = 0; hf < 2; hf++) {
            int row = wm * 32 + i * 16 + l2 + hf * 8;
            float m = fmaxf(fmaxf(redM[row][0], redM[row][1]), fmaxf(redM[row][2], redM[row][3]));
            float s = 0.0f;
            #pragma unroll
            for (int j = 0; j < 4; j++) {
                acc[i][j][2 * hf]     = expf(acc[i][j][2 * hf] - m);
                acc[i][j][2 * hf + 1] = expf(acc[i][j][2 * hf + 1] - m);
                s += acc[i][j][2 * hf] + acc[i][j][2 * hf + 1];
            }
            s += __shfl_xor_sync(0xffffffff, s, 1);
            s += __shfl_xor_sync(0xffffffff, s, 2);
            if (l3 == 0) redS[row][wn] = s;
        }
    __syncthreads();
    // normalize + split + write P
    #pragma unroll
    for (int i = 0; i < 2; i++)
        #pragma unroll
        for (int hf = 0; hf < 2; hf++) {
            int row = wm * 32 + i * 16 + l2 + hf * 8;
            float inv = 1.0f / (redS[row][0] + redS[row][1] + redS[row][2] + redS[row][3]);
            #pragma unroll
            for (int j = 0; j < 4; j++) {
                int col = wn * 32 + j * 8 + 2 * l3;
                float2 s0 = split2f(acc[i][j][2 * hf] * inv);
                float2 s1 = split2f(acc[i][j][2 * hf + 1] * inv);
                *(float4*)&Pbuf[row * PADQ + col] = make_float4(s0.x, s0.y, s1.x, s1.y);
            }
        }
    CP_WAIT(0);
    __syncthreads();

    // phase 2: O = P @ V
    float out[2][4][4] = {};
    #pragma unroll 4
    for (int ks = 0; ks < T; ks += 8) {
        unsigned ah[2][4], al[2][4], bh[4][2], bl[4][2];
        #pragma unroll
        for (int i = 0; i < 2; i++) {
            int m0 = wm * 32 + i * 16;
            fragA(Pbuf[(m0 + l2) * PADQ + ks + l3],     Pbuf[(m0 + l2 + 8) * PADQ + ks + l3],
                  Pbuf[(m0 + l2) * PADQ + ks + l3 + 4], Pbuf[(m0 + l2 + 8) * PADQ + ks + l3 + 4],
                  ah[i], al[i]);
        }
        #pragma unroll
        for (int j = 0; j < 4; j++) {
            int n0 = wn * 32 + j * 8;
            float2 b0 = Kbuf[(ks + l3) * PADQ + n0 + l2];
            float2 b1 = Kbuf[(ks + l3 + 4) * PADQ + n0 + l2];
            bh[j][0] = __float_as_uint(b0.x); bl[j][0] = __float_as_uint(b0.y);
            bh[j][1] = __float_as_uint(b1.x); bl[j][1] = __float_as_uint(b1.y);
        }
        #pragma unroll
        for (int i = 0; i < 2; i++)
            #pragma unroll
            for (int j = 0; j < 4; j++)
                mma3(out[i][j], ah[i], al[i], bh[j], bl[j]);
    }

    float2* Og = O + ((size_t)bb * T + qbase) * D + h * DK;
    #pragma unroll
    for (int i = 0; i < 2; i++)
        #pragma unroll
        for (int j = 0; j < 4; j++) {
            int r = wm * 32 + i * 16 + l2;
            int c = wn * 32 + j * 8 + 2 * l3;
            float2 s0 = split2f(out[i][j][0]), s1 = split2f(out[i][j][1]);
            float2 s2 = split2f(out[i][j][2]), s3 = split2f(out[i][j][3]);
            *(float4*)&Og[(size_t)r * D + c] = make_float4(s0.x, s0.y, s1.x, s1.y);
            *(float4*)&Og[(size_t)(r + 8) * D + c] = make_float4(s2.x, s2.y, s3.x, s3.y);
        }
}

// ---------------- warp helpers ----------------------------------------------
__device__ __forceinline__ float warp_sum(float v) {
    #pragma unroll
    for (int o = 16; o > 0; o >>= 1) v += __shfl_xor_sync(0xffffffff, v, o);
    return v;
}
__device__ __forceinline__ float warp_max(float v) {
    #pragma unroll
    for (int o = 16; o > 0; o >>= 1) v = fmaxf(v, __shfl_xor_sync(0xffffffff, v, o));
    return v;
}

// ---------------- LayerNorm kernels (128 threads, 4 elems/thread) ------------
__global__ void add_pos_ln_kernel(const float* __restrict__ x, const float* __restrict__ pos,
                                  const float* __restrict__ w, const float* __restrict__ b,
                                  float* __restrict__ raw_out, float2* __restrict__ outs) {
    int row = blockIdx.x, tid = threadIdx.x;
    int lane = tid & 31, wd = tid >> 5;
    __shared__ float p1[4], p2[4];

    float4 xv = ((const float4*)(x + (size_t)row * D))[tid];
    float4 pv = ((const float4*)(pos + (size_t)(row % T) * D))[tid];
    float4 v = make_float4(xv.x + pv.x, xv.y + pv.y, xv.z + pv.z, xv.w + pv.w);

    float s = warp_sum(v.x + v.y + v.z + v.w);
    if (lane == 0) p1[wd] = s;
    __syncthreads();
    float mean = (p1[0] + p1[1] + p1[2] + p1[3]) * (1.0f / D);
    float4 d = make_float4(v.x - mean, v.y - mean, v.z - mean, v.w - mean);
    float q = warp_sum(d.x * d.x + d.y * d.y + d.z * d.z + d.w * d.w);
    if (lane == 0) p2[wd] = q;
    __syncthreads();
    float inv = rsqrtf((p2[0] + p2[1] + p2[2] + p2[3]) * (1.0f / D) + 1e-12f);

    float4 wv = ((const float4*)w)[tid];
    float4 bv = ((const float4*)b)[tid];
    float4 n = make_float4(wv.x * d.x * inv + bv.x, wv.y * d.y * inv + bv.y,
                           wv.z * d.z * inv + bv.z, wv.w * d.w * inv + bv.w);
    ((float4*)(raw_out + (size_t)row * D))[tid] = n;
    float2* orow = outs + (size_t)row * D + tid * 4;
    float2 s0 = split2f(n.x), s1 = split2f(n.y), s2 = split2f(n.z), s3 = split2f(n.w);
    *(float4*)orow       = make_float4(s0.x, s0.y, s1.x, s1.y);
    *(float4*)(orow + 2) = make_float4(s2.x, s2.y, s3.x, s3.y);
}

// x += (y.hi+y.lo) (persist); LN -> split outs, optionally raw_out
__global__ void residual_ln_kernel(float* __restrict__ x, const float2* __restrict__ ys,
                                   float* __restrict__ raw_out, float2* __restrict__ outs,
                                   const float* __restrict__ w, const float* __restrict__ b) {
    int row = blockIdx.x, tid = threadIdx.x;
    int lane = tid & 31, wd = tid >> 5;
    __shared__ float p1[4], p2[4];

    float4 xv = ((const float4*)(x + (size_t)row * D))[tid];
    const float2* yr = ys + (size_t)row * D + tid * 4;
    float2 y0 = yr[0], y1 = yr[1], y2 = yr[2], y3 = yr[3];
    float4 v = make_float4(xv.x + y0.x + y0.y, xv.y + y1.x + y1.y,
                           xv.z + y2.x + y2.y, xv.w + y3.x + y3.y);
    ((float4*)(x + (size_t)row * D))[tid] = v;

    float s = warp_sum(v.x + v.y + v.z + v.w);
    if (lane == 0) p1[wd] = s;
    __syncthreads();
    float mean = (p1[0] + p1[1] + p1[2] + p1[3]) * (1.0f / D);
    float4 d = make_float4(v.x - mean, v.y - mean, v.z - mean, v.w - mean);
    float q = warp_sum(d.x * d.x + d.y * d.y + d.z * d.z + d.w * d.w);
    if (lane == 0) p2[wd] = q;
    __syncthreads();
    float inv = rsqrtf((p2[0] + p2[1] + p2[2] + p2[3]) * (1.0f / D) + 1e-12f);

    float4 wv = ((const float4*)w)[tid];
    float4 bv = ((const float4*)b)[tid];
    float4 n = make_float4(wv.x * d.x * inv + bv.x, wv.y * d.y * inv + bv.y,
                           wv.z * d.z * inv + bv.z, wv.w * d.w * inv + bv.w);
    if (raw_out) ((float4*)(raw_out + (size_t)row * D))[tid] = n;
    float2* orow = outs + (size_t)row * D + tid * 4;
    float2 s0 = split2f(n.x), s1 = split2f(n.y), s2 = split2f(n.z), s3 = split2f(n.w);
    *(float4*)orow       = make_float4(s0.x, s0.y, s1.x, s1.y);
    *(float4*)(orow + 2) = make_float4(s2.x, s2.y, s3.x, s3.y);
}

// ---------------- sim head helpers ------------------------------------------
__global__ void edot_kernel(const float2* __restrict__ Xs, const float* __restrict__ E,
                            float* __restrict__ out) {
    int row = blockIdx.x;
    int tid = threadIdx.x;
    __shared__ float red[NC * 256];
    float acc[NC] = {};
    for (int d = tid; d < D; d += 256) {
        float2 xv = Xs[(size_t)row * D + d];
        float x = xv.x + xv.y;
        #pragma unroll
        for (int c = 0; c < NC; c++) acc[c] += x * E[(size_t)c * D + d];
    }
    #pragma unroll
    for (int c = 0; c < NC; c++) red[c * 256 + tid] = acc[c];
    __syncthreads();
    for (int off = 128; off > 0; off >>= 1) {
        if (tid < off) {
            #pragma unroll
            for (int c = 0; c < NC; c++) red[c * 256 + tid] += red[c * 256 + tid + off];
        }
        __syncthreads();
    }
    if (tid < NC) out[(size_t)row * NC + tid] = red[tid * 256];
}

__global__ void gram_kernel(const float* __restrict__ E, float* __restrict__ G) {
    int i = threadIdx.x;
    if (i < NC * NC) {
        int c = i / NC, c2 = i % NC;
        float s = 0.0f;
        for (int d = 0; d < D; d++) s += E[(size_t)c * D + d] * E[(size_t)c2 * D + d];
        G[i] = s;
    }
}

__global__ void sim_attn_kernel(const float* __restrict__ QK, const float* __restrict__ qa,
                                const float* __restrict__ aq, const float* __restrict__ Eq,
                                const float* __restrict__ Ek, const float* __restrict__ G,
                                float2* __restrict__ P, float* __restrict__ Wout) {
    int t = blockIdx.x, b = blockIdx.y;
    int s = threadIdx.x;
    int lane = s & 31, wd = s >> 5;
    __shared__ float g[NC * NC];
    __shared__ float part[4];
    __shared__ float pv[T];
    if (s < NC * NC) g[s] = G[s];
    __syncthreads();

    float f1[NC], f2[NC];
    const float* r1 = qa + (((size_t)b * T + t) * T + s) * NC;
    const float* r2 = aq + (((size_t)b * T + s) * T + t) * NC;
    #pragma unroll
    for (int c = 0; c < NC; c++) { f1[c] = r1[c]; f2[c] = r2[c]; }

    float sc = QK[((size_t)b * T + t) * T + s];
    const float* eq = Eq + ((size_t)b * T + t) * NC;
    const float* ek = Ek + ((size_t)b * T + s) * NC;
    #pragma unroll
    for (int c = 0; c < NC; c++) sc += f1[c] * ek[c] + f2[c] * eq[c];
    #pragma unroll
    for (int c = 0; c < NC; c++)
        #pragma unroll
        for (int c2 = 0; c2 < NC; c2++)
            sc += f1[c] * g[c * NC + c2] * f2[c2];

    float m = warp_max(sc);
    if (lane == 0) part[wd] = m;
    __syncthreads();
    float m1 = fmaxf(fmaxf(part[0], part[1]), fmaxf(part[2], part[3]));
    float e1 = expf(sc - m1);
    float ssum = warp_sum(e1);
    if (lane == 0) part[wd] = ssum;
    __syncthreads();
    float p = e1 / (part[0] + part[1] + part[2] + part[3]);

    float l = 1000.0f * p;
    m = warp_max(l);
    __syncthreads();
    if (lane == 0) part[wd] = m;
    __syncthreads();
    float m2 = fmaxf(fmaxf(part[0], part[1]), fmaxf(part[2], part[3]));
    float e2 = expf(l - m2);
    ssum = warp_sum(e2);
    __syncthreads();
    if (lane == 0) part[wd] = ssum;
    __syncthreads();
    float p2 = e2 / (part[0] + part[1] + part[2] + part[3]);
    p2 = fminf(fmaxf(p2, 0.0f), 1.0f);

    P[((size_t)b * T + t) * T + s] = split2f(p2);
    pv[s] = p2;
    __syncthreads();

    #pragma unroll
    for (int c = 0; c < NC; c++) {
        float v = warp_sum(pv[s] * f2[c]);
        __syncthreads();
        if (lane == 0) part[wd] = v;
        __syncthreads();
        if (s == 0) Wout[((size_t)b * T + t) * NC + c] = part[0] + part[1] + part[2] + part[3];
    }
}

__global__ void final_kernel(const float* __restrict__ pk, const float* __restrict__ Wm,
                             const float* __restrict__ E, const float* __restrict__ clsw,
                             const float* __restrict__ clsb, float* __restrict__ out) {
    int b = blockIdx.x;
    int d = threadIdx.x;
    __shared__ float wm[NC];
    __shared__ float red[512];

    if (d < NC) {
        float s = 0.0f;
        for (int t = 0; t < T; t++) s += Wm[((size_t)b * T + t) * NC + d];
        wm[d] = s * (1.0f / T);
    }
    __syncthreads();

    float s = 0.0f;
    for (int t = 0; t < T; t++) s += pk[((size_t)b * T + t) * D + d];
    s *= (1.0f / T);
    #pragma unroll
    for (int c = 0; c < NC; c++) s += wm[c] * E[(size_t)c * D + d];

    for (int j = 0; j < 3; j++) {
        red[d] = s * clsw[(size_t)d * 3 + j];
        __syncthreads();
        for (int off = 256; off > 0; off >>= 1) { if (d < off) red[d] += red[d + off]; __syncthreads(); }
        if (d == 0) out[b * 3 + j] = red[0] + clsb[j];
        __syncthreads();
    }
}

// ---------------- host ------------------------------------------------------
#define GEMM_SMEM_NT ((3*64*PADA + 3*16*PADB) * (int)sizeof(float2))
#define GEMM_SMEM_T  ((3*64*PADA + 3*64*PADA) * (int)sizeof(float2))
#define ATTN_SMEM    ((64 + 128) * PADQ * (int)sizeof(float2))

extern "C" void kernel_launch(void* const* d_in, const int* in_sizes, int n_in,
                              void* d_out, int out_size) {
    const float* q_emb   = (const float*)d_in[0];
    const float* a_emb   = (const float*)d_in[1];
    const float* qa_rel  = (const float*)d_in[2];
    const float* aq_rel  = (const float*)d_in[3];
    const float* conceptE= (const float*)d_in[4];
    const float* pos_emb = (const float*)d_in[5];
    const float* pe_w    = (const float*)d_in[6];
    const float* pe_b    = (const float*)d_in[7];
    const float* Wq      = (const float*)d_in[8];
    const float* bq      = (const float*)d_in[9];
    const float* Wk      = (const float*)d_in[10];
    const float* bk      = (const float*)d_in[11];
    const float* Wv      = (const float*)d_in[12];
    const float* bv      = (const float*)d_in[13];
    const float* Wo      = (const float*)d_in[14];
    const float* bo      = (const float*)d_in[15];
    const float* ff1w    = (const float*)d_in[16];
    const float* ff1b    = (const float*)d_in[17];
    const float* ff2w    = (const float*)d_in[18];
    const float* ff2b    = (const float*)d_in[19];
    const float* lninw   = (const float*)d_in[20];
    const float* lninb   = (const float*)d_in[21];
    const float* lnoutw  = (const float*)d_in[22];
    const float* lnoutb  = (const float*)d_in[23];
    const float* simWq   = (const float*)d_in[24];
    const float* simbq   = (const float*)d_in[25];
    const float* simWk   = (const float*)d_in[26];
    const float* simbk   = (const float*)d_in[27];
    const float* clsw    = (const float*)d_in[28];
    const float* clsb    = (const float*)d_in[29];
    float* out = (float*)d_out;

    float* raw = nullptr;
    float2* as = nullptr;
    float2* ws = nullptr;
    cudaGetSymbolAddress((void**)&raw, g_scratch);
    cudaGetSymbolAddress((void**)&as, g_asplit);
    cudaGetSymbolAddress((void**)&ws, g_wsplit);

    float*  X   = raw + OFF_X;
    float*  QKb = raw + OFF_QK;
    float*  EQb = raw + OFF_EQ;
    float*  EKb = raw + OFF_EK;
    float*  Gb  = raw + OFF_G;
    float*  Wb  = raw + OFF_W;
    float*  PKb = raw + OFF_PK;

    float2* XS  = as + AS_X;
    float2* HS  = as + AS_H;
    float2* QS  = as + AS_Q;
    float2* KS  = as + AS_K;
    float2* VS  = as + AS_V;
    float2* T0S = as + AS_T0;
    float2* T1S = as + AS_T1;
    float2* FFS = as + AS_FFN;
    float2* PS  = as + AS_P;

    static bool attr_done = false;
    if (!attr_done) {
        cudaFuncSetAttribute(gemm_sp<0,1>, cudaFuncAttributeMaxDynamicSharedMemorySize, GEMM_SMEM_NT);
        cudaFuncSetAttribute(gemm_sp<0,0>, cudaFuncAttributeMaxDynamicSharedMemorySize, GEMM_SMEM_NT);
        cudaFuncSetAttribute(gemm_sp<1,0>, cudaFuncAttributeMaxDynamicSharedMemorySize, GEMM_SMEM_T);
        cudaFuncSetAttribute(fused_attn, cudaFuncAttributeMaxDynamicSharedMemorySize, ATTN_SMEM);
        attr_done = true;
    }

    // weight splits
    split_weights<<<2048, 256>>>(Wq, Wk, Wv, Wo, ff1w, ff2w, simWq, simWk);

    // pos + LN both towers
    add_pos_ln_kernel<<<512, 128>>>(q_emb, pos_emb, pe_w, pe_b, X, XS);
    add_pos_ln_kernel<<<512, 128>>>(a_emb, pos_emb, pe_w, pe_b,
                                    X + (size_t)512 * D, XS + (size_t)512 * D);

    for (int i = 0; i < NL; i++) {
        const float2* wsq = ws + WS_Q + (size_t)i * D * D;
        const float2* wsk = ws + WS_K + (size_t)i * D * D;
        const float2* wsv = ws + WS_V + (size_t)i * D * D;
        const float2* wso = ws + WS_O + (size_t)i * D * D;
        const float2* wf1 = ws + WS_F1 + (size_t)i * D * DFF;
        const float2* wf2 = ws + WS_F2 + (size_t)i * DFF * D;

        // QKV fused (grid 8x16x3)
        gemm_sp<0,1><<<dim3(8, 16, 3), 256, GEMM_SMEM_NT>>>(
            XS, XS, XS, wsq, wsk, wsv,
            bq + (size_t)i * D, bk + (size_t)i * D, bv + (size_t)i * D,
            QS, KS, VS, M2, D, D, D, D, D, 0, 0, 0, 0, 1);

        fused_attn<<<dim3(2, 32), 256, ATTN_SMEM>>>(QS, KS, VS, T0S);

        // output projection (grid 8x16)
        gemm_sp<0,1><<<dim3(8, 16, 1), 256, GEMM_SMEM_NT>>>(
            T0S, 0, 0, wso, 0, 0, bo + (size_t)i * D, 0, 0,
            T1S, 0, 0, M2, D, D, D, D, D, 0, 0, 0, 0, 1);

        residual_ln_kernel<<<M2, 128>>>(X, T1S, nullptr, HS,
                                        lninw + (size_t)i * D, lninb + (size_t)i * D);

        // ff1 (grid 32x16, gelu)
        gemm_sp<0,1><<<dim3(32, 16, 1), 256, GEMM_SMEM_NT>>>(
            HS, 0, 0, wf1, 0, 0, ff1b + (size_t)i * DFF, 0, 0,
            FFS, 0, 0, M2, DFF, D, D, DFF, DFF, 1, 0, 0, 0, 1);
        // ff2 (grid 8x16)
        gemm_sp<0,1><<<dim3(8, 16, 1), 256, GEMM_SMEM_NT>>>(
            FFS, 0, 0, wf2, 0, 0, ff2b + (size_t)i * D, 0, 0,
            T1S, 0, 0, M2, D, DFF, DFF, D, D, 0, 0, 0, 0, 1);

        residual_ln_kernel<<<M2, 128>>>(X, T1S, X, XS,
                                        lnoutw + (size_t)i * D, lnoutb + (size_t)i * D);
    }

    // --- sim head ---
    gemm_sp<0,1><<<dim3(8, 8, 2), 256, GEMM_SMEM_NT>>>(
        XS, XS + (size_t)512 * D, 0, ws + WS_SQ, ws + WS_SK, 0,
        simbq, simbk, 0, QS, KS, 0,
        512, D, D, D, D, D, 0, 0, 0, 0, 1);

    edot_kernel<<<512, 256>>>(QS, conceptE, EQb);
    edot_kernel<<<512, 256>>>(KS, conceptE, EKb);
    gram_kernel<<<1, 32>>>(conceptE, Gb);

    // QK[b] = q_sim[b] @ k_sim[b]^T (grid 2x2x4)
    gemm_sp<1,0><<<dim3(2, 2, 4), 256, GEMM_SMEM_T>>>(
        QS, 0, 0, KS, 0, 0, 0, 0, 0, QKb, 0, 0,
        T, T, D, D, D, T, 0,
        (long long)T * D, (long long)T * D, (long long)T * T, 4);

    sim_attn_kernel<<<dim3(T, Bb), 128>>>(QKb, qa_rel, aq_rel, EQb, EKb, Gb, PS, Wb);

    // pk[b] = P[b] @ k_sim[b] (grid 8x2x4)
    gemm_sp<0,0><<<dim3(8, 2, 4), 256, GEMM_SMEM_NT>>>(
        PS, 0, 0, KS, 0, 0, 0, 0, 0, PKb, 0, 0,
        T, D, T, T, D, D, 0,
        (long long)T * T, (long long)T * D, (long long)T * D, 4);

    final_kernel<<<Bb, 512>>>(PKb, Wb, conceptE, clsw, clsb, out);
}

// round 9
// speedup vs baseline: 1.1787x; 1.1786x over previous
#include <cuda_runtime.h>
#include <cuda_bf16.h>
#include <math.h>

// Problem constants
#define Bb   4
#define T    128
#define D    512
#define Hh   4
#define DK   128
#define NL   4
#define DFF  2048
#define NC   5

#define M2   1024            // merged towers: 2*Bb*T rows
#define ND   (M2*D)          // 524288

// ---------------- scratch ----------------------------------------------------
#define OFF_X   0
#define OFF_Q   (1*ND)
#define OFF_K   (2*ND)
#define OFF_V   (3*ND)
#define OFF_T0  (4*ND)
#define OFF_T1  (5*ND)
#define OFF_H   (6*ND)
#define OFF_FFN (7*ND)              // M2*DFF = 4*ND
#define OFF_QK  (11*ND)
#define OFF_P   (OFF_QK + 65536)
#define OFF_EQ  (OFF_P + 65536)
#define OFF_EK  (OFF_EQ + 2560)
#define OFF_G   (OFF_EK + 2560)
#define OFF_W   (OFF_G + 32)
#define OFF_PK  (OFF_W + 2560)      // 4*T*D = 262144
#define SCRATCH_TOTAL (OFF_PK + 262144)

__device__ float g_scratch[SCRATCH_TOTAL];

__device__ __forceinline__ float gelu_f(float x) {
    return 0.5f * x * (1.0f + erff(x * 0.7071067811865475f));
}

// ---------------- tf32 / mma / cp.async helpers ------------------------------
__device__ __forceinline__ unsigned f2tf32(float x) {
    unsigned r;
    asm("cvt.rna.tf32.f32 %0, %1;" : "=r"(r) : "f"(x));
    return r;
}
__device__ __forceinline__ void split2(float x, unsigned& hi, unsigned& lo) {
    hi = f2tf32(x);
    lo = f2tf32(x - __uint_as_float(hi));
}
__device__ __forceinline__ void mma_tf32(float* c, const unsigned* a, const unsigned* b) {
    asm volatile(
        "mma.sync.aligned.m16n8k8.row.col.f32.tf32.tf32.f32 "
        "{%0,%1,%2,%3},{%4,%5,%6,%7},{%8,%9},{%0,%1,%2,%3};"
        : "+f"(c[0]), "+f"(c[1]), "+f"(c[2]), "+f"(c[3])
        : "r"(a[0]), "r"(a[1]), "r"(a[2]), "r"(a[3]), "r"(b[0]), "r"(b[1]));
}
// 3xTF32: (ah+al)*(bh+bl) ~= ah*bh + ah*bl + al*bh
__device__ __forceinline__ void mma3(float* c, const unsigned* ah, const unsigned* al,
                                     const unsigned* bh, const unsigned* bl) {
    mma_tf32(c, ah, bh);
    mma_tf32(c, ah, bl);
    mma_tf32(c, al, bh);
}
__device__ __forceinline__ void cp16(void* s, const void* g) {
    unsigned sa = (unsigned)__cvta_generic_to_shared(s);
    asm volatile("cp.async.cg.shared.global [%0], [%1], 16;\n" :: "r"(sa), "l"(g) : "memory");
}
#define CP_COMMIT() asm volatile("cp.async.commit_group;\n" ::: "memory")
#define CP_WAIT(n)  asm volatile("cp.async.wait_group %0;\n" :: "n"(n) : "memory")

// ---------------- pipelined 3xTF32 GEMM, 64x64 tile, 3-stage cp.async --------
// C = A @ B (+bias)(+gelu). A:[M,K] (lda). B: [K,N](ldb) or TRANSB [N,K](ldb).
// 256 threads = 8 warps; warp grid 2(m) x 4(n); warp tile 32x16.
// NOTE: __launch_bounds__(256, 2) — smem ~29KB, regs<=96 -> 2 CTAs/SM.
#define PADK 20
#define PADN 72

template<int TRANSB>
__global__ __launch_bounds__(256, 2)
void gemm_tf32(const float* __restrict__ A0, const float* __restrict__ A1, const float* __restrict__ A2,
               const float* __restrict__ W0, const float* __restrict__ W1, const float* __restrict__ W2,
               const float* __restrict__ bias0, const float* __restrict__ bias1, const float* __restrict__ bias2,
               float* __restrict__ C0, float* __restrict__ C1, float* __restrict__ C2,
               int M, int N, int K, int lda, int ldb, int ldc,
               int act, int nH,
               long long sA, long long hA, long long sB, long long hB,
               long long sC, long long hC, int zPerSet) {
    int z = blockIdx.z;
    int set = z / zPerSet;
    int zz = z % zPerSet;
    int bb = zz / nH, hh = zz % nH;

    const float* A  = (set == 0) ? A0 : (set == 1 ? A1 : A2);
    const float* Bm = (set == 0) ? W0 : (set == 1 ? W1 : W2);
    const float* bias = (set == 0) ? bias0 : (set == 1 ? bias1 : bias2);
    float* C = (set == 0) ? C0 : (set == 1 ? C1 : C2);
    A  += bb * sA + hh * hA;
    Bm += bb * sB + hh * hB;
    C  += bb * sC + hh * hC;

    __shared__ float As[3][64][PADK];
    constexpr int BR = TRANSB ? 64 : 16;
    constexpr int BC = TRANSB ? PADK : PADN;
    __shared__ float Bs[3][BR][BC];

    int tid = threadIdx.x;
    int lane = tid & 31, wid = tid >> 5;
    int wm = wid & 1, wn = wid >> 1;
    int l3 = lane & 3, l2 = lane >> 2;

    int bm = blockIdx.y * 64;
    int bn = blockIdx.x * 64;

    // load indices
    int ar = tid >> 2, ak = (tid & 3) * 4;        // A: 64x16
    int tbr = tid >> 2, tbk = (tid & 3) * 4;      // B trans: 64x16
    int nbr = tid >> 4, nbc = (tid & 15) * 4;     // B non-trans: 16x64

    float acc[2][2][4] = {};

    int nk = K / 16;

    // prologue: stages 0,1
    #pragma unroll
    for (int p = 0; p < 2; p++) {
        int k0 = p * 16;
        cp16(&As[p][ar][ak], A + (size_t)(bm + ar) * lda + k0 + ak);
        if (TRANSB) cp16(&Bs[p][tbr][tbk], Bm + (size_t)(bn + tbr) * ldb + k0 + tbk);
        else        cp16(&Bs[p][nbr][nbc], Bm + (size_t)(k0 + nbr) * ldb + bn + nbc);
        CP_COMMIT();
    }

    for (int kt = 0; kt < nk; kt++) {
        CP_WAIT(1);
        __syncthreads();
        int st = kt % 3;
        if (kt + 2 < nk) {
            int ns = (kt + 2) % 3;
            int k0 = (kt + 2) * 16;
            cp16(&As[ns][ar][ak], A + (size_t)(bm + ar) * lda + k0 + ak);
            if (TRANSB) cp16(&Bs[ns][tbr][tbk], Bm + (size_t)(bn + tbr) * ldb + k0 + tbk);
            else        cp16(&Bs[ns][nbr][nbc], Bm + (size_t)(k0 + nbr) * ldb + bn + nbc);
        }
        CP_COMMIT();

        #pragma unroll
        for (int ks = 0; ks < 16; ks += 8) {
            unsigned ah[2][4], al[2][4], bh[2][2], bl[2][2];
            #pragma unroll
            for (int i = 0; i < 2; i++) {
                int m0 = wm * 32 + i * 16;
                split2(As[st][m0 + l2][ks + l3],         ah[i][0], al[i][0]);
                split2(As[st][m0 + l2 + 8][ks + l3],     ah[i][1], al[i][1]);
                split2(As[st][m0 + l2][ks + l3 + 4],     ah[i][2], al[i][2]);
                split2(As[st][m0 + l2 + 8][ks + l3 + 4], ah[i][3], al[i][3]);
            }
            #pragma unroll
            for (int j = 0; j < 2; j++) {
                int n0 = wn * 16 + j * 8;
                if (TRANSB) {
                    split2(Bs[st][n0 + l2][ks + l3],     bh[j][0], bl[j][0]);
                    split2(Bs[st][n0 + l2][ks + l3 + 4], bh[j][1], bl[j][1]);
                } else {
                    split2(Bs[st][ks + l3][n0 + l2],     bh[j][0], bl[j][0]);
                    split2(Bs[st][ks + l3 + 4][n0 + l2], bh[j][1], bl[j][1]);
                }
            }
            #pragma unroll
            for (int i = 0; i < 2; i++)
                #pragma unroll
                for (int j = 0; j < 2; j++)
                    mma3(acc[i][j], ah[i], al[i], bh[j], bl[j]);
        }
    }

    // epilogue
    #pragma unroll
    for (int i = 0; i < 2; i++) {
        #pragma unroll
        for (int j = 0; j < 2; j++) {
            int rg = bm + wm * 32 + i * 16 + l2;
            int cg = bn + wn * 16 + j * 8 + 2 * l3;
            float bv0 = bias ? bias[cg] : 0.0f;
            float bv1 = bias ? bias[cg + 1] : 0.0f;
            float v0 = acc[i][j][0] + bv0, v1 = acc[i][j][1] + bv1;
            float v2 = acc[i][j][2] + bv0, v3 = acc[i][j][3] + bv1;
            if (act) { v0 = gelu_f(v0); v1 = gelu_f(v1); v2 = gelu_f(v2); v3 = gelu_f(v3); }
            *(float2*)(C + (size_t)rg * ldc + cg) = make_float2(v0, v1);
            *(float2*)(C + (size_t)(rg + 8) * ldc + cg) = make_float2(v2, v3);
        }
    }
}

// ---------------- fused attention: S=QK^T, softmax, O=PV ---------------------
// grid: (2 row-halves, 32 (b',h)); 256 threads = 8 warps, warp grid 2(m) x 4(n).
#define APAD 132
__global__ __launch_bounds__(256)
void fused_attn(const float* __restrict__ Q, const float* __restrict__ K,
                const float* __restrict__ V, float* __restrict__ O) {
    extern __shared__ float dyn[];
    float* Pbuf = dyn;                  // [64][APAD]
    float* Kbuf = dyn + 64 * APAD;      // [128][APAD]
    __shared__ float redM[64][4];
    __shared__ float redS[64][4];

    int bz = blockIdx.y;
    int bb = bz >> 2, h = bz & 3;
    int qbase = blockIdx.x * 64;

    int tid = threadIdx.x;
    int lane = tid & 31, wid = tid >> 5;
    int wm = wid & 1, wn = wid >> 1;
    int l3 = lane & 3, l2 = lane >> 2;

    const float* Qg = Q + ((size_t)bb * T + qbase) * D + h * DK;
    const float* Kg = K + ((size_t)bb * T) * D + h * DK;
    const float* Vg = V + ((size_t)bb * T) * D + h * DK;

    #pragma unroll
    for (int t = 0; t < 8; t++) {
        int idx = tid + t * 256;
        int r = idx >> 5, c = (idx & 31) * 4;
        cp16(&Pbuf[r * APAD + c], Qg + (size_t)r * D + c);
    }
    CP_COMMIT();
    #pragma unroll
    for (int t = 0; t < 16; t++) {
        int idx = tid + t * 256;
        int r = idx >> 5, c = (idx & 31) * 4;
        cp16(&Kbuf[r * APAD + c], Kg + (size_t)r * D + c);
    }
    CP_COMMIT();
    CP_WAIT(0);
    __syncthreads();

    // phase 1: S = Q @ K^T
    float acc[2][4][4] = {};
    #pragma unroll 4
    for (int ks = 0; ks < DK; ks += 8) {
        unsigned ah[2][4], al[2][4], bh[4][2], bl[4][2];
        #pragma unroll
        for (int i = 0; i < 2; i++) {
            int m0 = wm * 32 + i * 16;
            split2(Pbuf[(m0 + l2) * APAD + ks + l3],         ah[i][0], al[i][0]);
            split2(Pbuf[(m0 + l2 + 8) * APAD + ks + l3],     ah[i][1], al[i][1]);
            split2(Pbuf[(m0 + l2) * APAD + ks + l3 + 4],     ah[i][2], al[i][2]);
            split2(Pbuf[(m0 + l2 + 8) * APAD + ks + l3 + 4], ah[i][3], al[i][3]);
        }
        #pragma unroll
        for (int j = 0; j < 4; j++) {
            int n0 = wn * 32 + j * 8;
            split2(Kbuf[(n0 + l2) * APAD + ks + l3],     bh[j][0], bl[j][0]);
            split2(Kbuf[(n0 + l2) * APAD + ks + l3 + 4], bh[j][1], bl[j][1]);
        }
        #pragma unroll
        for (int i = 0; i < 2; i++)
            #pragma unroll
            for (int j = 0; j < 4; j++)
                mma3(acc[i][j], ah[i], al[i], bh[j], bl[j]);
    }
    __syncthreads();   // Q/K reads done

    // V load overlaps softmax
    #pragma unroll
    for (int t = 0; t < 16; t++) {
        int idx = tid + t * 256;
        int r = idx >> 5, c = (idx & 31) * 4;
        cp16(&Kbuf[r * APAD + c], Vg + (size_t)r * D + c);
    }
    CP_COMMIT();

    const float sc = 0.08838834764831845f;
    #pragma unroll
    for (int i = 0; i < 2; i++)
        #pragma unroll
        for (int j = 0; j < 4; j++)
            #pragma unroll
            for (int q = 0; q < 4; q++) acc[i][j][q] *= sc;

    #pragma unroll
    for (int i = 0; i < 2; i++)
        #pragma unroll
        for (int hf = 0; hf < 2; hf++) {
            int row = wm * 32 + i * 16 + l2 + hf * 8;
            float m = -1e30f;
            #pragma unroll
            for (int j = 0; j < 4; j++) m = fmaxf(m, fmaxf(acc[i][j][2 * hf], acc[i][j][2 * hf + 1]));
            m = fmaxf(m, __shfl_xor_sync(0xffffffff, m, 1));
            m = fmaxf(m, __shfl_xor_sync(0xffffffff, m, 2));
            if (l3 == 0) redM[row][wn] = m;
        }
    __syncthreads();
    #pragma unroll
    for (int i = 0; i < 2; i++)
        #pragma unroll
        for (int hf = 0; hf < 2; hf++) {
            int row = wm * 32 + i * 16 + l2 + hf * 8;
            float m = fmaxf(fmaxf(redM[row][0], redM[row][1]), fmaxf(redM[row][2], redM[row][3]));
            float s = 0.0f;
            #pragma unroll
            for (int j = 0; j < 4; j++) {
                acc[i][j][2 * hf]     = expf(acc[i][j][2 * hf] - m);
                acc[i][j][2 * hf + 1] = expf(acc[i][j][2 * hf + 1] - m);
                s += acc[i][j][2 * hf] + acc[i][j][2 * hf + 1];
            }
            s += __shfl_xor_sync(0xffffffff, s, 1);
            s += __shfl_xor_sync(0xffffffff, s, 2);
            if (l3 == 0) redS[row][wn] = s;
        }
    __syncthreads();
    // normalize and write P into Pbuf
    #pragma unroll
    for (int i = 0; i < 2; i++)
        #pragma unroll
        for (int hf = 0; hf < 2; hf++) {
            int row = wm * 32 + i * 16 + l2 + hf * 8;
            float inv = 1.0f / (redS[row][0] + redS[row][1] + redS[row][2] + redS[row][3]);
            #pragma unroll
            for (int j = 0; j < 4; j++) {
                int col = wn * 32 + j * 8 + 2 * l3;
                Pbuf[row * APAD + col]     = acc[i][j][2 * hf] * inv;
                Pbuf[row * APAD + col + 1] = acc[i][j][2 * hf + 1] * inv;
            }
        }
    CP_WAIT(0);
    __syncthreads();   // P written, V arrived

    // phase 2: O = P @ V
    float out[2][4][4] = {};
    #pragma unroll 4
    for (int ks = 0; ks < T; ks += 8) {
        unsigned ah[2][4], al[2][4], bh[4][2], bl[4][2];
        #pragma unroll
        for (int i = 0; i < 2; i++) {
            int m0 = wm * 32 + i * 16;
            split2(Pbuf[(m0 + l2) * APAD + ks + l3],         ah[i][0], al[i][0]);
            split2(Pbuf[(m0 + l2 + 8) * APAD + ks + l3],     ah[i][1], al[i][1]);
            split2(Pbuf[(m0 + l2) * APAD + ks + l3 + 4],     ah[i][2], al[i][2]);
            split2(Pbuf[(m0 + l2 + 8) * APAD + ks + l3 + 4], ah[i][3], al[i][3]);
        }
        #pragma unroll
        for (int j = 0; j < 4; j++) {
            int n0 = wn * 32 + j * 8;
            split2(Kbuf[(ks + l3) * APAD + n0 + l2],     bh[j][0], bl[j][0]);
            split2(Kbuf[(ks + l3 + 4) * APAD + n0 + l2], bh[j][1], bl[j][1]);
        }
        #pragma unroll
        for (int i = 0; i < 2; i++)
            #pragma unroll
            for (int j = 0; j < 4; j++)
                mma3(out[i][j], ah[i], al[i], bh[j], bl[j]);
    }

    float* Og = O + ((size_t)bb * T + qbase) * D + h * DK;
    #pragma unroll
    for (int i = 0; i < 2; i++)
        #pragma unroll
        for (int j = 0; j < 4; j++) {
            int r = wm * 32 + i * 16 + l2;
            int c = wn * 32 + j * 8 + 2 * l3;
            *(float2*)(Og + (size_t)r * D + c) = make_float2(out[i][j][0], out[i][j][1]);
            *(float2*)(Og + (size_t)(r + 8) * D + c) = make_float2(out[i][j][2], out[i][j][3]);
        }
}

// ---------------- warp helpers ----------------------------------------------
__device__ __forceinline__ float warp_sum(float v) {
    #pragma unroll
    for (int o = 16; o > 0; o >>= 1) v += __shfl_xor_sync(0xffffffff, v, o);
    return v;
}
__device__ __forceinline__ float warp_max(float v) {
    #pragma unroll
    for (int o = 16; o > 0; o >>= 1) v = fmaxf(v, __shfl_xor_sync(0xffffffff, v, o));
    return v;
}

// ---------------- LayerNorm kernels ------------------------------------------
__global__ void add_pos_ln_kernel(const float* __restrict__ x, const float* __restrict__ pos,
                                  const float* __restrict__ w, const float* __restrict__ b,
                                  float* __restrict__ out) {
    int row = blockIdx.x, tid = threadIdx.x;
    int lane = tid & 31, wd = tid >> 5;
    __shared__ float p1[4], p2[4];

    float4 xv = ((const float4*)(x + (size_t)row * D))[tid];
    float4 pv = ((const float4*)(pos + (size_t)(row % T) * D))[tid];
    float4 v = make_float4(xv.x + pv.x, xv.y + pv.y, xv.z + pv.z, xv.w + pv.w);

    float s = warp_sum(v.x + v.y + v.z + v.w);
    if (lane == 0) p1[wd] = s;
    __syncthreads();
    float mean = (p1[0] + p1[1] + p1[2] + p1[3]) * (1.0f / D);
    float4 d = make_float4(v.x - mean, v.y - mean, v.z - mean, v.w - mean);
    float q = warp_sum(d.x * d.x + d.y * d.y + d.z * d.z + d.w * d.w);
    if (lane == 0) p2[wd] = q;
    __syncthreads();
    float inv = rsqrtf((p2[0] + p2[1] + p2[2] + p2[3]) * (1.0f / D) + 1e-12f);

    float4 wv = ((const float4*)w)[tid];
    float4 bv = ((const float4*)b)[tid];
    ((float4*)(out + (size_t)row * D))[tid] =
        make_float4(wv.x * d.x * inv + bv.x, wv.y * d.y * inv + bv.y,
                    wv.z * d.z * inv + bv.z, wv.w * d.w * inv + bv.w);
}

__global__ void residual_ln_kernel(float* __restrict__ x, const float* __restrict__ y,
                                   float* __restrict__ out,
                                   const float* __restrict__ w, const float* __restrict__ b) {
    int row = blockIdx.x, tid = threadIdx.x;
    int lane = tid & 31, wd = tid >> 5;
    __shared__ float p1[4], p2[4];

    float4 xv = ((const float4*)(x + (size_t)row * D))[tid];
    float4 yv = ((const float4*)(y + (size_t)row * D))[tid];
    float4 v = make_float4(xv.x + yv.x, xv.y + yv.y, xv.z + yv.z, xv.w + yv.w);
    ((float4*)(x + (size_t)row * D))[tid] = v;

    float s = warp_sum(v.x + v.y + v.z + v.w);
    if (lane == 0) p1[wd] = s;
    __syncthreads();
    float mean = (p1[0] + p1[1] + p1[2] + p1[3]) * (1.0f / D);
    float4 d = make_float4(v.x - mean, v.y - mean, v.z - mean, v.w - mean);
    float q = warp_sum(d.x * d.x + d.y * d.y + d.z * d.z + d.w * d.w);
    if (lane == 0) p2[wd] = q;
    __syncthreads();
    float inv = rsqrtf((p2[0] + p2[1] + p2[2] + p2[3]) * (1.0f / D) + 1e-12f);

    float4 wv = ((const float4*)w)[tid];
    float4 bv = ((const float4*)b)[tid];
    ((float4*)(out + (size_t)row * D))[tid] =
        make_float4(wv.x * d.x * inv + bv.x, wv.y * d.y * inv + bv.y,
                    wv.z * d.z * inv + bv.z, wv.w * d.w * inv + bv.w);
}

// ---------------- sim head helpers ------------------------------------------
__global__ void edot_kernel(const float* __restrict__ X, const float* __restrict__ E,
                            float* __restrict__ out) {
    int row = blockIdx.x;
    int tid = threadIdx.x;
    __shared__ float red[NC * 256];
    float acc[NC] = {};
    for (int d = tid; d < D; d += 256) {
        float x = X[(size_t)row * D + d];
        #pragma unroll
        for (int c = 0; c < NC; c++) acc[c] += x * E[(size_t)c * D + d];
    }
    #pragma unroll
    for (int c = 0; c < NC; c++) red[c * 256 + tid] = acc[c];
    __syncthreads();
    for (int off = 128; off > 0; off >>= 1) {
        if (tid < off) {
            #pragma unroll
            for (int c = 0; c < NC; c++) red[c * 256 + tid] += red[c * 256 + tid + off];
        }
        __syncthreads();
    }
    if (tid < NC) out[(size_t)row * NC + tid] = red[tid * 256];
}

__global__ void gram_kernel(const float* __restrict__ E, float* __restrict__ G) {
    int i = threadIdx.x;
    if (i < NC * NC) {
        int c = i / NC, c2 = i % NC;
        float s = 0.0f;
        for (int d = 0; d < D; d++) s += E[(size_t)c * D + d] * E[(size_t)c2 * D + d];
        G[i] = s;
    }
}

__global__ void sim_attn_kernel(const float* __restrict__ QK, const float* __restrict__ qa,
                                const float* __restrict__ aq, const float* __restrict__ Eq,
                                const float* __restrict__ Ek, const float* __restrict__ G,
                                float* __restrict__ P, float* __restrict__ Wout) {
    int t = blockIdx.x, b = blockIdx.y;
    int s = threadIdx.x;                 // 128 threads
    int lane = s & 31, wd = s >> 5;
    __shared__ float g[NC * NC];
    __shared__ float part[4];
    __shared__ float pv[T];
    if (s < NC * NC) g[s] = G[s];
    __syncthreads();

    float f1[NC], f2[NC];
    const float* r1 = qa + (((size_t)b * T + t) * T + s) * NC;
    const float* r2 = aq + (((size_t)b * T + s) * T + t) * NC;
    #pragma unroll
    for (int c = 0; c < NC; c++) { f1[c] = r1[c]; f2[c] = r2[c]; }

    float sc = QK[((size_t)b * T + t) * T + s];
    const float* eq = Eq + ((size_t)b * T + t) * NC;
    const float* ek = Ek + ((size_t)b * T + s) * NC;
    #pragma unroll
    for (int c = 0; c < NC; c++) sc += f1[c] * ek[c] + f2[c] * eq[c];
    #pragma unroll
    for (int c = 0; c < NC; c++)
        #pragma unroll
        for (int c2 = 0; c2 < NC; c2++)
            sc += f1[c] * g[c * NC + c2] * f2[c2];

    float m = warp_max(sc);
    if (lane == 0) part[wd] = m;
    __syncthreads();
    float m1 = fmaxf(fmaxf(part[0], part[1]), fmaxf(part[2], part[3]));
    float e1 = expf(sc - m1);
    float ssum = warp_sum(e1);
    if (lane == 0) part[wd] = ssum;
    __syncthreads();
    float p = e1 / (part[0] + part[1] + part[2] + part[3]);

    float l = 1000.0f * p;
    m = warp_max(l);
    __syncthreads();
    if (lane == 0) part[wd] = m;
    __syncthreads();
    float m2 = fmaxf(fmaxf(part[0], part[1]), fmaxf(part[2], part[3]));
    float e2 = expf(l - m2);
    ssum = warp_sum(e2);
    __syncthreads();
    if (lane == 0) part[wd] = ssum;
    __syncthreads();
    float p2 = e2 / (part[0] + part[1] + part[2] + part[3]);
    p2 = fminf(fmaxf(p2, 0.0f), 1.0f);

    P[((size_t)b * T + t) * T + s] = p2;
    pv[s] = p2;
    __syncthreads();

    #pragma unroll
    for (int c = 0; c < NC; c++) {
        float v = warp_sum(pv[s] * f2[c]);
        __syncthreads();
        if (lane == 0) part[wd] = v;
        __syncthreads();
        if (s == 0) Wout[((size_t)b * T + t) * NC + c] = part[0] + part[1] + part[2] + part[3];
    }
}

__global__ void final_kernel(const float* __restrict__ pk, const float* __restrict__ Wm,
                             const float* __restrict__ E, const float* __restrict__ clsw,
                             const float* __restrict__ clsb, float* __restrict__ out) {
    int b = blockIdx.x;
    int d = threadIdx.x;
    __shared__ float wm[NC];
    __shared__ float red[512];

    if (d < NC) {
        float s = 0.0f;
        for (int t = 0; t < T; t++) s += Wm[((size_t)b * T + t) * NC + d];
        wm[d] = s * (1.0f / T);
    }
    __syncthreads();

    float s = 0.0f;
    for (int t = 0; t < T; t++) s += pk[((size_t)b * T + t) * D + d];
    s *= (1.0f / T);
    #pragma unroll
    for (int c = 0; c < NC; c++) s += wm[c] * E[(size_t)c * D + d];

    for (int j = 0; j < 3; j++) {
        red[d] = s * clsw[(size_t)d * 3 + j];
        __syncthreads();
        for (int off = 256; off > 0; off >>= 1) { if (d < off) red[d] += red[d + off]; __syncthreads(); }
        if (d == 0) out[b * 3 + j] = red[0] + clsb[j];
        __syncthreads();
    }
}

// ---------------- host orchestration ----------------------------------------
static inline void g_launch(int transB,
                            const float* A0, const float* A1, const float* A2,
                            const float* W0, const float* W1, const float* W2,
                            const float* b0, const float* b1, const float* b2,
                            float* C0, float* C1, float* C2,
                            int M, int N, int K, int lda, int ldb, int ldc,
                            int act, int nH,
                            long long sA, long long hA, long long sB, long long hB,
                            long long sC, long long hC, int zPerSet, int nz) {
    dim3 grid(N / 64, M / 64, nz);
    if (transB)
        gemm_tf32<1><<<grid, 256>>>(A0, A1, A2, W0, W1, W2, b0, b1, b2, C0, C1, C2,
                                    M, N, K, lda, ldb, ldc, act, nH,
                                    sA, hA, sB, hB, sC, hC, zPerSet);
    else
        gemm_tf32<0><<<grid, 256>>>(A0, A1, A2, W0, W1, W2, b0, b1, b2, C0, C1, C2,
                                    M, N, K, lda, ldb, ldc, act, nH,
                                    sA, hA, sB, hB, sC, hC, zPerSet);
}

extern "C" void kernel_launch(void* const* d_in, const int* in_sizes, int n_in,
                              void* d_out, int out_size) {
    const float* q_emb   = (const float*)d_in[0];
    const float* a_emb   = (const float*)d_in[1];
    const float* qa_rel  = (const float*)d_in[2];
    const float* aq_rel  = (const float*)d_in[3];
    const float* conceptE= (const float*)d_in[4];
    const float* pos_emb = (const float*)d_in[5];
    const float* pe_w    = (const float*)d_in[6];
    const float* pe_b    = (const float*)d_in[7];
    const float* Wq      = (const float*)d_in[8];
    const float* bq      = (const float*)d_in[9];
    const float* Wk      = (const float*)d_in[10];
    const float* bk      = (const float*)d_in[11];
    const float* Wv      = (const float*)d_in[12];
    const float* bv      = (const float*)d_in[13];
    const float* Wo      = (const float*)d_in[14];
    const float* bo      = (const float*)d_in[15];
    const float* ff1w    = (const float*)d_in[16];
    const float* ff1b    = (const float*)d_in[17];
    const float* ff2w    = (const float*)d_in[18];
    const float* ff2b    = (const float*)d_in[19];
    const float* lninw   = (const float*)d_in[20];
    const float* lninb   = (const float*)d_in[21];
    const float* lnoutw  = (const float*)d_in[22];
    const float* lnoutb  = (const float*)d_in[23];
    const float* simWq   = (const float*)d_in[24];
    const float* simbq   = (const float*)d_in[25];
    const float* simWk   = (const float*)d_in[26];
    const float* simbk   = (const float*)d_in[27];
    const float* clsw    = (const float*)d_in[28];
    const float* clsb    = (const float*)d_in[29];
    float* out = (float*)d_out;

    float* base = nullptr;
    cudaGetSymbolAddress((void**)&base, g_scratch);

    float* X   = base + OFF_X;
    float* Qb  = base + OFF_Q;
    float* Kb  = base + OFF_K;
    float* Vb  = base + OFF_V;
    float* T0  = base + OFF_T0;
    float* T1b = base + OFF_T1;
    float* Hb  = base + OFF_H;
    float* FFN = base + OFF_FFN;
    float* QKb = base + OFF_QK;
    float* Pb  = base + OFF_P;
    float* EQb = base + OFF_EQ;
    float* EKb = base + OFF_EK;
    float* Gb  = base + OFF_G;
    float* Wb  = base + OFF_W;
    float* PKb = base + OFF_PK;

    static const int ATTN_SMEM = (64 + 128) * APAD * 4;
    cudaFuncSetAttribute(fused_attn, cudaFuncAttributeMaxDynamicSharedMemorySize, ATTN_SMEM);

    add_pos_ln_kernel<<<M2 / 2, 128>>>(q_emb, pos_emb, pe_w, pe_b, X);
    add_pos_ln_kernel<<<M2 / 2, 128>>>(a_emb, pos_emb, pe_w, pe_b, X + (size_t)(M2 / 2) * D);

    for (int i = 0; i < NL; i++) {
        const float* wq = Wq + (size_t)i * D * D;
        const float* wk = Wk + (size_t)i * D * D;
        const float* wv = Wv + (size_t)i * D * D;
        const float* wo = Wo + (size_t)i * D * D;

        // fused QKV: 3 sets, one launch (grid 8x16x3 = 384)
        g_launch(0, X, X, X, wq, wk, wv,
                 bq + (size_t)i * D, bk + (size_t)i * D, bv + (size_t)i * D,
                 Qb, Kb, Vb,
                 M2, D, D, D, D, D, 0, 1, 0, 0, 0, 0, 0, 0, 1, 3);

        // fused attention: grid (2, 32)
        fused_attn<<<dim3(2, 32), 256, ATTN_SMEM>>>(Qb, Kb, Vb, T0);

        // output projection (grid 128)
        g_launch(0, T0, 0, 0, wo, 0, 0, bo + (size_t)i * D, 0, 0, T1b, 0, 0,
                 M2, D, D, D, D, D, 0, 1, 0, 0, 0, 0, 0, 0, 1, 1);

        residual_ln_kernel<<<M2, 128>>>(X, T1b, Hb, lninw + (size_t)i * D, lninb + (size_t)i * D);

        g_launch(0, Hb, 0, 0, ff1w + (size_t)i * D * DFF, 0, 0, ff1b + (size_t)i * DFF, 0, 0, FFN, 0, 0,
                 M2, DFF, D, D, DFF, DFF, 1, 1, 0, 0, 0, 0, 0, 0, 1, 1);
        g_launch(0, FFN, 0, 0, ff2w + (size_t)i * DFF * D, 0, 0, ff2b + (size_t)i * D, 0, 0, T1b, 0, 0,
                 M2, D, DFF, DFF, D, D, 0, 1, 0, 0, 0, 0, 0, 0, 1, 1);

        residual_ln_kernel<<<M2, 128>>>(X, T1b, X, lnoutw + (size_t)i * D, lnoutb + (size_t)i * D);
    }

    // --- sim head ---
    g_launch(0, X, X + (size_t)(M2 / 2) * D, 0, simWq, simWk, 0, simbq, simbk, 0, Qb, Kb, 0,
             M2 / 2, D, D, D, D, D, 0, 1, 0, 0, 0, 0, 0, 0, 1, 2);

    edot_kernel<<<M2 / 2, 256>>>(Qb, conceptE, EQb);
    edot_kernel<<<M2 / 2, 256>>>(Kb, conceptE, EKb);
    gram_kernel<<<1, 32>>>(conceptE, Gb);

    // QK[b] = q_sim[b] @ k_sim[b]^T
    g_launch(1, Qb, 0, 0, Kb, 0, 0, 0, 0, 0, QKb, 0, 0,
             T, T, D, D, D, T, 0, 1,
             (long long)T * D, 0, (long long)T * D, 0, (long long)T * T, 0, 4, 4);

    sim_attn_kernel<<<dim3(T, Bb), 128>>>(QKb, qa_rel, aq_rel, EQb, EKb, Gb, Pb, Wb);

    // pk[b] = P[b] @ k_sim[b]
    g_launch(0, Pb, 0, 0, Kb, 0, 0, 0, 0, 0, PKb, 0, 0,
             T, D, T, T, D, D, 0, 1,
             (long long)T * T, 0, (long long)T * D, 0, (long long)T * D, 0, 4, 4);

    final_kernel<<<Bb, 512>>>(PKb, Wb, conceptE, clsw, clsb, out);
}

// round 10
// speedup vs baseline: 1.2479x; 1.0587x over previous
#include <cuda_runtime.h>
#include <cuda_bf16.h>
#include <math.h>

// Problem constants
#define Bb   4
#define T    128
#define D    512
#define Hh   4
#define DK   128
#define NL   4
#define DFF  2048
#define NC   5

#define M2   1024            // merged towers: 2*Bb*T rows
#define ND   (M2*D)          // 524288

// ---------------- scratch ----------------------------------------------------
#define OFF_X   0
#define OFF_Q   (1*ND)
#define OFF_K   (2*ND)
#define OFF_V   (3*ND)
#define OFF_T0  (4*ND)
#define OFF_T1  (5*ND)
#define OFF_H   (6*ND)
#define OFF_FFN (7*ND)              // M2*DFF = 4*ND
#define OFF_QK  (11*ND)
#define OFF_P   (OFF_QK + 65536)
#define OFF_EQ  (OFF_P + 65536)
#define OFF_EK  (OFF_EQ + 2560)
#define OFF_G   (OFF_EK + 2560)
#define OFF_W   (OFF_G + 32)
#define OFF_PK  (OFF_W + 2560)      // 4*T*D = 262144
#define SCRATCH_TOTAL (OFF_PK + 262144)

__device__ float g_scratch[SCRATCH_TOTAL];

__device__ __forceinline__ float gelu_f(float x) {
    return 0.5f * x * (1.0f + erff(x * 0.7071067811865475f));
}

// ---------------- tf32 / mma / cp.async helpers ------------------------------
__device__ __forceinline__ unsigned f2tf32(float x) {
    unsigned r;
    asm("cvt.rna.tf32.f32 %0, %1;" : "=r"(r) : "f"(x));
    return r;
}
__device__ __forceinline__ void split2(float x, unsigned& hi, unsigned& lo) {
    hi = f2tf32(x);
    lo = f2tf32(x - __uint_as_float(hi));
}
__device__ __forceinline__ void mma_tf32(float* c, const unsigned* a, const unsigned* b) {
    asm volatile(
        "mma.sync.aligned.m16n8k8.row.col.f32.tf32.tf32.f32 "
        "{%0,%1,%2,%3},{%4,%5,%6,%7},{%8,%9},{%0,%1,%2,%3};"
        : "+f"(c[0]), "+f"(c[1]), "+f"(c[2]), "+f"(c[3])
        : "r"(a[0]), "r"(a[1]), "r"(a[2]), "r"(a[3]), "r"(b[0]), "r"(b[1]));
}
__device__ __forceinline__ void cp16(void* s, const void* g) {
    unsigned sa = (unsigned)__cvta_generic_to_shared(s);
    asm volatile("cp.async.cg.shared.global [%0], [%1], 16;\n" :: "r"(sa), "l"(g) : "memory");
}
#define CP_COMMIT() asm volatile("cp.async.commit_group;\n" ::: "memory")
#define CP_WAIT(n)  asm volatile("cp.async.wait_group %0;\n" :: "n"(n) : "memory")

// ---------------- pipelined 3xTF32 GEMM, 64x64 tile, BK=32, 3-stage ----------
// C = A @ B (+bias)(+gelu). A:[M,K] (lda). B: [K,N](ldb) or TRANSB [N,K](ldb).
// 256 threads = 8 warps; warp grid 2(m) x 4(n); warp tile 32x16.
// 3xTF32 issued as 3 passes over all acc tiles (dependency spacing 4).
#define PADK 36
#define PADN 72

template<int TRANSB>
__global__ __launch_bounds__(256, 2)
void gemm_tf32(const float* __restrict__ A0, const float* __restrict__ A1, const float* __restrict__ A2,
               const float* __restrict__ W0, const float* __restrict__ W1, const float* __restrict__ W2,
               const float* __restrict__ bias0, const float* __restrict__ bias1, const float* __restrict__ bias2,
               float* __restrict__ C0, float* __restrict__ C1, float* __restrict__ C2,
               int M, int N, int K, int lda, int ldb, int ldc,
               int act, int nH,
               long long sA, long long hA, long long sB, long long hB,
               long long sC, long long hC, int zPerSet) {
    int z = blockIdx.z;
    int set = z / zPerSet;
    int zz = z % zPerSet;
    int bb = zz / nH, hh = zz % nH;

    const float* A  = (set == 0) ? A0 : (set == 1 ? A1 : A2);
    const float* Bm = (set == 0) ? W0 : (set == 1 ? W1 : W2);
    const float* bias = (set == 0) ? bias0 : (set == 1 ? bias1 : bias2);
    float* C = (set == 0) ? C0 : (set == 1 ? C1 : C2);
    A  += bb * sA + hh * hA;
    Bm += bb * sB + hh * hB;
    C  += bb * sC + hh * hC;

    __shared__ float As[3][64][PADK];
    constexpr int BR = TRANSB ? 64 : 32;
    constexpr int BC = TRANSB ? PADK : PADN;
    __shared__ float Bs[3][BR][BC];

    int tid = threadIdx.x;
    int lane = tid & 31, wid = tid >> 5;
    int wm = wid & 1, wn = wid >> 1;
    int l3 = lane & 3, l2 = lane >> 2;

    int bm = blockIdx.y * 64;
    int bn = blockIdx.x * 64;

    // load indices (BK=32: 2 cp16 per array per thread)
    int ar = tid >> 2, ak = (tid & 3) * 4;        // A rows 0..63, k-quads (two halves)
    int nbr = tid >> 4, nbc = (tid & 15) * 4;     // B nt rows 0..15 (+16), cols

    float acc[2][2][4] = {};

    int nk = K / 32;

    // prologue: stages 0,1
    #pragma unroll
    for (int p = 0; p < 2; p++) {
        int k0 = p * 32;
        cp16(&As[p][ar][ak],      A + (size_t)(bm + ar) * lda + k0 + ak);
        cp16(&As[p][ar][ak + 16], A + (size_t)(bm + ar) * lda + k0 + 16 + ak);
        if (TRANSB) {
            cp16(&Bs[p][ar][ak],      Bm + (size_t)(bn + ar) * ldb + k0 + ak);
            cp16(&Bs[p][ar][ak + 16], Bm + (size_t)(bn + ar) * ldb + k0 + 16 + ak);
        } else {
            cp16(&Bs[p][nbr][nbc],      Bm + (size_t)(k0 + nbr) * ldb + bn + nbc);
            cp16(&Bs[p][nbr + 16][nbc], Bm + (size_t)(k0 + nbr + 16) * ldb + bn + nbc);
        }
        CP_COMMIT();
    }

    for (int kt = 0; kt < nk; kt++) {
        CP_WAIT(1);
        __syncthreads();
        int st = kt % 3;
        if (kt + 2 < nk) {
            int ns = (kt + 2) % 3;
            int k0 = (kt + 2) * 32;
            cp16(&As[ns][ar][ak],      A + (size_t)(bm + ar) * lda + k0 + ak);
            cp16(&As[ns][ar][ak + 16], A + (size_t)(bm + ar) * lda + k0 + 16 + ak);
            if (TRANSB) {
                cp16(&Bs[ns][ar][ak],      Bm + (size_t)(bn + ar) * ldb + k0 + ak);
                cp16(&Bs[ns][ar][ak + 16], Bm + (size_t)(bn + ar) * ldb + k0 + 16 + ak);
            } else {
                cp16(&Bs[ns][nbr][nbc],      Bm + (size_t)(k0 + nbr) * ldb + bn + nbc);
                cp16(&Bs[ns][nbr + 16][nbc], Bm + (size_t)(k0 + nbr + 16) * ldb + bn + nbc);
            }
        }
        CP_COMMIT();

        #pragma unroll
        for (int ks = 0; ks < 32; ks += 8) {
            unsigned ah[2][4], al[2][4], bh[2][2], bl[2][2];
            #pragma unroll
            for (int i = 0; i < 2; i++) {
                int m0 = wm * 32 + i * 16;
                split2(As[st][m0 + l2][ks + l3],         ah[i][0], al[i][0]);
                split2(As[st][m0 + l2 + 8][ks + l3],     ah[i][1], al[i][1]);
                split2(As[st][m0 + l2][ks + l3 + 4],     ah[i][2], al[i][2]);
                split2(As[st][m0 + l2 + 8][ks + l3 + 4], ah[i][3], al[i][3]);
            }
            #pragma unroll
            for (int j = 0; j < 2; j++) {
                int n0 = wn * 16 + j * 8;
                if (TRANSB) {
                    split2(Bs[st][n0 + l2][ks + l3],     bh[j][0], bl[j][0]);
                    split2(Bs[st][n0 + l2][ks + l3 + 4], bh[j][1], bl[j][1]);
                } else {
                    split2(Bs[st][ks + l3][n0 + l2],     bh[j][0], bl[j][0]);
                    split2(Bs[st][ks + l3 + 4][n0 + l2], bh[j][1], bl[j][1]);
                }
            }
            // three passes: dependency spacing 4 on each accumulator
            #pragma unroll
            for (int i = 0; i < 2; i++)
                #pragma unroll
                for (int j = 0; j < 2; j++)
                    mma_tf32(acc[i][j], ah[i], bh[j]);
            #pragma unroll
            for (int i = 0; i < 2; i++)
                #pragma unroll
                for (int j = 0; j < 2; j++)
                    mma_tf32(acc[i][j], ah[i], bl[j]);
            #pragma unroll
            for (int i = 0; i < 2; i++)
                #pragma unroll
                for (int j = 0; j < 2; j++)
                    mma_tf32(acc[i][j], al[i], bh[j]);
        }
    }

    // epilogue
    #pragma unroll
    for (int i = 0; i < 2; i++) {
        #pragma unroll
        for (int j = 0; j < 2; j++) {
            int rg = bm + wm * 32 + i * 16 + l2;
            int cg = bn + wn * 16 + j * 8 + 2 * l3;
            float bv0 = bias ? bias[cg] : 0.0f;
            float bv1 = bias ? bias[cg + 1] : 0.0f;
            float v0 = acc[i][j][0] + bv0, v1 = acc[i][j][1] + bv1;
            float v2 = acc[i][j][2] + bv0, v3 = acc[i][j][3] + bv1;
            if (act) { v0 = gelu_f(v0); v1 = gelu_f(v1); v2 = gelu_f(v2); v3 = gelu_f(v3); }
            *(float2*)(C + (size_t)rg * ldc + cg) = make_float2(v0, v1);
            *(float2*)(C + (size_t)(rg + 8) * ldc + cg) = make_float2(v2, v3);
        }
    }
}

// ---------------- fused attention: S=QK^T, softmax, O=PV ---------------------
// grid: (2 row-halves, 32 (b',h)); 256 threads = 8 warps, warp grid 2(m) x 4(n).
#define APAD 132
__global__ __launch_bounds__(256)
void fused_attn(const float* __restrict__ Q, const float* __restrict__ K,
                const float* __restrict__ V, float* __restrict__ O) {
    extern __shared__ float dyn[];
    float* Pbuf = dyn;                  // [64][APAD]
    float* Kbuf = dyn + 64 * APAD;      // [128][APAD]
    __shared__ float redM[64][4];
    __shared__ float redS[64][4];

    int bz = blockIdx.y;
    int bb = bz >> 2, h = bz & 3;
    int qbase = blockIdx.x * 64;

    int tid = threadIdx.x;
    int lane = tid & 31, wid = tid >> 5;
    int wm = wid & 1, wn = wid >> 1;
    int l3 = lane & 3, l2 = lane >> 2;

    const float* Qg = Q + ((size_t)bb * T + qbase) * D + h * DK;
    const float* Kg = K + ((size_t)bb * T) * D + h * DK;
    const float* Vg = V + ((size_t)bb * T) * D + h * DK;

    #pragma unroll
    for (int t = 0; t < 8; t++) {
        int idx = tid + t * 256;
        int r = idx >> 5, c = (idx & 31) * 4;
        cp16(&Pbuf[r * APAD + c], Qg + (size_t)r * D + c);
    }
    CP_COMMIT();
    #pragma unroll
    for (int t = 0; t < 16; t++) {
        int idx = tid + t * 256;
        int r = idx >> 5, c = (idx & 31) * 4;
        cp16(&Kbuf[r * APAD + c], Kg + (size_t)r * D + c);
    }
    CP_COMMIT();
    CP_WAIT(0);
    __syncthreads();

    // phase 1: S = Q @ K^T
    float acc[2][4][4] = {};
    #pragma unroll 4
    for (int ks = 0; ks < DK; ks += 8) {
        unsigned ah[2][4], al[2][4], bh[4][2], bl[4][2];
        #pragma unroll
        for (int i = 0; i < 2; i++) {
            int m0 = wm * 32 + i * 16;
            split2(Pbuf[(m0 + l2) * APAD + ks + l3],         ah[i][0], al[i][0]);
            split2(Pbuf[(m0 + l2 + 8) * APAD + ks + l3],     ah[i][1], al[i][1]);
            split2(Pbuf[(m0 + l2) * APAD + ks + l3 + 4],     ah[i][2], al[i][2]);
            split2(Pbuf[(m0 + l2 + 8) * APAD + ks + l3 + 4], ah[i][3], al[i][3]);
        }
        #pragma unroll
        for (int j = 0; j < 4; j++) {
            int n0 = wn * 32 + j * 8;
            split2(Kbuf[(n0 + l2) * APAD + ks + l3],     bh[j][0], bl[j][0]);
            split2(Kbuf[(n0 + l2) * APAD + ks + l3 + 4], bh[j][1], bl[j][1]);
        }
        #pragma unroll
        for (int i = 0; i < 2; i++)
            #pragma unroll
            for (int j = 0; j < 4; j++)
                mma_tf32(acc[i][j], ah[i], bh[j]);
        #pragma unroll
        for (int i = 0; i < 2; i++)
            #pragma unroll
            for (int j = 0; j < 4; j++)
                mma_tf32(acc[i][j], ah[i], bl[j]);
        #pragma unroll
        for (int i = 0; i < 2; i++)
            #pragma unroll
            for (int j = 0; j < 4; j++)
                mma_tf32(acc[i][j], al[i], bh[j]);
    }
    __syncthreads();   // Q/K reads done

    // V load overlaps softmax
    #pragma unroll
    for (int t = 0; t < 16; t++) {
        int idx = tid + t * 256;
        int r = idx >> 5, c = (idx & 31) * 4;
        cp16(&Kbuf[r * APAD + c], Vg + (size_t)r * D + c);
    }
    CP_COMMIT();

    const float sc = 0.08838834764831845f;
    #pragma unroll
    for (int i = 0; i < 2; i++)
        #pragma unroll
        for (int j = 0; j < 4; j++)
            #pragma unroll
            for (int q = 0; q < 4; q++) acc[i][j][q] *= sc;

    #pragma unroll
    for (int i = 0; i < 2; i++)
        #pragma unroll
        for (int hf = 0; hf < 2; hf++) {
            int row = wm * 32 + i * 16 + l2 + hf * 8;
            float m = -1e30f;
            #pragma unroll
            for (int j = 0; j < 4; j++) m = fmaxf(m, fmaxf(acc[i][j][2 * hf], acc[i][j][2 * hf + 1]));
            m = fmaxf(m, __shfl_xor_sync(0xffffffff, m, 1));
            m = fmaxf(m, __shfl_xor_sync(0xffffffff, m, 2));
            if (l3 == 0) redM[row][wn] = m;
        }
    __syncthreads();
    #pragma unroll
    for (int i = 0; i < 2; i++)
        #pragma unroll
        for (int hf = 0; hf < 2; hf++) {
            int row = wm * 32 + i * 16 + l2 + hf * 8;
            float m = fmaxf(fmaxf(redM[row][0], redM[row][1]), fmaxf(redM[row][2], redM[row][3]));
            float s = 0.0f;
            #pragma unroll
            for (int j = 0; j < 4; j++) {
                acc[i][j][2 * hf]     = expf(acc[i][j][2 * hf] - m);
                acc[i][j][2 * hf + 1] = expf(acc[i][j][2 * hf + 1] - m);
                s += acc[i][j][2 * hf] + acc[i][j][2 * hf + 1];
            }
            s += __shfl_xor_sync(0xffffffff, s, 1);
            s += __shfl_xor_sync(0xffffffff, s, 2);
            if (l3 == 0) redS[row][wn] = s;
        }
    __syncthreads();
    // normalize and write P into Pbuf
    #pragma unroll
    for (int i = 0; i < 2; i++)
        #pragma unroll
        for (int hf = 0; hf < 2; hf++) {
            int row = wm * 32 + i * 16 + l2 + hf * 8;
            float inv = 1.0f / (redS[row][0] + redS[row][1] + redS[row][2] + redS[row][3]);
            #pragma unroll
            for (int j = 0; j < 4; j++) {
                int col = wn * 32 + j * 8 + 2 * l3;
                Pbuf[row * APAD + col]     = acc[i][j][2 * hf] * inv;
                Pbuf[row * APAD + col + 1] = acc[i][j][2 * hf + 1] * inv;
            }
        }
    CP_WAIT(0);
    __syncthreads();   // P written, V arrived

    // phase 2: O = P @ V
    float out[2][4][4] = {};
    #pragma unroll 4
    for (int ks = 0; ks < T; ks += 8) {
        unsigned ah[2][4], al[2][4], bh[4][2], bl[4][2];
        #pragma unroll
        for (int i = 0; i < 2; i++) {
            int m0 = wm * 32 + i * 16;
            split2(Pbuf[(m0 + l2) * APAD + ks + l3],         ah[i][0], al[i][0]);
            split2(Pbuf[(m0 + l2 + 8) * APAD + ks + l3],     ah[i][1], al[i][1]);
            split2(Pbuf[(m0 + l2) * APAD + ks + l3 + 4],     ah[i][2], al[i][2]);
            split2(Pbuf[(m0 + l2 + 8) * APAD + ks + l3 + 4], ah[i][3], al[i][3]);
        }
        #pragma unroll
        for (int j = 0; j < 4; j++) {
            int n0 = wn * 32 + j * 8;
            split2(Kbuf[(ks + l3) * APAD + n0 + l2],     bh[j][0], bl[j][0]);
            split2(Kbuf[(ks + l3 + 4) * APAD + n0 + l2], bh[j][1], bl[j][1]);
        }
        #pragma unroll
        for (int i = 0; i < 2; i++)
            #pragma unroll
            for (int j = 0; j < 4; j++)
                mma_tf32(out[i][j], ah[i], bh[j]);
        #pragma unroll
        for (int i = 0; i < 2; i++)
            #pragma unroll
            for (int j = 0; j < 4; j++)
                mma_tf32(out[i][j], ah[i], bl[j]);
        #pragma unroll
        for (int i = 0; i < 2; i++)
            #pragma unroll
            for (int j = 0; j < 4; j++)
                mma_tf32(out[i][j], al[i], bh[j]);
    }

    float* Og = O + ((size_t)bb * T + qbase) * D + h * DK;
    #pragma unroll
    for (int i = 0; i < 2; i++)
        #pragma unroll
        for (int j = 0; j < 4; j++) {
            int r = wm * 32 + i * 16 + l2;
            int c = wn * 32 + j * 8 + 2 * l3;
            *(float2*)(Og + (size_t)r * D + c) = make_float2(out[i][j][0], out[i][j][1]);
            *(float2*)(Og + (size_t)(r + 8) * D + c) = make_float2(out[i][j][2], out[i][j][3]);
        }
}

// ---------------- warp helpers ----------------------------------------------
__device__ __forceinline__ float warp_sum(float v) {
    #pragma unroll
    for (int o = 16; o > 0; o >>= 1) v += __shfl_xor_sync(0xffffffff, v, o);
    return v;
}
__device__ __forceinline__ float warp_max(float v) {
    #pragma unroll
    for (int o = 16; o > 0; o >>= 1) v = fmaxf(v, __shfl_xor_sync(0xffffffff, v, o));
    return v;
}

// ---------------- LayerNorm kernels ------------------------------------------
__global__ void add_pos_ln_kernel(const float* __restrict__ x, const float* __restrict__ pos,
                                  const float* __restrict__ w, const float* __restrict__ b,
                                  float* __restrict__ out) {
    int row = blockIdx.x, tid = threadIdx.x;
    int lane = tid & 31, wd = tid >> 5;
    __shared__ float p1[4], p2[4];

    float4 xv = ((const float4*)(x + (size_t)row * D))[tid];
    float4 pv = ((const float4*)(pos + (size_t)(row % T) * D))[tid];
    float4 v = make_float4(xv.x + pv.x, xv.y + pv.y, xv.z + pv.z, xv.w + pv.w);

    float s = warp_sum(v.x + v.y + v.z + v.w);
    if (lane == 0) p1[wd] = s;
    __syncthreads();
    float mean = (p1[0] + p1[1] + p1[2] + p1[3]) * (1.0f / D);
    float4 d = make_float4(v.x - mean, v.y - mean, v.z - mean, v.w - mean);
    float q = warp_sum(d.x * d.x + d.y * d.y + d.z * d.z + d.w * d.w);
    if (lane == 0) p2[wd] = q;
    __syncthreads();
    float inv = rsqrtf((p2[0] + p2[1] + p2[2] + p2[3]) * (1.0f / D) + 1e-12f);

    float4 wv = ((const float4*)w)[tid];
    float4 bv = ((const float4*)b)[tid];
    ((float4*)(out + (size_t)row * D))[tid] =
        make_float4(wv.x * d.x * inv + bv.x, wv.y * d.y * inv + bv.y,
                    wv.z * d.z * inv + bv.z, wv.w * d.w * inv + bv.w);
}

__global__ void residual_ln_kernel(float* __restrict__ x, const float* __restrict__ y,
                                   float* __restrict__ out,
                                   const float* __restrict__ w, const float* __restrict__ b) {
    int row = blockIdx.x, tid = threadIdx.x;
    int lane = tid & 31, wd = tid >> 5;
    __shared__ float p1[4], p2[4];

    float4 xv = ((const float4*)(x + (size_t)row * D))[tid];
    float4 yv = ((const float4*)(y + (size_t)row * D))[tid];
    float4 v = make_float4(xv.x + yv.x, xv.y + yv.y, xv.z + yv.z, xv.w + yv.w);
    ((float4*)(x + (size_t)row * D))[tid] = v;

    float s = warp_sum(v.x + v.y + v.z + v.w);
    if (lane == 0) p1[wd] = s;
    __syncthreads();
    float mean = (p1[0] + p1[1] + p1[2] + p1[3]) * (1.0f / D);
    float4 d = make_float4(v.x - mean, v.y - mean, v.z - mean, v.w - mean);
    float q = warp_sum(d.x * d.x + d.y * d.y + d.z * d.z + d.w * d.w);
    if (lane == 0) p2[wd] = q;
    __syncthreads();
    float inv = rsqrtf((p2[0] + p2[1] + p2[2] + p2[3]) * (1.0f / D) + 1e-12f);

    float4 wv = ((const float4*)w)[tid];
    float4 bv = ((const float4*)b)[tid];
    ((float4*)(out + (size_t)row * D))[tid] =
        make_float4(wv.x * d.x * inv + bv.x, wv.y * d.y * inv + bv.y,
                    wv.z * d.z * inv + bv.z, wv.w * d.w * inv + bv.w);
}

// ---------------- sim head helpers ------------------------------------------
__global__ void edot_kernel(const float* __restrict__ X, const float* __restrict__ E,
                            float* __restrict__ out) {
    int row = blockIdx.x;
    int tid = threadIdx.x;
    __shared__ float red[NC * 256];
    float acc[NC] = {};
    for (int d = tid; d < D; d += 256) {
        float x = X[(size_t)row * D + d];
        #pragma unroll
        for (int c = 0; c < NC; c++) acc[c] += x * E[(size_t)c * D + d];
    }
    #pragma unroll
    for (int c = 0; c < NC; c++) red[c * 256 + tid] = acc[c];
    __syncthreads();
    for (int off = 128; off > 0; off >>= 1) {
        if (tid < off) {
            #pragma unroll
            for (int c = 0; c < NC; c++) red[c * 256 + tid] += red[c * 256 + tid + off];
        }
        __syncthreads();
    }
    if (tid < NC) out[(size_t)row * NC + tid] = red[tid * 256];
}

__global__ void gram_kernel(const float* __restrict__ E, float* __restrict__ G) {
    int i = threadIdx.x;
    if (i < NC * NC) {
        int c = i / NC, c2 = i % NC;
        float s = 0.0f;
        for (int d = 0; d < D; d++) s += E[(size_t)c * D + d] * E[(size_t)c2 * D + d];
        G[i] = s;
    }
}

__global__ void sim_attn_kernel(const float* __restrict__ QK, const float* __restrict__ qa,
                                const float* __restrict__ aq, const float* __restrict__ Eq,
                                const float* __restrict__ Ek, const float* __restrict__ G,
                                float* __restrict__ P, float* __restrict__ Wout) {
    int t = blockIdx.x, b = blockIdx.y;
    int s = threadIdx.x;                 // 128 threads
    int lane = s & 31, wd = s >> 5;
    __shared__ float g[NC * NC];
    __shared__ float part[4];
    __shared__ float pv[T];
    if (s < NC * NC) g[s] = G[s];
    __syncthreads();

    float f1[NC], f2[NC];
    const float* r1 = qa + (((size_t)b * T + t) * T + s) * NC;
    const float* r2 = aq + (((size_t)b * T + s) * T + t) * NC;
    #pragma unroll
    for (int c = 0; c < NC; c++) { f1[c] = r1[c]; f2[c] = r2[c]; }

    float sc = QK[((size_t)b * T + t) * T + s];
    const float* eq = Eq + ((size_t)b * T + t) * NC;
    const float* ek = Ek + ((size_t)b * T + s) * NC;
    #pragma unroll
    for (int c = 0; c < NC; c++) sc += f1[c] * ek[c] + f2[c] * eq[c];
    #pragma unroll
    for (int c = 0; c < NC; c++)
        #pragma unroll
        for (int c2 = 0; c2 < NC; c2++)
            sc += f1[c] * g[c * NC + c2] * f2[c2];

    float m = warp_max(sc);
    if (lane == 0) part[wd] = m;
    __syncthreads();
    float m1 = fmaxf(fmaxf(part[0], part[1]), fmaxf(part[2], part[3]));
    float e1 = expf(sc - m1);
    float ssum = warp_sum(e1);
    if (lane == 0) part[wd] = ssum;
    __syncthreads();
    float p = e1 / (part[0] + part[1] + part[2] + part[3]);

    float l = 1000.0f * p;
    m = warp_max(l);
    __syncthreads();
    if (lane == 0) part[wd] = m;
    __syncthreads();
    float m2 = fmaxf(fmaxf(part[0], part[1]), fmaxf(part[2], part[3]));
    float e2 = expf(l - m2);
    ssum = warp_sum(e2);
    __syncthreads();
    if (lane == 0) part[wd] = ssum;
    __syncthreads();
    float p2 = e2 / (part[0] + part[1] + part[2] + part[3]);
    p2 = fminf(fmaxf(p2, 0.0f), 1.0f);

    P[((size_t)b * T + t) * T + s] = p2;
    pv[s] = p2;
    __syncthreads();

    #pragma unroll
    for (int c = 0; c < NC; c++) {
        float v = warp_sum(pv[s] * f2[c]);
        __syncthreads();
        if (lane == 0) part[wd] = v;
        __syncthreads();
        if (s == 0) Wout[((size_t)b * T + t) * NC + c] = part[0] + part[1] + part[2] + part[3];
    }
}

__global__ void final_kernel(const float* __restrict__ pk, const float* __restrict__ Wm,
                             const float* __restrict__ E, const float* __restrict__ clsw,
                             const float* __restrict__ clsb, float* __restrict__ out) {
    int b = blockIdx.x;
    int d = threadIdx.x;
    __shared__ float wm[NC];
    __shared__ float red[512];

    if (d < NC) {
        float s = 0.0f;
        for (int t = 0; t < T; t++) s += Wm[((size_t)b * T + t) * NC + d];
        wm[d] = s * (1.0f / T);
    }
    __syncthreads();

    float s = 0.0f;
    for (int t = 0; t < T; t++) s += pk[((size_t)b * T + t) * D + d];
    s *= (1.0f / T);
    #pragma unroll
    for (int c = 0; c < NC; c++) s += wm[c] * E[(size_t)c * D + d];

    for (int j = 0; j < 3; j++) {
        red[d] = s * clsw[(size_t)d * 3 + j];
        __syncthreads();
        for (int off = 256; off > 0; off >>= 1) { if (d < off) red[d] += red[d + off]; __syncthreads(); }
        if (d == 0) out[b * 3 + j] = red[0] + clsb[j];
        __syncthreads();
    }
}

// ---------------- host orchestration ----------------------------------------
static inline void g_launch(int transB,
                            const float* A0, const float* A1, const float* A2,
                            const float* W0, const float* W1, const float* W2,
                            const float* b0, const float* b1, const float* b2,
                            float* C0, float* C1, float* C2,
                            int M, int N, int K, int lda, int ldb, int ldc,
                            int act, int nH,
                            long long sA, long long hA, long long sB, long long hB,
                            long long sC, long long hC, int zPerSet, int nz) {
    dim3 grid(N / 64, M / 64, nz);
    if (transB)
        gemm_tf32<1><<<grid, 256>>>(A0, A1, A2, W0, W1, W2, b0, b1, b2, C0, C1, C2,
                                    M, N, K, lda, ldb, ldc, act, nH,
                                    sA, hA, sB, hB, sC, hC, zPerSet);
    else
        gemm_tf32<0><<<grid, 256>>>(A0, A1, A2, W0, W1, W2, b0, b1, b2, C0, C1, C2,
                                    M, N, K, lda, ldb, ldc, act, nH,
                                    sA, hA, sB, hB, sC, hC, zPerSet);
}

extern "C" void kernel_launch(void* const* d_in, const int* in_sizes, int n_in,
                              void* d_out, int out_size) {
    const float* q_emb   = (const float*)d_in[0];
    const float* a_emb   = (const float*)d_in[1];
    const float* qa_rel  = (const float*)d_in[2];
    const float* aq_rel  = (const float*)d_in[3];
    const float* conceptE= (const float*)d_in[4];
    const float* pos_emb = (const float*)d_in[5];
    const float* pe_w    = (const float*)d_in[6];
    const float* pe_b    = (const float*)d_in[7];
    const float* Wq      = (const float*)d_in[8];
    const float* bq      = (const float*)d_in[9];
    const float* Wk      = (const float*)d_in[10];
    const float* bk      = (const float*)d_in[11];
    const float* Wv      = (const float*)d_in[12];
    const float* bv      = (const float*)d_in[13];
    const float* Wo      = (const float*)d_in[14];
    const float* bo      = (const float*)d_in[15];
    const float* ff1w    = (const float*)d_in[16];
    const float* ff1b    = (const float*)d_in[17];
    const float* ff2w    = (const float*)d_in[18];
    const float* ff2b    = (const float*)d_in[19];
    const float* lninw   = (const float*)d_in[20];
    const float* lninb   = (const float*)d_in[21];
    const float* lnoutw  = (const float*)d_in[22];
    const float* lnoutb  = (const float*)d_in[23];
    const float* simWq   = (const float*)d_in[24];
    const float* simbq   = (const float*)d_in[25];
    const float* simWk   = (const float*)d_in[26];
    const float* simbk   = (const float*)d_in[27];
    const float* clsw    = (const float*)d_in[28];
    const float* clsb    = (const float*)d_in[29];
    float* out = (float*)d_out;

    float* base = nullptr;
    cudaGetSymbolAddress((void**)&base, g_scratch);

    float* X   = base + OFF_X;
    float* Qb  = base + OFF_Q;
    float* Kb  = base + OFF_K;
    float* Vb  = base + OFF_V;
    float* T0  = base + OFF_T0;
    float* T1b = base + OFF_T1;
    float* Hb  = base + OFF_H;
    float* FFN = base + OFF_FFN;
    float* QKb = base + OFF_QK;
    float* Pb  = base + OFF_P;
    float* EQb = base + OFF_EQ;
    float* EKb = base + OFF_EK;
    float* Gb  = base + OFF_G;
    float* Wb  = base + OFF_W;
    float* PKb = base + OFF_PK;

    static const int ATTN_SMEM = (64 + 128) * APAD * 4;
    cudaFuncSetAttribute(fused_attn, cudaFuncAttributeMaxDynamicSharedMemorySize, ATTN_SMEM);

    add_pos_ln_kernel<<<M2 / 2, 128>>>(q_emb, pos_emb, pe_w, pe_b, X);
    add_pos_ln_kernel<<<M2 / 2, 128>>>(a_emb, pos_emb, pe_w, pe_b, X + (size_t)(M2 / 2) * D);

    for (int i = 0; i < NL; i++) {
        const float* wq = Wq + (size_t)i * D * D;
        const float* wk = Wk + (size_t)i * D * D;
        const float* wv = Wv + (size_t)i * D * D;
        const float* wo = Wo + (size_t)i * D * D;

        // fused QKV: 3 sets, one launch (grid 8x16x3 = 384)
        g_launch(0, X, X, X, wq, wk, wv,
                 bq + (size_t)i * D, bk + (size_t)i * D, bv + (size_t)i * D,
                 Qb, Kb, Vb,
                 M2, D, D, D, D, D, 0, 1, 0, 0, 0, 0, 0, 0, 1, 3);

        // fused attention: grid (2, 32)
        fused_attn<<<dim3(2, 32), 256, ATTN_SMEM>>>(Qb, Kb, Vb, T0);

        // output projection (grid 128)
        g_launch(0, T0, 0, 0, wo, 0, 0, bo + (size_t)i * D, 0, 0, T1b, 0, 0,
                 M2, D, D, D, D, D, 0, 1, 0, 0, 0, 0, 0, 0, 1, 1);

        residual_ln_kernel<<<M2, 128>>>(X, T1b, Hb, lninw + (size_t)i * D, lninb + (size_t)i * D);

        g_launch(0, Hb, 0, 0, ff1w + (size_t)i * D * DFF, 0, 0, ff1b + (size_t)i * DFF, 0, 0, FFN, 0, 0,
                 M2, DFF, D, D, DFF, DFF, 1, 1, 0, 0, 0, 0, 0, 0, 1, 1);
        g_launch(0, FFN, 0, 0, ff2w + (size_t)i * DFF * D, 0, 0, ff2b + (size_t)i * D, 0, 0, T1b, 0, 0,
                 M2, D, DFF, DFF, D, D, 0, 1, 0, 0, 0, 0, 0, 0, 1, 1);

        residual_ln_kernel<<<M2, 128>>>(X, T1b, X, lnoutw + (size_t)i * D, lnoutb + (size_t)i * D);
    }

    // --- sim head ---
    g_launch(0, X, X + (size_t)(M2 / 2) * D, 0, simWq, simWk, 0, simbq, simbk, 0, Qb, Kb, 0,
             M2 / 2, D, D, D, D, D, 0, 1, 0, 0, 0, 0, 0, 0, 1, 2);

    edot_kernel<<<M2 / 2, 256>>>(Qb, conceptE, EQb);
    edot_kernel<<<M2 / 2, 256>>>(Kb, conceptE, EKb);
    gram_kernel<<<1, 32>>>(conceptE, Gb);

    // QK[b] = q_sim[b] @ k_sim[b]^T
    g_launch(1, Qb, 0, 0, Kb, 0, 0, 0, 0, 0, QKb, 0, 0,
             T, T, D, D, D, T, 0, 1,
             (long long)T * D, 0, (long long)T * D, 0, (long long)T * T, 0, 4, 4);

    sim_attn_kernel<<<dim3(T, Bb), 128>>>(QKb, qa_rel, aq_rel, EQb, EKb, Gb, Pb, Wb);

    // pk[b] = P[b] @ k_sim[b]  (K=128 -> nk=4, fine for BK=32 pipeline)
    g_launch(0, Pb, 0, 0, Kb, 0, 0, 0, 0, 0, PKb, 0, 0,
             T, D, T, T, D, D, 0, 1,
             (long long)T * T, 0, (long long)T * D, 0, (long long)T * D, 0, 4, 4);

    final_kernel<<<Bb, 512>>>(PKb, Wb, conceptE, clsw, clsb, out);
}

// round 11
// speedup vs baseline: 1.3183x; 1.0564x over previous
#include <cuda_runtime.h>
#include <cuda_bf16.h>
#include <math.h>

// Problem constants
#define Bb   4
#define T    128
#define D    512
#define Hh   4
#define DK   128
#define NL   4
#define DFF  2048
#define NC   5

#define M2   1024            // merged towers: 2*Bb*T rows
#define ND   (M2*D)          // 524288

// ---------------- scratch ----------------------------------------------------
#define OFF_X   0
#define OFF_Q   (1*ND)
#define OFF_K   (2*ND)
#define OFF_V   (3*ND)
#define OFF_T0  (4*ND)
#define OFF_T1  (5*ND)
#define OFF_H   (6*ND)
#define OFF_FFN (7*ND)              // M2*DFF = 4*ND
#define OFF_QK  (11*ND)
#define OFF_P   (OFF_QK + 65536)
#define OFF_EQ  (OFF_P + 65536)
#define OFF_EK  (OFF_EQ + 2560)
#define OFF_G   (OFF_EK + 2560)
#define OFF_W   (OFF_G + 32)
#define OFF_PK  (OFF_W + 2560)      // 4*T*D = 262144
#define OFF_T2  (OFF_PK + 262144)   // second split-K partial [1024,512]
#define SCRATCH_TOTAL (OFF_T2 + ND)

__device__ float g_scratch[SCRATCH_TOTAL];

__device__ __forceinline__ float gelu_f(float x) {
    return 0.5f * x * (1.0f + erff(x * 0.7071067811865475f));
}

// ---------------- tf32 / mma / cp.async helpers ------------------------------
__device__ __forceinline__ unsigned f2tf32(float x) {
    unsigned r;
    asm("cvt.rna.tf32.f32 %0, %1;" : "=r"(r) : "f"(x));
    return r;
}
__device__ __forceinline__ void split2(float x, unsigned& hi, unsigned& lo) {
    hi = f2tf32(x);
    lo = f2tf32(x - __uint_as_float(hi));
}
__device__ __forceinline__ void mma_tf32(float* c, const unsigned* a, const unsigned* b) {
    asm volatile(
        "mma.sync.aligned.m16n8k8.row.col.f32.tf32.tf32.f32 "
        "{%0,%1,%2,%3},{%4,%5,%6,%7},{%8,%9},{%0,%1,%2,%3};"
        : "+f"(c[0]), "+f"(c[1]), "+f"(c[2]), "+f"(c[3])
        : "r"(a[0]), "r"(a[1]), "r"(a[2]), "r"(a[3]), "r"(b[0]), "r"(b[1]));
}
__device__ __forceinline__ void cp16(void* s, const void* g) {
    unsigned sa = (unsigned)__cvta_generic_to_shared(s);
    asm volatile("cp.async.cg.shared.global [%0], [%1], 16;\n" :: "r"(sa), "l"(g) : "memory");
}
#define CP_COMMIT() asm volatile("cp.async.commit_group;\n" ::: "memory")
#define CP_WAIT(n)  asm volatile("cp.async.wait_group %0;\n" :: "n"(n) : "memory")

// ---------------- pipelined 3xTF32 GEMM, 64x64 tile, BK=32, 3-stage ----------
// C = A @ B (+bias)(+gelu). A:[M,K] (lda). B: [K,N](ldb) or TRANSB [N,K](ldb).
// 256 threads = 8 warps; warp grid 2(m) x 4(n); warp tile 32x16.
#define PADK 36
#define PADN 72

template<int TRANSB>
__global__ __launch_bounds__(256, 2)
void gemm_tf32(const float* __restrict__ A0, const float* __restrict__ A1, const float* __restrict__ A2,
               const float* __restrict__ W0, const float* __restrict__ W1, const float* __restrict__ W2,
               const float* __restrict__ bias0, const float* __restrict__ bias1, const float* __restrict__ bias2,
               float* __restrict__ C0, float* __restrict__ C1, float* __restrict__ C2,
               int M, int N, int K, int lda, int ldb, int ldc,
               int act, int nH,
               long long sA, long long hA, long long sB, long long hB,
               long long sC, long long hC, int zPerSet) {
    int z = blockIdx.z;
    int set = z / zPerSet;
    int zz = z % zPerSet;
    int bb = zz / nH, hh = zz % nH;

    const float* A  = (set == 0) ? A0 : (set == 1 ? A1 : A2);
    const float* Bm = (set == 0) ? W0 : (set == 1 ? W1 : W2);
    const float* bias = (set == 0) ? bias0 : (set == 1 ? bias1 : bias2);
    float* C = (set == 0) ? C0 : (set == 1 ? C1 : C2);
    A  += bb * sA + hh * hA;
    Bm += bb * sB + hh * hB;
    C  += bb * sC + hh * hC;

    __shared__ float As[3][64][PADK];
    constexpr int BR = TRANSB ? 64 : 32;
    constexpr int BC = TRANSB ? PADK : PADN;
    __shared__ float Bs[3][BR][BC];

    int tid = threadIdx.x;
    int lane = tid & 31, wid = tid >> 5;
    int wm = wid & 1, wn = wid >> 1;
    int l3 = lane & 3, l2 = lane >> 2;

    int bm = blockIdx.y * 64;
    int bn = blockIdx.x * 64;

    int ar = tid >> 2, ak = (tid & 3) * 4;
    int nbr = tid >> 4, nbc = (tid & 15) * 4;

    float acc[2][2][4] = {};

    int nk = K / 32;

    #pragma unroll
    for (int p = 0; p < 2; p++) {
        int k0 = p * 32;
        cp16(&As[p][ar][ak],      A + (size_t)(bm + ar) * lda + k0 + ak);
        cp16(&As[p][ar][ak + 16], A + (size_t)(bm + ar) * lda + k0 + 16 + ak);
        if (TRANSB) {
            cp16(&Bs[p][ar][ak],      Bm + (size_t)(bn + ar) * ldb + k0 + ak);
            cp16(&Bs[p][ar][ak + 16], Bm + (size_t)(bn + ar) * ldb + k0 + 16 + ak);
        } else {
            cp16(&Bs[p][nbr][nbc],      Bm + (size_t)(k0 + nbr) * ldb + bn + nbc);
            cp16(&Bs[p][nbr + 16][nbc], Bm + (size_t)(k0 + nbr + 16) * ldb + bn + nbc);
        }
        CP_COMMIT();
    }

    for (int kt = 0; kt < nk; kt++) {
        CP_WAIT(1);
        __syncthreads();
        int st = kt % 3;
        if (kt + 2 < nk) {
            int ns = (kt + 2) % 3;
            int k0 = (kt + 2) * 32;
            cp16(&As[ns][ar][ak],      A + (size_t)(bm + ar) * lda + k0 + ak);
            cp16(&As[ns][ar][ak + 16], A + (size_t)(bm + ar) * lda + k0 + 16 + ak);
            if (TRANSB) {
                cp16(&Bs[ns][ar][ak],      Bm + (size_t)(bn + ar) * ldb + k0 + ak);
                cp16(&Bs[ns][ar][ak + 16], Bm + (size_t)(bn + ar) * ldb + k0 + 16 + ak);
            } else {
                cp16(&Bs[ns][nbr][nbc],      Bm + (size_t)(k0 + nbr) * ldb + bn + nbc);
                cp16(&Bs[ns][nbr + 16][nbc], Bm + (size_t)(k0 + nbr + 16) * ldb + bn + nbc);
            }
        }
        CP_COMMIT();

        #pragma unroll
        for (int ks = 0; ks < 32; ks += 8) {
            unsigned ah[2][4], al[2][4], bh[2][2], bl[2][2];
            #pragma unroll
            for (int i = 0; i < 2; i++) {
                int m0 = wm * 32 + i * 16;
                split2(As[st][m0 + l2][ks + l3],         ah[i][0], al[i][0]);
                split2(As[st][m0 + l2 + 8][ks + l3],     ah[i][1], al[i][1]);
                split2(As[st][m0 + l2][ks + l3 + 4],     ah[i][2], al[i][2]);
                split2(As[st][m0 + l2 + 8][ks + l3 + 4], ah[i][3], al[i][3]);
            }
            #pragma unroll
            for (int j = 0; j < 2; j++) {
                int n0 = wn * 16 + j * 8;
                if (TRANSB) {
                    split2(Bs[st][n0 + l2][ks + l3],     bh[j][0], bl[j][0]);
                    split2(Bs[st][n0 + l2][ks + l3 + 4], bh[j][1], bl[j][1]);
                } else {
                    split2(Bs[st][ks + l3][n0 + l2],     bh[j][0], bl[j][0]);
                    split2(Bs[st][ks + l3 + 4][n0 + l2], bh[j][1], bl[j][1]);
                }
            }
            #pragma unroll
            for (int i = 0; i < 2; i++)
                #pragma unroll
                for (int j = 0; j < 2; j++)
                    mma_tf32(acc[i][j], ah[i], bh[j]);
            #pragma unroll
            for (int i = 0; i < 2; i++)
                #pragma unroll
                for (int j = 0; j < 2; j++)
                    mma_tf32(acc[i][j], ah[i], bl[j]);
            #pragma unroll
            for (int i = 0; i < 2; i++)
                #pragma unroll
                for (int j = 0; j < 2; j++)
                    mma_tf32(acc[i][j], al[i], bh[j]);
        }
    }

    #pragma unroll
    for (int i = 0; i < 2; i++) {
        #pragma unroll
        for (int j = 0; j < 2; j++) {
            int rg = bm + wm * 32 + i * 16 + l2;
            int cg = bn + wn * 16 + j * 8 + 2 * l3;
            float bv0 = bias ? bias[cg] : 0.0f;
            float bv1 = bias ? bias[cg + 1] : 0.0f;
            float v0 = acc[i][j][0] + bv0, v1 = acc[i][j][1] + bv1;
            float v2 = acc[i][j][2] + bv0, v3 = acc[i][j][3] + bv1;
            if (act) { v0 = gelu_f(v0); v1 = gelu_f(v1); v2 = gelu_f(v2); v3 = gelu_f(v3); }
            *(float2*)(C + (size_t)rg * ldc + cg) = make_float2(v0, v1);
            *(float2*)(C + (size_t)(rg + 8) * ldc + cg) = make_float2(v2, v3);
        }
    }
}

// ---------------- fused attention: 32-row Q tiles, grid (4, 32) --------------
// 256 threads = 8 warps; each warp 16 n-cols; S tile 32x128.
#define APAD 132
#define QR 32
__global__ __launch_bounds__(256)
void fused_attn(const float* __restrict__ Q, const float* __restrict__ K,
                const float* __restrict__ V, float* __restrict__ O) {
    extern __shared__ float dyn[];
    float* Pbuf = dyn;                  // [QR][APAD]
    float* Kbuf = dyn + QR * APAD;      // [128][APAD]
    __shared__ float redM[QR][8];
    __shared__ float redS[QR][8];

    int bz = blockIdx.y;
    int bb = bz >> 2, h = bz & 3;
    int qbase = blockIdx.x * QR;

    int tid = threadIdx.x;
    int lane = tid & 31, wn = tid >> 5;     // warp id = n-slice
    int l3 = lane & 3, l2 = lane >> 2;

    const float* Qg = Q + ((size_t)bb * T + qbase) * D + h * DK;
    const float* Kg = K + ((size_t)bb * T) * D + h * DK;
    const float* Vg = V + ((size_t)bb * T) * D + h * DK;

    // load Q (32x128) and K (128x128)
    #pragma unroll
    for (int t = 0; t < 4; t++) {
        int idx = tid + t * 256;
        int r = idx >> 5, c = (idx & 31) * 4;
        cp16(&Pbuf[r * APAD + c], Qg + (size_t)r * D + c);
    }
    CP_COMMIT();
    #pragma unroll
    for (int t = 0; t < 16; t++) {
        int idx = tid + t * 256;
        int r = idx >> 5, c = (idx & 31) * 4;
        cp16(&Kbuf[r * APAD + c], Kg + (size_t)r * D + c);
    }
    CP_COMMIT();
    CP_WAIT(0);
    __syncthreads();

    // phase 1: S = Q @ K^T  (M=32, N per warp=16, K=128)
    float acc[2][2][4] = {};
    #pragma unroll 4
    for (int ks = 0; ks < DK; ks += 8) {
        unsigned ah[2][4], al[2][4], bh[2][2], bl[2][2];
        #pragma unroll
        for (int i = 0; i < 2; i++) {
            int m0 = i * 16;
            split2(Pbuf[(m0 + l2) * APAD + ks + l3],         ah[i][0], al[i][0]);
            split2(Pbuf[(m0 + l2 + 8) * APAD + ks + l3],     ah[i][1], al[i][1]);
            split2(Pbuf[(m0 + l2) * APAD + ks + l3 + 4],     ah[i][2], al[i][2]);
            split2(Pbuf[(m0 + l2 + 8) * APAD + ks + l3 + 4], ah[i][3], al[i][3]);
        }
        #pragma unroll
        for (int j = 0; j < 2; j++) {
            int n0 = wn * 16 + j * 8;
            split2(Kbuf[(n0 + l2) * APAD + ks + l3],     bh[j][0], bl[j][0]);
            split2(Kbuf[(n0 + l2) * APAD + ks + l3 + 4], bh[j][1], bl[j][1]);
        }
        #pragma unroll
        for (int i = 0; i < 2; i++)
            #pragma unroll
            for (int j = 0; j < 2; j++)
                mma_tf32(acc[i][j], ah[i], bh[j]);
        #pragma unroll
        for (int i = 0; i < 2; i++)
            #pragma unroll
            for (int j = 0; j < 2; j++)
                mma_tf32(acc[i][j], ah[i], bl[j]);
        #pragma unroll
        for (int i = 0; i < 2; i++)
            #pragma unroll
            for (int j = 0; j < 2; j++)
                mma_tf32(acc[i][j], al[i], bh[j]);
    }
    __syncthreads();   // Q/K reads done

    // V load overlaps softmax
    #pragma unroll
    for (int t = 0; t < 16; t++) {
        int idx = tid + t * 256;
        int r = idx >> 5, c = (idx & 31) * 4;
        cp16(&Kbuf[r * APAD + c], Vg + (size_t)r * D + c);
    }
    CP_COMMIT();

    const float sc = 0.08838834764831845f;
    #pragma unroll
    for (int i = 0; i < 2; i++)
        #pragma unroll
        for (int j = 0; j < 2; j++)
            #pragma unroll
            for (int q = 0; q < 4; q++) acc[i][j][q] *= sc;

    #pragma unroll
    for (int i = 0; i < 2; i++)
        #pragma unroll
        for (int hf = 0; hf < 2; hf++) {
            int row = i * 16 + l2 + hf * 8;
            float m = fmaxf(fmaxf(acc[i][0][2 * hf], acc[i][0][2 * hf + 1]),
                            fmaxf(acc[i][1][2 * hf], acc[i][1][2 * hf + 1]));
            m = fmaxf(m, __shfl_xor_sync(0xffffffff, m, 1));
            m = fmaxf(m, __shfl_xor_sync(0xffffffff, m, 2));
            if (l3 == 0) redM[row][wn] = m;
        }
    __syncthreads();
    #pragma unroll
    for (int i = 0; i < 2; i++)
        #pragma unroll
        for (int hf = 0; hf < 2; hf++) {
            int row = i * 16 + l2 + hf * 8;
            float m = redM[row][0];
            #pragma unroll
            for (int w2 = 1; w2 < 8; w2++) m = fmaxf(m, redM[row][w2]);
            float s = 0.0f;
            #pragma unroll
            for (int j = 0; j < 2; j++) {
                acc[i][j][2 * hf]     = expf(acc[i][j][2 * hf] - m);
                acc[i][j][2 * hf + 1] = expf(acc[i][j][2 * hf + 1] - m);
                s += acc[i][j][2 * hf] + acc[i][j][2 * hf + 1];
            }
            s += __shfl_xor_sync(0xffffffff, s, 1);
            s += __shfl_xor_sync(0xffffffff, s, 2);
            if (l3 == 0) redS[row][wn] = s;
        }
    __syncthreads();
    // normalize and write P into Pbuf
    #pragma unroll
    for (int i = 0; i < 2; i++)
        #pragma unroll
        for (int hf = 0; hf < 2; hf++) {
            int row = i * 16 + l2 + hf * 8;
            float ssum = redS[row][0];
            #pragma unroll
            for (int w2 = 1; w2 < 8; w2++) ssum += redS[row][w2];
            float inv = 1.0f / ssum;
            #pragma unroll
            for (int j = 0; j < 2; j++) {
                int col = wn * 16 + j * 8 + 2 * l3;
                Pbuf[row * APAD + col]     = acc[i][j][2 * hf] * inv;
                Pbuf[row * APAD + col + 1] = acc[i][j][2 * hf + 1] * inv;
            }
        }
    CP_WAIT(0);
    __syncthreads();   // P written, V arrived

    // phase 2: O = P @ V  (M=32, N per warp=16 dims, K=128 keys)
    float out[2][2][4] = {};
    #pragma unroll 4
    for (int ks = 0; ks < T; ks += 8) {
        unsigned ah[2][4], al[2][4], bh[2][2], bl[2][2];
        #pragma unroll
        for (int i = 0; i < 2; i++) {
            int m0 = i * 16;
            split2(Pbuf[(m0 + l2) * APAD + ks + l3],         ah[i][0], al[i][0]);
            split2(Pbuf[(m0 + l2 + 8) * APAD + ks + l3],     ah[i][1], al[i][1]);
            split2(Pbuf[(m0 + l2) * APAD + ks + l3 + 4],     ah[i][2], al[i][2]);
            split2(Pbuf[(m0 + l2 + 8) * APAD + ks + l3 + 4], ah[i][3], al[i][3]);
        }
        #pragma unroll
        for (int j = 0; j < 2; j++) {
            int n0 = wn * 16 + j * 8;
            split2(Kbuf[(ks + l3) * APAD + n0 + l2],     bh[j][0], bl[j][0]);
            split2(Kbuf[(ks + l3 + 4) * APAD + n0 + l2], bh[j][1], bl[j][1]);
        }
        #pragma unroll
        for (int i = 0; i < 2; i++)
            #pragma unroll
            for (int j = 0; j < 2; j++)
                mma_tf32(out[i][j], ah[i], bh[j]);
        #pragma unroll
        for (int i = 0; i < 2; i++)
            #pragma unroll
            for (int j = 0; j < 2; j++)
                mma_tf32(out[i][j], ah[i], bl[j]);
        #pragma unroll
        for (int i = 0; i < 2; i++)
            #pragma unroll
            for (int j = 0; j < 2; j++)
                mma_tf32(out[i][j], al[i], bh[j]);
    }

    float* Og = O + ((size_t)bb * T + qbase) * D + h * DK;
    #pragma unroll
    for (int i = 0; i < 2; i++)
        #pragma unroll
        for (int j = 0; j < 2; j++) {
            int r = i * 16 + l2;
            int c = wn * 16 + j * 8 + 2 * l3;
            *(float2*)(Og + (size_t)r * D + c) = make_float2(out[i][j][0], out[i][j][1]);
            *(float2*)(Og + (size_t)(r + 8) * D + c) = make_float2(out[i][j][2], out[i][j][3]);
        }
}

// ---------------- warp helpers ----------------------------------------------
__device__ __forceinline__ float warp_sum(float v) {
    #pragma unroll
    for (int o = 16; o > 0; o >>= 1) v += __shfl_xor_sync(0xffffffff, v, o);
    return v;
}
__device__ __forceinline__ float warp_max(float v) {
    #pragma unroll
    for (int o = 16; o > 0; o >>= 1) v = fmaxf(v, __shfl_xor_sync(0xffffffff, v, o));
    return v;
}

// ---------------- LayerNorm kernels ------------------------------------------
__global__ void add_pos_ln_kernel(const float* __restrict__ x, const float* __restrict__ pos,
                                  const float* __restrict__ w, const float* __restrict__ b,
                                  float* __restrict__ out) {
    int row = blockIdx.x, tid = threadIdx.x;
    int lane = tid & 31, wd = tid >> 5;
    __shared__ float p1[4], p2[4];

    float4 xv = ((const float4*)(x + (size_t)row * D))[tid];
    float4 pv = ((const float4*)(pos + (size_t)(row % T) * D))[tid];
    float4 v = make_float4(xv.x + pv.x, xv.y + pv.y, xv.z + pv.z, xv.w + pv.w);

    float s = warp_sum(v.x + v.y + v.z + v.w);
    if (lane == 0) p1[wd] = s;
    __syncthreads();
    float mean = (p1[0] + p1[1] + p1[2] + p1[3]) * (1.0f / D);
    float4 d = make_float4(v.x - mean, v.y - mean, v.z - mean, v.w - mean);
    float q = warp_sum(d.x * d.x + d.y * d.y + d.z * d.z + d.w * d.w);
    if (lane == 0) p2[wd] = q;
    __syncthreads();
    float inv = rsqrtf((p2[0] + p2[1] + p2[2] + p2[3]) * (1.0f / D) + 1e-12f);

    float4 wv = ((const float4*)w)[tid];
    float4 bv = ((const float4*)b)[tid];
    ((float4*)(out + (size_t)row * D))[tid] =
        make_float4(wv.x * d.x * inv + bv.x, wv.y * d.y * inv + bv.y,
                    wv.z * d.z * inv + bv.z, wv.w * d.w * inv + bv.w);
}

// x += y0 + y1 (persist); out = LN(x)*w+b.  (out may alias x; y1 may be null)
__global__ void residual_ln2_kernel(float* __restrict__ x, const float* __restrict__ y0,
                                    const float* __restrict__ y1,
                                    float* __restrict__ out,
                                    const float* __restrict__ w, const float* __restrict__ b) {
    int row = blockIdx.x, tid = threadIdx.x;
    int lane = tid & 31, wd = tid >> 5;
    __shared__ float p1[4], p2[4];

    float4 xv = ((const float4*)(x + (size_t)row * D))[tid];
    float4 y0v = ((const float4*)(y0 + (size_t)row * D))[tid];
    float4 v = make_float4(xv.x + y0v.x, xv.y + y0v.y, xv.z + y0v.z, xv.w + y0v.w);
    if (y1) {
        float4 y1v = ((const float4*)(y1 + (size_t)row * D))[tid];
        v.x += y1v.x; v.y += y1v.y; v.z += y1v.z; v.w += y1v.w;
    }
    ((float4*)(x + (size_t)row * D))[tid] = v;

    float s = warp_sum(v.x + v.y + v.z + v.w);
    if (lane == 0) p1[wd] = s;
    __syncthreads();
    float mean = (p1[0] + p1[1] + p1[2] + p1[3]) * (1.0f / D);
    float4 d = make_float4(v.x - mean, v.y - mean, v.z - mean, v.w - mean);
    float q = warp_sum(d.x * d.x + d.y * d.y + d.z * d.z + d.w * d.w);
    if (lane == 0) p2[wd] = q;
    __syncthreads();
    float inv = rsqrtf((p2[0] + p2[1] + p2[2] + p2[3]) * (1.0f / D) + 1e-12f);

    float4 wv = ((const float4*)w)[tid];
    float4 bv = ((const float4*)b)[tid];
    ((float4*)(out + (size_t)row * D))[tid] =
        make_float4(wv.x * d.x * inv + bv.x, wv.y * d.y * inv + bv.y,
                    wv.z * d.z * inv + bv.z, wv.w * d.w * inv + bv.w);
}

// ---------------- sim head helpers ------------------------------------------
__global__ void edot_kernel(const float* __restrict__ X, const float* __restrict__ E,
                            float* __restrict__ out) {
    int row = blockIdx.x;
    int tid = threadIdx.x;
    __shared__ float red[NC * 256];
    float acc[NC] = {};
    for (int d = tid; d < D; d += 256) {
        float x = X[(size_t)row * D + d];
        #pragma unroll
        for (int c = 0; c < NC; c++) acc[c] += x * E[(size_t)c * D + d];
    }
    #pragma unroll
    for (int c = 0; c < NC; c++) red[c * 256 + tid] = acc[c];
    __syncthreads();
    for (int off = 128; off > 0; off >>= 1) {
        if (tid < off) {
            #pragma unroll
            for (int c = 0; c < NC; c++) red[c * 256 + tid] += red[c * 256 + tid + off];
        }
        __syncthreads();
    }
    if (tid < NC) out[(size_t)row * NC + tid] = red[tid * 256];
}

__global__ void gram_kernel(const float* __restrict__ E, float* __restrict__ G) {
    int i = threadIdx.x;
    if (i < NC * NC) {
        int c = i / NC, c2 = i % NC;
        float s = 0.0f;
        for (int d = 0; d < D; d++) s += E[(size_t)c * D + d] * E[(size_t)c2 * D + d];
        G[i] = s;
    }
}

__global__ void sim_attn_kernel(const float* __restrict__ QK, const float* __restrict__ qa,
                                const float* __restrict__ aq, const float* __restrict__ Eq,
                                const float* __restrict__ Ek, const float* __restrict__ G,
                                float* __restrict__ P, float* __restrict__ Wout) {
    int t = blockIdx.x, b = blockIdx.y;
    int s = threadIdx.x;                 // 128 threads
    int lane = s & 31, wd = s >> 5;
    __shared__ float g[NC * NC];
    __shared__ float part[4];
    __shared__ float pv[T];
    if (s < NC * NC) g[s] = G[s];
    __syncthreads();

    float f1[NC], f2[NC];
    const float* r1 = qa + (((size_t)b * T + t) * T + s) * NC;
    const float* r2 = aq + (((size_t)b * T + s) * T + t) * NC;
    #pragma unroll
    for (int c = 0; c < NC; c++) { f1[c] = r1[c]; f2[c] = r2[c]; }

    float sc = QK[((size_t)b * T + t) * T + s];
    const float* eq = Eq + ((size_t)b * T + t) * NC;
    const float* ek = Ek + ((size_t)b * T + s) * NC;
    #pragma unroll
    for (int c = 0; c < NC; c++) sc += f1[c] * ek[c] + f2[c] * eq[c];
    #pragma unroll
    for (int c = 0; c < NC; c++)
        #pragma unroll
        for (int c2 = 0; c2 < NC; c2++)
            sc += f1[c] * g[c * NC + c2] * f2[c2];

    float m = warp_max(sc);
    if (lane == 0) part[wd] = m;
    __syncthreads();
    float m1 = fmaxf(fmaxf(part[0], part[1]), fmaxf(part[2], part[3]));
    float e1 = expf(sc - m1);
    float ssum = warp_sum(e1);
    if (lane == 0) part[wd] = ssum;
    __syncthreads();
    float p = e1 / (part[0] + part[1] + part[2] + part[3]);

    float l = 1000.0f * p;
    m = warp_max(l);
    __syncthreads();
    if (lane == 0) part[wd] = m;
    __syncthreads();
    float m2 = fmaxf(fmaxf(part[0], part[1]), fmaxf(part[2], part[3]));
    float e2 = expf(l - m2);
    ssum = warp_sum(e2);
    __syncthreads();
    if (lane == 0) part[wd] = ssum;
    __syncthreads();
    float p2 = e2 / (part[0] + part[1] + part[2] + part[3]);
    p2 = fminf(fmaxf(p2, 0.0f), 1.0f);

    P[((size_t)b * T + t) * T + s] = p2;
    pv[s] = p2;
    __syncthreads();

    #pragma unroll
    for (int c = 0; c < NC; c++) {
        float v = warp_sum(pv[s] * f2[c]);
        __syncthreads();
        if (lane == 0) part[wd] = v;
        __syncthreads();
        if (s == 0) Wout[((size_t)b * T + t) * NC + c] = part[0] + part[1] + part[2] + part[3];
    }
}

__global__ void final_kernel(const float* __restrict__ pk, const float* __restrict__ Wm,
                             const float* __restrict__ E, const float* __restrict__ clsw,
                             const float* __restrict__ clsb, float* __restrict__ out) {
    int b = blockIdx.x;
    int d = threadIdx.x;
    __shared__ float wm[NC];
    __shared__ float red[512];

    if (d < NC) {
        float s = 0.0f;
        for (int t = 0; t < T; t++) s += Wm[((size_t)b * T + t) * NC + d];
        wm[d] = s * (1.0f / T);
    }
    __syncthreads();

    float s = 0.0f;
    for (int t = 0; t < T; t++) s += pk[((size_t)b * T + t) * D + d];
    s *= (1.0f / T);
    #pragma unroll
    for (int c = 0; c < NC; c++) s += wm[c] * E[(size_t)c * D + d];

    for (int j = 0; j < 3; j++) {
        red[d] = s * clsw[(size_t)d * 3 + j];
        __syncthreads();
        for (int off = 256; off > 0; off >>= 1) { if (d < off) red[d] += red[d + off]; __syncthreads(); }
        if (d == 0) out[b * 3 + j] = red[0] + clsb[j];
        __syncthreads();
    }
}

// ---------------- host orchestration ----------------------------------------
static inline void g_launch(int transB,
                            const float* A0, const float* A1, const float* A2,
                            const float* W0, const float* W1, const float* W2,
                            const float* b0, const float* b1, const float* b2,
                            float* C0, float* C1, float* C2,
                            int M, int N, int K, int lda, int ldb, int ldc,
                            int act, int nH,
                            long long sA, long long hA, long long sB, long long hB,
                            long long sC, long long hC, int zPerSet, int nz) {
    dim3 grid(N / 64, M / 64, nz);
    if (transB)
        gemm_tf32<1><<<grid, 256>>>(A0, A1, A2, W0, W1, W2, b0, b1, b2, C0, C1, C2,
                                    M, N, K, lda, ldb, ldc, act, nH,
                                    sA, hA, sB, hB, sC, hC, zPerSet);
    else
        gemm_tf32<0><<<grid, 256>>>(A0, A1, A2, W0, W1, W2, b0, b1, b2, C0, C1, C2,
                                    M, N, K, lda, ldb, ldc, act, nH,
                                    sA, hA, sB, hB, sC, hC, zPerSet);
}

extern "C" void kernel_launch(void* const* d_in, const int* in_sizes, int n_in,
                              void* d_out, int out_size) {
    const float* q_emb   = (const float*)d_in[0];
    const float* a_emb   = (const float*)d_in[1];
    const float* qa_rel  = (const float*)d_in[2];
    const float* aq_rel  = (const float*)d_in[3];
    const float* conceptE= (const float*)d_in[4];
    const float* pos_emb = (const float*)d_in[5];
    const float* pe_w    = (const float*)d_in[6];
    const float* pe_b    = (const float*)d_in[7];
    const float* Wq      = (const float*)d_in[8];
    const float* bq      = (const float*)d_in[9];
    const float* Wk      = (const float*)d_in[10];
    const float* bk      = (const float*)d_in[11];
    const float* Wv      = (const float*)d_in[12];
    const float* bv      = (const float*)d_in[13];
    const float* Wo      = (const float*)d_in[14];
    const float* bo      = (const float*)d_in[15];
    const float* ff1w    = (const float*)d_in[16];
    const float* ff1b    = (const float*)d_in[17];
    const float* ff2w    = (const float*)d_in[18];
    const float* ff2b    = (const float*)d_in[19];
    const float* lninw   = (const float*)d_in[20];
    const float* lninb   = (const float*)d_in[21];
    const float* lnoutw  = (const float*)d_in[22];
    const float* lnoutb  = (const float*)d_in[23];
    const float* simWq   = (const float*)d_in[24];
    const float* simbq   = (const float*)d_in[25];
    const float* simWk   = (const float*)d_in[26];
    const float* simbk   = (const float*)d_in[27];
    const float* clsw    = (const float*)d_in[28];
    const float* clsb    = (const float*)d_in[29];
    float* out = (float*)d_out;

    float* base = nullptr;
    cudaGetSymbolAddress((void**)&base, g_scratch);

    float* X   = base + OFF_X;
    float* Qb  = base + OFF_Q;
    float* Kb  = base + OFF_K;
    float* Vb  = base + OFF_V;
    float* T0  = base + OFF_T0;
    float* T1b = base + OFF_T1;
    float* T2b = base + OFF_T2;
    float* Hb  = base + OFF_H;
    float* FFN = base + OFF_FFN;
    float* QKb = base + OFF_QK;
    float* Pb  = base + OFF_P;
    float* EQb = base + OFF_EQ;
    float* EKb = base + OFF_EK;
    float* Gb  = base + OFF_G;
    float* Wb  = base + OFF_W;
    float* PKb = base + OFF_PK;

    static const int ATTN_SMEM = (QR + 128) * APAD * 4;
    cudaFuncSetAttribute(fused_attn, cudaFuncAttributeMaxDynamicSharedMemorySize, ATTN_SMEM);

    add_pos_ln_kernel<<<M2 / 2, 128>>>(q_emb, pos_emb, pe_w, pe_b, X);
    add_pos_ln_kernel<<<M2 / 2, 128>>>(a_emb, pos_emb, pe_w, pe_b, X + (size_t)(M2 / 2) * D);

    for (int i = 0; i < NL; i++) {
        const float* wq = Wq + (size_t)i * D * D;
        const float* wk = Wk + (size_t)i * D * D;
        const float* wv = Wv + (size_t)i * D * D;
        const float* wo = Wo + (size_t)i * D * D;

        // fused QKV: 3 sets, one launch (grid 8x16x3 = 384)
        g_launch(0, X, X, X, wq, wk, wv,
                 bq + (size_t)i * D, bk + (size_t)i * D, bv + (size_t)i * D,
                 Qb, Kb, Vb,
                 M2, D, D, D, D, D, 0, 1, 0, 0, 0, 0, 0, 0, 1, 3);

        // fused attention: grid (4, 32) = 128 CTAs
        fused_attn<<<dim3(4, 32), 256, ATTN_SMEM>>>(Qb, Kb, Vb, T0);

        // output projection split-K=2 (grid 8x16x2 = 256)
        g_launch(0, T0, T0 + 256, 0, wo, wo + (size_t)256 * D, 0,
                 bo + (size_t)i * D, 0, 0, T1b, T2b, 0,
                 M2, D, 256, D, D, D, 0, 1, 0, 0, 0, 0, 0, 0, 1, 2);

        residual_ln2_kernel<<<M2, 128>>>(X, T1b, T2b, Hb,
                                         lninw + (size_t)i * D, lninb + (size_t)i * D);

        g_launch(0, Hb, 0, 0, ff1w + (size_t)i * D * DFF, 0, 0, ff1b + (size_t)i * DFF, 0, 0, FFN, 0, 0,
                 M2, DFF, D, D, DFF, DFF, 1, 1, 0, 0, 0, 0, 0, 0, 1, 1);

        // ff2 split-K=2 (grid 8x16x2 = 256)
        g_launch(0, FFN, FFN + 1024, 0,
                 ff2w + (size_t)i * DFF * D, ff2w + (size_t)i * DFF * D + (size_t)1024 * D, 0,
                 ff2b + (size_t)i * D, 0, 0, T1b, T2b, 0,
                 M2, D, 1024, DFF, D, D, 0, 1, 0, 0, 0, 0, 0, 0, 1, 2);

        residual_ln2_kernel<<<M2, 128>>>(X, T1b, T2b, X,
                                         lnoutw + (size_t)i * D, lnoutb + (size_t)i * D);
    }

    // --- sim head ---
    g_launch(0, X, X + (size_t)(M2 / 2) * D, 0, simWq, simWk, 0, simbq, simbk, 0, Qb, Kb, 0,
             M2 / 2, D, D, D, D, D, 0, 1, 0, 0, 0, 0, 0, 0, 1, 2);

    edot_kernel<<<M2 / 2, 256>>>(Qb, conceptE, EQb);
    edot_kernel<<<M2 / 2, 256>>>(Kb, conceptE, EKb);
    gram_kernel<<<1, 32>>>(conceptE, Gb);

    // QK[b] = q_sim[b] @ k_sim[b]^T
    g_launch(1, Qb, 0, 0, Kb, 0, 0, 0, 0, 0, QKb, 0, 0,
             T, T, D, D, D, T, 0, 1,
             (long long)T * D, 0, (long long)T * D, 0, (long long)T * T, 0, 4, 4);

    sim_attn_kernel<<<dim3(T, Bb), 128>>>(QKb, qa_rel, aq_rel, EQb, EKb, Gb, Pb, Wb);

    // pk[b] = P[b] @ k_sim[b]
    g_launch(0, Pb, 0, 0, Kb, 0, 0, 0, 0, 0, PKb, 0, 0,
             T, D, T, T, D, D, 0, 1,
             (long long)T * T, 0, (long long)T * D, 0, (long long)T * D, 0, 4, 4);

    final_kernel<<<Bb, 512>>>(PKb, Wb, conceptE, clsw, clsb, out);
}

// round 12
// speedup vs baseline: 1.3269x; 1.0065x over previous
#include <cuda_runtime.h>
#include <cuda_bf16.h>
#include <math.h>

// Problem constants
#define Bb   4
#define T    128
#define D    512
#define Hh   4
#define DK   128
#define NL   4
#define DFF  2048
#define NC   5

#define M2   1024            // merged towers: 2*Bb*T rows
#define ND   (M2*D)          // 524288

// ---------------- scratch ----------------------------------------------------
#define OFF_X   0
#define OFF_Q   (1*ND)
#define OFF_K   (2*ND)
#define OFF_V   (3*ND)
#define OFF_T0  (4*ND)
#define OFF_T1  (5*ND)
#define OFF_H   (6*ND)
#define OFF_FFN (7*ND)              // M2*DFF = 4*ND
#define OFF_QK  (11*ND)
#define OFF_P   (OFF_QK + 65536)
#define OFF_EQ  (OFF_P + 65536)
#define OFF_EK  (OFF_EQ + 2560)
#define OFF_G   (OFF_EK + 2560)
#define OFF_W   (OFF_G + 32)
#define OFF_PK  (OFF_W + 2560)      // 4*T*D = 262144
#define OFF_T2  (OFF_PK + 262144)   // second split-K partial [1024,512]
#define OFF_QK2 (OFF_T2 + ND)       // QK split-K partial 2
#define OFF_PK2 (OFF_QK2 + 65536)   // PK split-K partial 2
#define SCRATCH_TOTAL (OFF_PK2 + 262144)

__device__ float g_scratch[SCRATCH_TOTAL];

__device__ __forceinline__ float gelu_f(float x) {
    return 0.5f * x * (1.0f + erff(x * 0.7071067811865475f));
}

// ---------------- tf32 / mma / cp.async helpers ------------------------------
__device__ __forceinline__ unsigned f2tf32(float x) {
    unsigned r;
    asm("cvt.rna.tf32.f32 %0, %1;" : "=r"(r) : "f"(x));
    return r;
}
__device__ __forceinline__ void split2(float x, unsigned& hi, unsigned& lo) {
    hi = f2tf32(x);
    lo = f2tf32(x - __uint_as_float(hi));
}
__device__ __forceinline__ void mma_tf32(float* c, const unsigned* a, const unsigned* b) {
    asm volatile(
        "mma.sync.aligned.m16n8k8.row.col.f32.tf32.tf32.f32 "
        "{%0,%1,%2,%3},{%4,%5,%6,%7},{%8,%9},{%0,%1,%2,%3};"
        : "+f"(c[0]), "+f"(c[1]), "+f"(c[2]), "+f"(c[3])
        : "r"(a[0]), "r"(a[1]), "r"(a[2]), "r"(a[3]), "r"(b[0]), "r"(b[1]));
}
__device__ __forceinline__ void cp16(void* s, const void* g) {
    unsigned sa = (unsigned)__cvta_generic_to_shared(s);
    asm volatile("cp.async.cg.shared.global [%0], [%1], 16;\n" :: "r"(sa), "l"(g) : "memory");
}
#define CP_COMMIT() asm volatile("cp.async.commit_group;\n" ::: "memory")
#define CP_WAIT(n)  asm volatile("cp.async.wait_group %0;\n" :: "n"(n) : "memory")

// ---------------- pipelined 3xTF32 GEMM, 64x64 tile, BK=32, 3-stage ----------
#define PADK 36
#define PADN 72

template<int TRANSB>
__global__ __launch_bounds__(256, 2)
void gemm_tf32(const float* __restrict__ A0, const float* __restrict__ A1, const float* __restrict__ A2,
               const float* __restrict__ W0, const float* __restrict__ W1, const float* __restrict__ W2,
               const float* __restrict__ bias0, const float* __restrict__ bias1, const float* __restrict__ bias2,
               float* __restrict__ C0, float* __restrict__ C1, float* __restrict__ C2,
               int M, int N, int K, int lda, int ldb, int ldc,
               int act, int nH,
               long long sA, long long hA, long long sB, long long hB,
               long long sC, long long hC, int zPerSet) {
    int z = blockIdx.z;
    int set = z / zPerSet;
    int zz = z % zPerSet;
    int bb = zz / nH, hh = zz % nH;

    const float* A  = (set == 0) ? A0 : (set == 1 ? A1 : A2);
    const float* Bm = (set == 0) ? W0 : (set == 1 ? W1 : W2);
    const float* bias = (set == 0) ? bias0 : (set == 1 ? bias1 : bias2);
    float* C = (set == 0) ? C0 : (set == 1 ? C1 : C2);
    A  += bb * sA + hh * hA;
    Bm += bb * sB + hh * hB;
    C  += bb * sC + hh * hC;

    __shared__ float As[3][64][PADK];
    constexpr int BR = TRANSB ? 64 : 32;
    constexpr int BC = TRANSB ? PADK : PADN;
    __shared__ float Bs[3][BR][BC];

    int tid = threadIdx.x;
    int lane = tid & 31, wid = tid >> 5;
    int wm = wid & 1, wn = wid >> 1;
    int l3 = lane & 3, l2 = lane >> 2;

    int bm = blockIdx.y * 64;
    int bn = blockIdx.x * 64;

    int ar = tid >> 2, ak = (tid & 3) * 4;
    int nbr = tid >> 4, nbc = (tid & 15) * 4;

    float acc[2][2][4] = {};

    int nk = K / 32;

    #pragma unroll
    for (int p = 0; p < 2; p++) {
        int k0 = p * 32;
        cp16(&As[p][ar][ak],      A + (size_t)(bm + ar) * lda + k0 + ak);
        cp16(&As[p][ar][ak + 16], A + (size_t)(bm + ar) * lda + k0 + 16 + ak);
        if (TRANSB) {
            cp16(&Bs[p][ar][ak],      Bm + (size_t)(bn + ar) * ldb + k0 + ak);
            cp16(&Bs[p][ar][ak + 16], Bm + (size_t)(bn + ar) * ldb + k0 + 16 + ak);
        } else {
            cp16(&Bs[p][nbr][nbc],      Bm + (size_t)(k0 + nbr) * ldb + bn + nbc);
            cp16(&Bs[p][nbr + 16][nbc], Bm + (size_t)(k0 + nbr + 16) * ldb + bn + nbc);
        }
        CP_COMMIT();
    }

    for (int kt = 0; kt < nk; kt++) {
        CP_WAIT(1);
        __syncthreads();
        int st = kt % 3;
        if (kt + 2 < nk) {
            int ns = (kt + 2) % 3;
            int k0 = (kt + 2) * 32;
            cp16(&As[ns][ar][ak],      A + (size_t)(bm + ar) * lda + k0 + ak);
            cp16(&As[ns][ar][ak + 16], A + (size_t)(bm + ar) * lda + k0 + 16 + ak);
            if (TRANSB) {
                cp16(&Bs[ns][ar][ak],      Bm + (size_t)(bn + ar) * ldb + k0 + ak);
                cp16(&Bs[ns][ar][ak + 16], Bm + (size_t)(bn + ar) * ldb + k0 + 16 + ak);
            } else {
                cp16(&Bs[ns][nbr][nbc],      Bm + (size_t)(k0 + nbr) * ldb + bn + nbc);
                cp16(&Bs[ns][nbr + 16][nbc], Bm + (size_t)(k0 + nbr + 16) * ldb + bn + nbc);
            }
        }
        CP_COMMIT();

        #pragma unroll
        for (int ks = 0; ks < 32; ks += 8) {
            unsigned ah[2][4], al[2][4], bh[2][2], bl[2][2];
            #pragma unroll
            for (int i = 0; i < 2; i++) {
                int m0 = wm * 32 + i * 16;
                split2(As[st][m0 + l2][ks + l3],         ah[i][0], al[i][0]);
                split2(As[st][m0 + l2 + 8][ks + l3],     ah[i][1], al[i][1]);
                split2(As[st][m0 + l2][ks + l3 + 4],     ah[i][2], al[i][2]);
                split2(As[st][m0 + l2 + 8][ks + l3 + 4], ah[i][3], al[i][3]);
            }
            #pragma unroll
            for (int j = 0; j < 2; j++) {
                int n0 = wn * 16 + j * 8;
                if (TRANSB) {
                    split2(Bs[st][n0 + l2][ks + l3],     bh[j][0], bl[j][0]);
                    split2(Bs[st][n0 + l2][ks + l3 + 4], bh[j][1], bl[j][1]);
                } else {
                    split2(Bs[st][ks + l3][n0 + l2],     bh[j][0], bl[j][0]);
                    split2(Bs[st][ks + l3 + 4][n0 + l2], bh[j][1], bl[j][1]);
                }
            }
            #pragma unroll
            for (int i = 0; i < 2; i++)
                #pragma unroll
                for (int j = 0; j < 2; j++)
                    mma_tf32(acc[i][j], ah[i], bh[j]);
            #pragma unroll
            for (int i = 0; i < 2; i++)
                #pragma unroll
                for (int j = 0; j < 2; j++)
                    mma_tf32(acc[i][j], ah[i], bl[j]);
            #pragma unroll
            for (int i = 0; i < 2; i++)
                #pragma unroll
                for (int j = 0; j < 2; j++)
                    mma_tf32(acc[i][j], al[i], bh[j]);
        }
    }

    #pragma unroll
    for (int i = 0; i < 2; i++) {
        #pragma unroll
        for (int j = 0; j < 2; j++) {
            int rg = bm + wm * 32 + i * 16 + l2;
            int cg = bn + wn * 16 + j * 8 + 2 * l3;
            float bv0 = bias ? bias[cg] : 0.0f;
            float bv1 = bias ? bias[cg + 1] : 0.0f;
            float v0 = acc[i][j][0] + bv0, v1 = acc[i][j][1] + bv1;
            float v2 = acc[i][j][2] + bv0, v3 = acc[i][j][3] + bv1;
            if (act) { v0 = gelu_f(v0); v1 = gelu_f(v1); v2 = gelu_f(v2); v3 = gelu_f(v3); }
            *(float2*)(C + (size_t)rg * ldc + cg) = make_float2(v0, v1);
            *(float2*)(C + (size_t)(rg + 8) * ldc + cg) = make_float2(v2, v3);
        }
    }
}

// ---------------- fused attention: 32-row Q tiles, pre-split Q/P planes ------
// dyn smem: Qraw[QR][APAD] f32, Qsp[QR][APAD] float2(hi,lo), Kbuf[128][APAD] f32
#define APAD 132
#define QR 32
__global__ __launch_bounds__(256)
void fused_attn(const float* __restrict__ Q, const float* __restrict__ K,
                const float* __restrict__ V, float* __restrict__ O) {
    extern __shared__ float dyn[];
    float*  Qraw = dyn;
    float2* Qsp  = (float2*)(dyn + QR * APAD);
    float*  Kbuf = dyn + QR * APAD * 3;
    __shared__ float redM[QR][8];
    __shared__ float redS[QR][8];

    int bz = blockIdx.y;
    int bb = bz >> 2, h = bz & 3;
    int qbase = blockIdx.x * QR;

    int tid = threadIdx.x;
    int lane = tid & 31, wn = tid >> 5;
    int l3 = lane & 3, l2 = lane >> 2;

    const float* Qg = Q + ((size_t)bb * T + qbase) * D + h * DK;
    const float* Kg = K + ((size_t)bb * T) * D + h * DK;
    const float* Vg = V + ((size_t)bb * T) * D + h * DK;

    #pragma unroll
    for (int t = 0; t < 4; t++) {
        int idx = tid + t * 256;
        int r = idx >> 5, c = (idx & 31) * 4;
        cp16(&Qraw[r * APAD + c], Qg + (size_t)r * D + c);
    }
    CP_COMMIT();
    #pragma unroll
    for (int t = 0; t < 16; t++) {
        int idx = tid + t * 256;
        int r = idx >> 5, c = (idx & 31) * 4;
        cp16(&Kbuf[r * APAD + c], Kg + (size_t)r * D + c);
    }
    CP_COMMIT();
    CP_WAIT(0);
    __syncthreads();

    // split Q once into (hi,lo) plane
    #pragma unroll
    for (int t = 0; t < 16; t++) {
        int idx = tid + t * 256;            // QR*128 = 4096
        int r = idx >> 7, c = idx & 127;
        unsigned hh2, ll2;
        split2(Qraw[r * APAD + c], hh2, ll2);
        Qsp[r * APAD + c] = make_float2(__uint_as_float(hh2), __uint_as_float(ll2));
    }
    __syncthreads();

    // phase 1: S = Q @ K^T  (M=32, N per warp=16, K=128)
    float acc[2][2][4] = {};
    #pragma unroll 4
    for (int ks = 0; ks < DK; ks += 8) {
        unsigned ah[2][4], al[2][4], bh[2][2], bl[2][2];
        #pragma unroll
        for (int i = 0; i < 2; i++) {
            int m0 = i * 16;
            float2 v0 = Qsp[(m0 + l2) * APAD + ks + l3];
            float2 v1 = Qsp[(m0 + l2 + 8) * APAD + ks + l3];
            float2 v2 = Qsp[(m0 + l2) * APAD + ks + l3 + 4];
            float2 v3 = Qsp[(m0 + l2 + 8) * APAD + ks + l3 + 4];
            ah[i][0] = __float_as_uint(v0.x); al[i][0] = __float_as_uint(v0.y);
            ah[i][1] = __float_as_uint(v1.x); al[i][1] = __float_as_uint(v1.y);
            ah[i][2] = __float_as_uint(v2.x); al[i][2] = __float_as_uint(v2.y);
            ah[i][3] = __float_as_uint(v3.x); al[i][3] = __float_as_uint(v3.y);
        }
        #pragma unroll
        for (int j = 0; j < 2; j++) {
            int n0 = wn * 16 + j * 8;
            split2(Kbuf[(n0 + l2) * APAD + ks + l3],     bh[j][0], bl[j][0]);
            split2(Kbuf[(n0 + l2) * APAD + ks + l3 + 4], bh[j][1], bl[j][1]);
        }
        #pragma unroll
        for (int i = 0; i < 2; i++)
            #pragma unroll
            for (int j = 0; j < 2; j++)
                mma_tf32(acc[i][j], ah[i], bh[j]);
        #pragma unroll
        for (int i = 0; i < 2; i++)
            #pragma unroll
            for (int j = 0; j < 2; j++)
                mma_tf32(acc[i][j], ah[i], bl[j]);
        #pragma unroll
        for (int i = 0; i < 2; i++)
            #pragma unroll
            for (int j = 0; j < 2; j++)
                mma_tf32(acc[i][j], al[i], bh[j]);
    }
    __syncthreads();   // K reads done

    // V load overlaps softmax
    #pragma unroll
    for (int t = 0; t < 16; t++) {
        int idx = tid + t * 256;
        int r = idx >> 5, c = (idx & 31) * 4;
        cp16(&Kbuf[r * APAD + c], Vg + (size_t)r * D + c);
    }
    CP_COMMIT();

    const float sc = 0.08838834764831845f;
    #pragma unroll
    for (int i = 0; i < 2; i++)
        #pragma unroll
        for (int j = 0; j < 2; j++)
            #pragma unroll
            for (int q = 0; q < 4; q++) acc[i][j][q] *= sc;

    #pragma unroll
    for (int i = 0; i < 2; i++)
        #pragma unroll
        for (int hf = 0; hf < 2; hf++) {
            int row = i * 16 + l2 + hf * 8;
            float m = fmaxf(fmaxf(acc[i][0][2 * hf], acc[i][0][2 * hf + 1]),
                            fmaxf(acc[i][1][2 * hf], acc[i][1][2 * hf + 1]));
            m = fmaxf(m, __shfl_xor_sync(0xffffffff, m, 1));
            m = fmaxf(m, __shfl_xor_sync(0xffffffff, m, 2));
            if (l3 == 0) redM[row][wn] = m;
        }
    __syncthreads();
    #pragma unroll
    for (int i = 0; i < 2; i++)
        #pragma unroll
        for (int hf = 0; hf < 2; hf++) {
            int row = i * 16 + l2 + hf * 8;
            float m = redM[row][0];
            #pragma unroll
            for (int w2 = 1; w2 < 8; w2++) m = fmaxf(m, redM[row][w2]);
            float s = 0.0f;
            #pragma unroll
            for (int j = 0; j < 2; j++) {
                acc[i][j][2 * hf]     = expf(acc[i][j][2 * hf] - m);
                acc[i][j][2 * hf + 1] = expf(acc[i][j][2 * hf + 1] - m);
                s += acc[i][j][2 * hf] + acc[i][j][2 * hf + 1];
            }
            s += __shfl_xor_sync(0xffffffff, s, 1);
            s += __shfl_xor_sync(0xffffffff, s, 2);
            if (l3 == 0) redS[row][wn] = s;
        }
    __syncthreads();
    // normalize and write P pre-split into Qsp
    #pragma unroll
    for (int i = 0; i < 2; i++)
        #pragma unroll
        for (int hf = 0; hf < 2; hf++) {
            int row = i * 16 + l2 + hf * 8;
            float ssum = redS[row][0];
            #pragma unroll
            for (int w2 = 1; w2 < 8; w2++) ssum += redS[row][w2];
            float inv = 1.0f / ssum;
            #pragma unroll
            for (int j = 0; j < 2; j++) {
                int col = wn * 16 + j * 8 + 2 * l3;
                unsigned h0, l0, h1, l1;
                split2(acc[i][j][2 * hf] * inv, h0, l0);
                split2(acc[i][j][2 * hf + 1] * inv, h1, l1);
                Qsp[row * APAD + col]     = make_float2(__uint_as_float(h0), __uint_as_float(l0));
                Qsp[row * APAD + col + 1] = make_float2(__uint_as_float(h1), __uint_as_float(l1));
            }
        }
    CP_WAIT(0);
    __syncthreads();   // P written, V arrived

    // phase 2: O = P @ V
    float out[2][2][4] = {};
    #pragma unroll 4
    for (int ks = 0; ks < T; ks += 8) {
        unsigned ah[2][4], al[2][4], bh[2][2], bl[2][2];
        #pragma unroll
        for (int i = 0; i < 2; i++) {
            int m0 = i * 16;
            float2 v0 = Qsp[(m0 + l2) * APAD + ks + l3];
            float2 v1 = Qsp[(m0 + l2 + 8) * APAD + ks + l3];
            float2 v2 = Qsp[(m0 + l2) * APAD + ks + l3 + 4];
            float2 v3 = Qsp[(m0 + l2 + 8) * APAD + ks + l3 + 4];
            ah[i][0] = __float_as_uint(v0.x); al[i][0] = __float_as_uint(v0.y);
            ah[i][1] = __float_as_uint(v1.x); al[i][1] = __float_as_uint(v1.y);
            ah[i][2] = __float_as_uint(v2.x); al[i][2] = __float_as_uint(v2.y);
            ah[i][3] = __float_as_uint(v3.x); al[i][3] = __float_as_uint(v3.y);
        }
        #pragma unroll
        for (int j = 0; j < 2; j++) {
            int n0 = wn * 16 + j * 8;
            split2(Kbuf[(ks + l3) * APAD + n0 + l2],     bh[j][0], bl[j][0]);
            split2(Kbuf[(ks + l3 + 4) * APAD + n0 + l2], bh[j][1], bl[j][1]);
        }
        #pragma unroll
        for (int i = 0; i < 2; i++)
            #pragma unroll
            for (int j = 0; j < 2; j++)
                mma_tf32(out[i][j], ah[i], bh[j]);
        #pragma unroll
        for (int i = 0; i < 2; i++)
            #pragma unroll
            for (int j = 0; j < 2; j++)
                mma_tf32(out[i][j], ah[i], bl[j]);
        #pragma unroll
        for (int i = 0; i < 2; i++)
            #pragma unroll
            for (int j = 0; j < 2; j++)
                mma_tf32(out[i][j], al[i], bh[j]);
    }

    float* Og = O + ((size_t)bb * T + qbase) * D + h * DK;
    #pragma unroll
    for (int i = 0; i < 2; i++)
        #pragma unroll
        for (int j = 0; j < 2; j++) {
            int r = i * 16 + l2;
            int c = wn * 16 + j * 8 + 2 * l3;
            *(float2*)(Og + (size_t)r * D + c) = make_float2(out[i][j][0], out[i][j][1]);
            *(float2*)(Og + (size_t)(r + 8) * D + c) = make_float2(out[i][j][2], out[i][j][3]);
        }
}

// ---------------- warp helpers ----------------------------------------------
__device__ __forceinline__ float warp_sum(float v) {
    #pragma unroll
    for (int o = 16; o > 0; o >>= 1) v += __shfl_xor_sync(0xffffffff, v, o);
    return v;
}
__device__ __forceinline__ float warp_max(float v) {
    #pragma unroll
    for (int o = 16; o > 0; o >>= 1) v = fmaxf(v, __shfl_xor_sync(0xffffffff, v, o));
    return v;
}

// ---------------- LayerNorm kernels ------------------------------------------
// merged both towers: row<512 -> q_emb, else a_emb
__global__ void add_pos_ln_kernel(const float* __restrict__ qe, const float* __restrict__ ae,
                                  const float* __restrict__ pos,
                                  const float* __restrict__ w, const float* __restrict__ b,
                                  float* __restrict__ out) {
    int row = blockIdx.x, tid = threadIdx.x;
    int lane = tid & 31, wd = tid >> 5;
    __shared__ float p1[4], p2[4];

    const float* src = (row < 512) ? (qe + (size_t)row * D) : (ae + (size_t)(row - 512) * D);
    float4 xv = ((const float4*)src)[tid];
    float4 pv = ((const float4*)(pos + (size_t)(row % T) * D))[tid];
    float4 v = make_float4(xv.x + pv.x, xv.y + pv.y, xv.z + pv.z, xv.w + pv.w);

    float s = warp_sum(v.x + v.y + v.z + v.w);
    if (lane == 0) p1[wd] = s;
    __syncthreads();
    float mean = (p1[0] + p1[1] + p1[2] + p1[3]) * (1.0f / D);
    float4 d = make_float4(v.x - mean, v.y - mean, v.z - mean, v.w - mean);
    float q = warp_sum(d.x * d.x + d.y * d.y + d.z * d.z + d.w * d.w);
    if (lane == 0) p2[wd] = q;
    __syncthreads();
    float inv = rsqrtf((p2[0] + p2[1] + p2[2] + p2[3]) * (1.0f / D) + 1e-12f);

    float4 wv = ((const float4*)w)[tid];
    float4 bv = ((const float4*)b)[tid];
    ((float4*)(out + (size_t)row * D))[tid] =
        make_float4(wv.x * d.x * inv + bv.x, wv.y * d.y * inv + bv.y,
                    wv.z * d.z * inv + bv.z, wv.w * d.w * inv + bv.w);
}

// x += y0 + y1 (persist); out = LN(x)*w+b.  (out may alias x; y1 may be null)
__global__ void residual_ln2_kernel(float* __restrict__ x, const float* __restrict__ y0,
                                    const float* __restrict__ y1,
                                    float* __restrict__ out,
                                    const float* __restrict__ w, const float* __restrict__ b) {
    int row = blockIdx.x, tid = threadIdx.x;
    int lane = tid & 31, wd = tid >> 5;
    __shared__ float p1[4], p2[4];

    float4 xv = ((const float4*)(x + (size_t)row * D))[tid];
    float4 y0v = ((const float4*)(y0 + (size_t)row * D))[tid];
    float4 v = make_float4(xv.x + y0v.x, xv.y + y0v.y, xv.z + y0v.z, xv.w + y0v.w);
    if (y1) {
        float4 y1v = ((const float4*)(y1 + (size_t)row * D))[tid];
        v.x += y1v.x; v.y += y1v.y; v.z += y1v.z; v.w += y1v.w;
    }
    ((float4*)(x + (size_t)row * D))[tid] = v;

    float s = warp_sum(v.x + v.y + v.z + v.w);
    if (lane == 0) p1[wd] = s;
    __syncthreads();
    float mean = (p1[0] + p1[1] + p1[2] + p1[3]) * (1.0f / D);
    float4 d = make_float4(v.x - mean, v.y - mean, v.z - mean, v.w - mean);
    float q = warp_sum(d.x * d.x + d.y * d.y + d.z * d.z + d.w * d.w);
    if (lane == 0) p2[wd] = q;
    __syncthreads();
    float inv = rsqrtf((p2[0] + p2[1] + p2[2] + p2[3]) * (1.0f / D) + 1e-12f);

    float4 wv = ((const float4*)w)[tid];
    float4 bv = ((const float4*)b)[tid];
    ((float4*)(out + (size_t)row * D))[tid] =
        make_float4(wv.x * d.x * inv + bv.x, wv.y * d.y * inv + bv.y,
                    wv.z * d.z * inv + bv.z, wv.w * d.w * inv + bv.w);
}

// ---------------- sim head helpers ------------------------------------------
__global__ void edot_kernel(const float* __restrict__ X, const float* __restrict__ E,
                            float* __restrict__ out) {
    int row = blockIdx.x;
    int tid = threadIdx.x;
    __shared__ float red[NC * 256];
    float acc[NC] = {};
    for (int d = tid; d < D; d += 256) {
        float x = X[(size_t)row * D + d];
        #pragma unroll
        for (int c = 0; c < NC; c++) acc[c] += x * E[(size_t)c * D + d];
    }
    #pragma unroll
    for (int c = 0; c < NC; c++) red[c * 256 + tid] = acc[c];
    __syncthreads();
    for (int off = 128; off > 0; off >>= 1) {
        if (tid < off) {
            #pragma unroll
            for (int c = 0; c < NC; c++) red[c * 256 + tid] += red[c * 256 + tid + off];
        }
        __syncthreads();
    }
    if (tid < NC) out[(size_t)row * NC + tid] = red[tid * 256];
}

__global__ void gram_kernel(const float* __restrict__ E, float* __restrict__ G) {
    int i = threadIdx.x;
    if (i < NC * NC) {
        int c = i / NC, c2 = i % NC;
        float s = 0.0f;
        for (int d = 0; d < D; d++) s += E[(size_t)c * D + d] * E[(size_t)c2 * D + d];
        G[i] = s;
    }
}

__global__ void sim_attn_kernel(const float* __restrict__ QK, const float* __restrict__ QK2,
                                const float* __restrict__ qa,
                                const float* __restrict__ aq, const float* __restrict__ Eq,
                                const float* __restrict__ Ek, const float* __restrict__ G,
                                float* __restrict__ P, float* __restrict__ Wout) {
    int t = blockIdx.x, b = blockIdx.y;
    int s = threadIdx.x;                 // 128 threads
    int lane = s & 31, wd = s >> 5;
    __shared__ float g[NC * NC];
    __shared__ float part[4];
    __shared__ float pv[T];
    if (s < NC * NC) g[s] = G[s];
    __syncthreads();

    float f1[NC], f2[NC];
    const float* r1 = qa + (((size_t)b * T + t) * T + s) * NC;
    const float* r2 = aq + (((size_t)b * T + s) * T + t) * NC;
    #pragma unroll
    for (int c = 0; c < NC; c++) { f1[c] = r1[c]; f2[c] = r2[c]; }

    size_t qkidx = ((size_t)b * T + t) * T + s;
    float sc = QK[qkidx] + QK2[qkidx];
    const float* eq = Eq + ((size_t)b * T + t) * NC;
    const float* ek = Ek + ((size_t)b * T + s) * NC;
    #pragma unroll
    for (int c = 0; c < NC; c++) sc += f1[c] * ek[c] + f2[c] * eq[c];
    #pragma unroll
    for (int c = 0; c < NC; c++)
        #pragma unroll
        for (int c2 = 0; c2 < NC; c2++)
            sc += f1[c] * g[c * NC + c2] * f2[c2];

    float m = warp_max(sc);
    if (lane == 0) part[wd] = m;
    __syncthreads();
    float m1 = fmaxf(fmaxf(part[0], part[1]), fmaxf(part[2], part[3]));
    float e1 = expf(sc - m1);
    float ssum = warp_sum(e1);
    if (lane == 0) part[wd] = ssum;
    __syncthreads();
    float p = e1 / (part[0] + part[1] + part[2] + part[3]);

    float l = 1000.0f * p;
    m = warp_max(l);
    __syncthreads();
    if (lane == 0) part[wd] = m;
    __syncthreads();
    float m2 = fmaxf(fmaxf(part[0], part[1]), fmaxf(part[2], part[3]));
    float e2 = expf(l - m2);
    ssum = warp_sum(e2);
    __syncthreads();
    if (lane == 0) part[wd] = ssum;
    __syncthreads();
    float p2 = e2 / (part[0] + part[1] + part[2] + part[3]);
    p2 = fminf(fmaxf(p2, 0.0f), 1.0f);

    P[((size_t)b * T + t) * T + s] = p2;
    pv[s] = p2;
    __syncthreads();

    #pragma unroll
    for (int c = 0; c < NC; c++) {
        float v = warp_sum(pv[s] * f2[c]);
        __syncthreads();
        if (lane == 0) part[wd] = v;
        __syncthreads();
        if (s == 0) Wout[((size_t)b * T + t) * NC + c] = part[0] + part[1] + part[2] + part[3];
    }
}

__global__ void final_kernel(const float* __restrict__ pk, const float* __restrict__ pk2,
                             const float* __restrict__ Wm,
                             const float* __restrict__ E, const float* __restrict__ clsw,
                             const float* __restrict__ clsb, float* __restrict__ out) {
    int b = blockIdx.x;
    int d = threadIdx.x;
    __shared__ float wm[NC];
    __shared__ float red[512];

    if (d < NC) {
        float s = 0.0f;
        for (int t = 0; t < T; t++) s += Wm[((size_t)b * T + t) * NC + d];
        wm[d] = s * (1.0f / T);
    }
    __syncthreads();

    float s = 0.0f;
    for (int t = 0; t < T; t++)
        s += pk[((size_t)b * T + t) * D + d] + pk2[((size_t)b * T + t) * D + d];
    s *= (1.0f / T);
    #pragma unroll
    for (int c = 0; c < NC; c++) s += wm[c] * E[(size_t)c * D + d];

    for (int j = 0; j < 3; j++) {
        red[d] = s * clsw[(size_t)d * 3 + j];
        __syncthreads();
        for (int off = 256; off > 0; off >>= 1) { if (d < off) red[d] += red[d + off]; __syncthreads(); }
        if (d == 0) out[b * 3 + j] = red[0] + clsb[j];
        __syncthreads();
    }
}

// ---------------- host orchestration ----------------------------------------
static inline void g_launch(int transB,
                            const float* A0, const float* A1, const float* A2,
                            const float* W0, const float* W1, const float* W2,
                            const float* b0, const float* b1, const float* b2,
                            float* C0, float* C1, float* C2,
                            int M, int N, int K, int lda, int ldb, int ldc,
                            int act, int nH,
                            long long sA, long long hA, long long sB, long long hB,
                            long long sC, long long hC, int zPerSet, int nz) {
    dim3 grid(N / 64, M / 64, nz);
    if (transB)
        gemm_tf32<1><<<grid, 256>>>(A0, A1, A2, W0, W1, W2, b0, b1, b2, C0, C1, C2,
                                    M, N, K, lda, ldb, ldc, act, nH,
                                    sA, hA, sB, hB, sC, hC, zPerSet);
    else
        gemm_tf32<0><<<grid, 256>>>(A0, A1, A2, W0, W1, W2, b0, b1, b2, C0, C1, C2,
                                    M, N, K, lda, ldb, ldc, act, nH,
                                    sA, hA, sB, hB, sC, hC, zPerSet);
}

extern "C" void kernel_launch(void* const* d_in, const int* in_sizes, int n_in,
                              void* d_out, int out_size) {
    const float* q_emb   = (const float*)d_in[0];
    const float* a_emb   = (const float*)d_in[1];
    const float* qa_rel  = (const float*)d_in[2];
    const float* aq_rel  = (const float*)d_in[3];
    const float* conceptE= (const float*)d_in[4];
    const float* pos_emb = (const float*)d_in[5];
    const float* pe_w    = (const float*)d_in[6];
    const float* pe_b    = (const float*)d_in[7];
    const float* Wq      = (const float*)d_in[8];
    const float* bq      = (const float*)d_in[9];
    const float* Wk      = (const float*)d_in[10];
    const float* bk      = (const float*)d_in[11];
    const float* Wv      = (const float*)d_in[12];
    const float* bv      = (const float*)d_in[13];
    const float* Wo      = (const float*)d_in[14];
    const float* bo      = (const float*)d_in[15];
    const float* ff1w    = (const float*)d_in[16];
    const float* ff1b    = (const float*)d_in[17];
    const float* ff2w    = (const float*)d_in[18];
    const float* ff2b    = (const float*)d_in[19];
    const float* lninw   = (const float*)d_in[20];
    const float* lninb   = (const float*)d_in[21];
    const float* lnoutw  = (const float*)d_in[22];
    const float* lnoutb  = (const float*)d_in[23];
    const float* simWq   = (const float*)d_in[24];
    const float* simbq   = (const float*)d_in[25];
    const float* simWk   = (const float*)d_in[26];
    const float* simbk   = (const float*)d_in[27];
    const float* clsw    = (const float*)d_in[28];
    const float* clsb    = (const float*)d_in[29];
    float* out = (float*)d_out;

    float* base = nullptr;
    cudaGetSymbolAddress((void**)&base, g_scratch);

    float* X   = base + OFF_X;
    float* Qb  = base + OFF_Q;
    float* Kb  = base + OFF_K;
    float* Vb  = base + OFF_V;
    float* T0  = base + OFF_T0;
    float* T1b = base + OFF_T1;
    float* T2b = base + OFF_T2;
    float* Hb  = base + OFF_H;
    float* FFN = base + OFF_FFN;
    float* QKb = base + OFF_QK;
    float* QK2b= base + OFF_QK2;
    float* Pb  = base + OFF_P;
    float* EQb = base + OFF_EQ;
    float* EKb = base + OFF_EK;
    float* Gb  = base + OFF_G;
    float* Wb  = base + OFF_W;
    float* PKb = base + OFF_PK;
    float* PK2b= base + OFF_PK2;

    static const int ATTN_SMEM = (QR * APAD * 3 + 128 * APAD) * 4;
    cudaFuncSetAttribute(fused_attn, cudaFuncAttributeMaxDynamicSharedMemorySize, ATTN_SMEM);

    add_pos_ln_kernel<<<M2, 128>>>(q_emb, a_emb, pos_emb, pe_w, pe_b, X);

    for (int i = 0; i < NL; i++) {
        const float* wq = Wq + (size_t)i * D * D;
        const float* wk = Wk + (size_t)i * D * D;
        const float* wv = Wv + (size_t)i * D * D;
        const float* wo = Wo + (size_t)i * D * D;

        // fused QKV: 3 sets, one launch (grid 8x16x3 = 384)
        g_launch(0, X, X, X, wq, wk, wv,
                 bq + (size_t)i * D, bk + (size_t)i * D, bv + (size_t)i * D,
                 Qb, Kb, Vb,
                 M2, D, D, D, D, D, 0, 1, 0, 0, 0, 0, 0, 0, 1, 3);

        // fused attention: grid (4, 32) = 128 CTAs
        fused_attn<<<dim3(4, 32), 256, ATTN_SMEM>>>(Qb, Kb, Vb, T0);

        // output projection split-K=2 (grid 8x16x2 = 256)
        g_launch(0, T0, T0 + 256, 0, wo, wo + (size_t)256 * D, 0,
                 bo + (size_t)i * D, 0, 0, T1b, T2b, 0,
                 M2, D, 256, D, D, D, 0, 1, 0, 0, 0, 0, 0, 0, 1, 2);

        residual_ln2_kernel<<<M2, 128>>>(X, T1b, T2b, Hb,
                                         lninw + (size_t)i * D, lninb + (size_t)i * D);

        g_launch(0, Hb, 0, 0, ff1w + (size_t)i * D * DFF, 0, 0, ff1b + (size_t)i * DFF, 0, 0, FFN, 0, 0,
                 M2, DFF, D, D, DFF, DFF, 1, 1, 0, 0, 0, 0, 0, 0, 1, 1);

        // ff2 split-K=2 (grid 8x16x2 = 256)
        g_launch(0, FFN, FFN + 1024, 0,
                 ff2w + (size_t)i * DFF * D, ff2w + (size_t)i * DFF * D + (size_t)1024 * D, 0,
                 ff2b + (size_t)i * D, 0, 0, T1b, T2b, 0,
                 M2, D, 1024, DFF, D, D, 0, 1, 0, 0, 0, 0, 0, 0, 1, 2);

        residual_ln2_kernel<<<M2, 128>>>(X, T1b, T2b, X,
                                         lnoutw + (size_t)i * D, lnoutb + (size_t)i * D);
    }

    // --- sim head ---
    g_launch(0, X, X + (size_t)(M2 / 2) * D, 0, simWq, simWk, 0, simbq, simbk, 0, Qb, Kb, 0,
             M2 / 2, D, D, D, D, D, 0, 1, 0, 0, 0, 0, 0, 0, 1, 2);

    edot_kernel<<<M2 / 2, 256>>>(Qb, conceptE, EQb);
    edot_kernel<<<M2 / 2, 256>>>(Kb, conceptE, EKb);
    gram_kernel<<<1, 32>>>(conceptE, Gb);

    // QK[b] = q_sim[b] @ k_sim[b]^T, split-K=2 via sets (grid 2x2x8 = 32 CTAs)
    g_launch(1, Qb, Qb + 256, 0, Kb, Kb + 256, 0, 0, 0, 0, QKb, QK2b, 0,
             T, T, 256, D, D, T, 0, 1,
             (long long)T * D, 0, (long long)T * D, 0, (long long)T * T, 0, 4, 8);

    sim_attn_kernel<<<dim3(T, Bb), 128>>>(QKb, QK2b, qa_rel, aq_rel, EQb, EKb, Gb, Pb, Wb);

    // pk[b] = P[b] @ k_sim[b], split-K=2 via sets (grid 8x2x8 = 128 CTAs)
    g_launch(0, Pb, Pb + 64, 0, Kb, Kb + (size_t)64 * D, 0, 0, 0, 0, PKb, PK2b, 0,
             T, D, 64, T, D, D, 0, 1,
             (long long)T * T, 0, (long long)T * D, 0, (long long)T * D, 0, 4, 8);

    final_kernel<<<Bb, 512>>>(PKb, PK2b, Wb, conceptE, clsw, clsb, out);
}